// round 9
// baseline (speedup 1.0000x reference)
#include <cuda_runtime.h>
#include <cuda_bf16.h>
#include <math.h>
#include <stdint.h>

#define TT 50
#define BB 256
#define DBEL 1024
#define DST 128
#define DACT 32
#define DHID 1024
#define DEMB 1024
#define GRU3 (3*DBEL)
#define THR 128

// ---- output layout (beliefs, prior_s, mp, sp, post_s, mq, sq) ----
static constexpr size_t OFF_BEL = 0;
static constexpr size_t OFF_PRS = (size_t)TT*BB*DBEL;
static constexpr size_t OFF_MP  = OFF_PRS + (size_t)TT*BB*DST;
static constexpr size_t OFF_SP  = OFF_MP  + (size_t)TT*BB*DST;
static constexpr size_t OFF_POS = OFF_SP  + (size_t)TT*BB*DST;
static constexpr size_t OFF_MQ  = OFF_POS + (size_t)TT*BB*DST;
static constexpr size_t OFF_SQ  = OFF_MQ  + (size_t)TT*BB*DST;

// ---- fp32 scratch ----
__device__ float g_x[BB*DBEL];
__device__ float g_gi[BB*GRU3];
__device__ float g_gi2[BB*GRU3];
__device__ float g_gh[BB*GRU3];
__device__ float g_gh2[BB*GRU3];
__device__ float g_belief[BB*DBEL];
__device__ float g_hq[BB*DHID];
__device__ float g_hp[(size_t)TT*BB*DHID];

// ---- bf16 hi/lo weight planes ----
__device__ __nv_bfloat16 g_wsa_h[DBEL*(DST+DACT)],   g_wsa_l[DBEL*(DST+DACT)];
__device__ __nv_bfloat16 g_wih_h[GRU3*DBEL],         g_wih_l[GRU3*DBEL];
__device__ __nv_bfloat16 g_whh_h[GRU3*DBEL],         g_whh_l[GRU3*DBEL];
__device__ __nv_bfloat16 g_wpoh_h[DHID*(DBEL+DEMB)], g_wpoh_l[DHID*(DBEL+DEMB)];
__device__ __nv_bfloat16 g_wpos_h[2*DST*DHID],       g_wpos_l[2*DST*DHID];
__device__ __nv_bfloat16 g_wprh_h[DHID*DBEL],        g_wprh_l[DHID*DBEL];
__device__ __nv_bfloat16 g_wprs_h[2*DST*DHID],       g_wprs_l[2*DST*DHID];

// ---- grid barrier (zero-init at module load; count invariant 0 between barriers) ----
__device__ unsigned g_bar_count;
__device__ unsigned g_bar_gen;

__device__ __forceinline__ float eluf(float x)   { return x > 0.f ? x : expm1f(x); }
__device__ __forceinline__ float splusf(float x) { return fmaxf(x, 0.f) + log1pf(expf(-fabsf(x))); }
__device__ __forceinline__ float sigf(float x)   { return 1.f / (1.f + expf(-x)); }

__device__ __forceinline__ void grid_barrier(int nblk)
{
    __syncthreads();
    if (threadIdx.x == 0) {
        unsigned gen = *((volatile unsigned*)&g_bar_gen);
        __threadfence();
        unsigned old = atomicAdd(&g_bar_count, 1u);
        if (old == (unsigned)(nblk - 1)) {
            g_bar_count = 0u;
            __threadfence();
            atomicAdd(&g_bar_gen, 1u);
        } else {
            while (*((volatile unsigned*)&g_bar_gen) == gen) __nanosleep(32);
        }
        __threadfence();
    }
    __syncthreads();
}

// ================= GEMM core (64x64 block, 4 warps of 32x32, BK=32) =================
enum { ALOAD_PLAIN = 0, ALOAD_ELU = 1, ALOAD_STATE = 2 };
enum { EPI_BIAS = 0, EPI_BIAS_ELU = 1, EPI_PLAIN = 2, EPI_ATOMIC = 3, EPI_HEAD_ATOMIC = 4, EPI_HEAD_STORE = 5 };

struct Smem {
    __nv_bfloat16 A[2][2][64*40];   // [stage][plane hi/lo][64 rows x (32+8 pad)]
    __nv_bfloat16 B[2][2][64*40];
};

// Mutable cross-phase buffers read via __ldcg (L1 not coherent across SMs; sw barrier
// does not flush L1 — only kernel boundaries do).
template<int ALOAD>
__device__ __forceinline__ void load_a8(
    int gm, int k, float* r,
    const float* A1, int lda1, const float* A2, int lda2, int K1,
    const float* st_mq, const float* st_sq, const float* st_eps,
    const float* st_nt, const float* st_prev)
{
    if (ALOAD == ALOAD_STATE && k < K1) {
        const float nt = st_nt[gm];
        const int base = gm * DST + k;
        if (st_mq) {
#pragma unroll
            for (int i = 0; i < 8; i++) {
                float mq = __ldcg(st_mq + base + i);
                float sq = __ldcg(st_sq + base + i);
                float s = splusf(sq) + 0.1f;
                r[i] = (mq + s * __ldg(st_eps + base + i)) * nt;
            }
        } else {
#pragma unroll
            for (int i = 0; i < 8; i++) r[i] = __ldg(st_prev + base + i) * nt;
        }
        return;
    }
    const float* p;
    if (k < K1) p = A1 + (size_t)gm * lda1 + k;
    else        p = A2 + (size_t)gm * lda2 + (k - K1);
    float4 v0 = __ldcg(reinterpret_cast<const float4*>(p));
    float4 v1 = __ldcg(reinterpret_cast<const float4*>(p + 4));
    r[0] = v0.x; r[1] = v0.y; r[2] = v0.z; r[3] = v0.w;
    r[4] = v1.x; r[5] = v1.y; r[6] = v1.z; r[7] = v1.w;
    if (ALOAD == ALOAD_ELU) {
#pragma unroll
        for (int i = 0; i < 8; i++) r[i] = eluf(r[i]);
    }
}

__device__ __forceinline__ void split_pack8(const float* r, uint4& h, uint4& l)
{
    uint32_t hw[4], lw[4];
#pragma unroll
    for (int i = 0; i < 4; i++) {
        __nv_bfloat16 h0 = __float2bfloat16_rn(r[2*i]);
        __nv_bfloat16 h1 = __float2bfloat16_rn(r[2*i+1]);
        __nv_bfloat16 l0 = __float2bfloat16_rn(r[2*i]   - __bfloat162float(h0));
        __nv_bfloat16 l1 = __float2bfloat16_rn(r[2*i+1] - __bfloat162float(h1));
        __nv_bfloat162 hp = __halves2bfloat162(h0, h1);
        __nv_bfloat162 lp = __halves2bfloat162(l0, l1);
        hw[i] = *reinterpret_cast<uint32_t*>(&hp);
        lw[i] = *reinterpret_cast<uint32_t*>(&lp);
    }
    h = make_uint4(hw[0], hw[1], hw[2], hw[3]);
    l = make_uint4(lw[0], lw[1], lw[2], lw[3]);
}

__device__ __forceinline__ void ldsm4(uint32_t (&r)[4], uint32_t addr) {
    asm volatile("ldmatrix.sync.aligned.m8n8.x4.shared.b16 {%0,%1,%2,%3}, [%4];"
        : "=r"(r[0]), "=r"(r[1]), "=r"(r[2]), "=r"(r[3]) : "r"(addr));
}
__device__ __forceinline__ void mma16816(float (&d)[4], const uint32_t (&a)[4], const uint32_t (&b)[2]) {
    asm volatile("mma.sync.aligned.m16n8k16.row.col.f32.bf16.bf16.f32 "
        "{%0,%1,%2,%3}, {%4,%5,%6,%7}, {%8,%9}, {%0,%1,%2,%3};"
        : "+f"(d[0]), "+f"(d[1]), "+f"(d[2]), "+f"(d[3])
        : "r"(a[0]), "r"(a[1]), "r"(a[2]), "r"(a[3]), "r"(b[0]), "r"(b[1]));
}
__device__ __forceinline__ void cp16(uint32_t dst, const void* src) {
    asm volatile("cp.async.ca.shared.global [%0], [%1], 16;" :: "r"(dst), "l"(src));
}
__device__ __forceinline__ void cp_commit() { asm volatile("cp.async.commit_group;"); }
__device__ __forceinline__ void cp_wait0()  { asm volatile("cp.async.wait_group 0;"); }

template<int EPI>
__device__ __forceinline__ void epi_pair(
    int kc, int r, int c, float v0, float v1,
    const float* bias, float* out, int ldout, float* mean_out, float* std_out)
{
    if (EPI == EPI_BIAS) {
        float2 o = make_float2(v0 + __ldg(bias + c), v1 + __ldg(bias + c + 1));
        *reinterpret_cast<float2*>(out + (size_t)r * ldout + c) = o;
    } else if (EPI == EPI_BIAS_ELU) {
        float2 o = make_float2(eluf(v0 + __ldg(bias + c)), eluf(v1 + __ldg(bias + c + 1)));
        *reinterpret_cast<float2*>(out + (size_t)r * ldout + c) = o;
    } else if (EPI == EPI_PLAIN) {
        float2 o = make_float2(v0, v1);
        *reinterpret_cast<float2*>(out + (size_t)r * ldout + c) = o;
    } else if (EPI == EPI_ATOMIC) {
        float* o = out + (size_t)r * ldout + c;
        atomicAdd(o, v0); atomicAdd(o + 1, v1);
    } else if (EPI == EPI_HEAD_ATOMIC) {
        float b0 = (kc == 0) ? __ldg(bias + c)     : 0.f;
        float b1 = (kc == 0) ? __ldg(bias + c + 1) : 0.f;
        if (c < DST) {
            atomicAdd(mean_out + (size_t)r * DST + c,     v0 + b0);
            atomicAdd(mean_out + (size_t)r * DST + c + 1, v1 + b1);
        } else {
            atomicAdd(std_out + (size_t)r * DST + (c - DST),     v0 + b0);
            atomicAdd(std_out + (size_t)r * DST + (c - DST) + 1, v1 + b1);
        }
    } else { // EPI_HEAD_STORE
        float w0 = v0 + __ldg(bias + c), w1 = v1 + __ldg(bias + c + 1);
        if (c < DST) {
            mean_out[(size_t)r * DST + c]     = w0;
            mean_out[(size_t)r * DST + c + 1] = w1;
        } else {
            std_out[(size_t)r * DST + (c - DST)]     = splusf(w0) + 0.1f;
            std_out[(size_t)r * DST + (c - DST) + 1] = splusf(w1) + 0.1f;
        }
    }
}

template<int KC, int ALOAD, int EPI>
__device__ void gemm_tile(
    Smem* sm, int mb, int nb, int kc,
    const float* A1, int lda1, const float* A2, int lda2, int K1,
    const __nv_bfloat16* __restrict__ Wh, const __nv_bfloat16* __restrict__ Wl, int ldw,
    const float* __restrict__ bias, float* out, int ldout,
    float* mean_out, float* std_out,
    const float* st_mq, const float* st_sq, const float* st_eps,
    const float* st_nt, const float* st_prev)
{
    constexpr int NST = KC / 32;
    const int kbeg = kc * KC;

    const int tid  = threadIdx.x;          // 0..127
    const int lrow = tid >> 1;             // 0..63
    const int lkb  = (tid & 1) << 4;       // 0 or 16
    const int gm   = mb * 64 + lrow;
    const int gn   = nb * 64 + lrow;
    const size_t gnK = (size_t)gn * ldw;

    const int lane = tid & 31;
    const int wid  = tid >> 5;             // 0..3
    const int wm = (wid >> 1) * 32;
    const int wn = (wid & 1) * 32;

    // A ldmatrix lane mapping (16x16 tile, x4)
    const int amat = lane >> 3, arin = lane & 7;
    const int arowb = wm + ((amat & 1) << 3) + arin;
    const int acol  = (amat >> 1) << 3;
    // B ldmatrix lane mapping (two 8-col n-frags per x4)
    const int brow = wn + ((lane >> 4) << 3) + (lane & 7);
    const int bcol = ((lane >> 3) & 1) << 3;

    const uint32_t aBase = (uint32_t)__cvta_generic_to_shared(&sm->A[0][0][0]);
    const uint32_t bBase = (uint32_t)__cvta_generic_to_shared(&sm->B[0][0][0]);
    const uint32_t PLN = 64u * 40 * 2;      // bytes per plane
    const uint32_t STG = 2u * PLN;          // bytes per stage

    __syncthreads();   // protect smem reuse across tiles in the same phase

    // ---- prologue: stage 0 ----
    {
        int kb = kbeg;
        cp16(bBase + (uint32_t)((lrow*40 + lkb)     * 2),        Wh + gnK + kb + lkb);
        cp16(bBase + (uint32_t)((lrow*40 + lkb + 8) * 2),        Wh + gnK + kb + lkb + 8);
        cp16(bBase + PLN + (uint32_t)((lrow*40 + lkb)     * 2),  Wl + gnK + kb + lkb);
        cp16(bBase + PLN + (uint32_t)((lrow*40 + lkb + 8) * 2),  Wl + gnK + kb + lkb + 8);
        cp_commit();
#pragma unroll
        for (int j = 0; j < 2; j++) {
            float r8[8];
            load_a8<ALOAD>(gm, kb + lkb + j*8, r8, A1, lda1, A2, lda2, K1,
                           st_mq, st_sq, st_eps, st_nt, st_prev);
            uint4 ah, al; split_pack8(r8, ah, al);
            *reinterpret_cast<uint4*>(&sm->A[0][0][lrow*40 + lkb + j*8]) = ah;
            *reinterpret_cast<uint4*>(&sm->A[0][1][lrow*40 + lkb + j*8]) = al;
        }
        cp_wait0();
    }
    __syncthreads();

    float acc[2][4][4];
#pragma unroll
    for (int i = 0; i < 2; i++)
#pragma unroll
        for (int j = 0; j < 4; j++)
#pragma unroll
            for (int q = 0; q < 4; q++) acc[i][j][q] = 0.f;

    float ra[16];

#pragma unroll 1
    for (int t = 0; t < NST; t++) {
        const int cur = t & 1;
        const int nxt = cur ^ 1;
        const bool more = (t + 1 < NST);
        if (more) {
            int kb = kbeg + (t + 1) * 32;
            cp16(bBase + nxt*STG + (uint32_t)((lrow*40 + lkb)     * 2),       Wh + gnK + kb + lkb);
            cp16(bBase + nxt*STG + (uint32_t)((lrow*40 + lkb + 8) * 2),       Wh + gnK + kb + lkb + 8);
            cp16(bBase + nxt*STG + PLN + (uint32_t)((lrow*40 + lkb)     * 2), Wl + gnK + kb + lkb);
            cp16(bBase + nxt*STG + PLN + (uint32_t)((lrow*40 + lkb + 8) * 2), Wl + gnK + kb + lkb + 8);
            cp_commit();
            load_a8<ALOAD>(gm, kb + lkb,     ra,     A1, lda1, A2, lda2, K1, st_mq, st_sq, st_eps, st_nt, st_prev);
            load_a8<ALOAD>(gm, kb + lkb + 8, ra + 8, A1, lda1, A2, lda2, K1, st_mq, st_sq, st_eps, st_nt, st_prev);
        }
        const uint32_t aOff = aBase + cur * STG;
        const uint32_t bOff = bBase + cur * STG;
#pragma unroll
        for (int kk = 0; kk < 32; kk += 16) {
            uint32_t Ah[2][4], Al[2][4], Bh[4][2], Bl[4][2];
#pragma unroll
            for (int mf = 0; mf < 2; mf++) {
                uint32_t off = (uint32_t)(((arowb + mf*16) * 40 + kk + acol) * 2);
                ldsm4(Ah[mf], aOff + off);
                ldsm4(Al[mf], aOff + PLN + off);
            }
#pragma unroll
            for (int nfp = 0; nfp < 2; nfp++) {
                uint32_t off = (uint32_t)(((brow + nfp*16) * 40 + kk + bcol) * 2);
                uint32_t rh[4], rl[4];
                ldsm4(rh, bOff + off);
                ldsm4(rl, bOff + PLN + off);
                Bh[nfp*2][0] = rh[0]; Bh[nfp*2][1] = rh[1];
                Bh[nfp*2+1][0] = rh[2]; Bh[nfp*2+1][1] = rh[3];
                Bl[nfp*2][0] = rl[0]; Bl[nfp*2][1] = rl[1];
                Bl[nfp*2+1][0] = rl[2]; Bl[nfp*2+1][1] = rl[3];
            }
#pragma unroll
            for (int mf = 0; mf < 2; mf++)
#pragma unroll
                for (int nf = 0; nf < 4; nf++) {
                    mma16816(acc[mf][nf], Ah[mf], Bh[nf]);
                    mma16816(acc[mf][nf], Ah[mf], Bl[nf]);
                    mma16816(acc[mf][nf], Al[mf], Bh[nf]);
                }
        }
        if (more) {
#pragma unroll
            for (int j = 0; j < 2; j++) {
                uint4 ah, al; split_pack8(ra + j*8, ah, al);
                *reinterpret_cast<uint4*>(&sm->A[nxt][0][lrow*40 + lkb + j*8]) = ah;
                *reinterpret_cast<uint4*>(&sm->A[nxt][1][lrow*40 + lkb + j*8]) = al;
            }
        }
        cp_wait0();
        __syncthreads();
    }

    const int gr = lane >> 2, gc = (lane & 3) << 1;
#pragma unroll
    for (int mf = 0; mf < 2; mf++)
#pragma unroll
        for (int nf = 0; nf < 4; nf++) {
            int r = mb * 64 + wm + mf * 16 + gr;
            int c = nb * 64 + wn + nf * 8 + gc;
            epi_pair<EPI>(kc, r,     c, acc[mf][nf][0], acc[mf][nf][1], bias, out, ldout, mean_out, std_out);
            epi_pair<EPI>(kc, r + 8, c, acc[mf][nf][2], acc[mf][nf][3], bias, out, ldout, mean_out, std_out);
        }
}

// ================= elementwise =================
__device__ void conv_seg(const float* __restrict__ s, __nv_bfloat16* hi, __nv_bfloat16* lo,
                         int n, int gtid, int nthr)
{
    for (int i = gtid * 4; i < n; i += nthr * 4) {
        float4 v = __ldg(reinterpret_cast<const float4*>(s + i));
        float vv[4] = {v.x, v.y, v.z, v.w};
        __nv_bfloat16 h[4], l[4];
#pragma unroll
        for (int j = 0; j < 4; j++) {
            h[j] = __float2bfloat16_rn(vv[j]);
            l[j] = __float2bfloat16_rn(vv[j] - __bfloat162float(h[j]));
        }
        *reinterpret_cast<__nv_bfloat162*>(hi + i)     = __halves2bfloat162(h[0], h[1]);
        *reinterpret_cast<__nv_bfloat162*>(hi + i + 2) = __halves2bfloat162(h[2], h[3]);
        *reinterpret_cast<__nv_bfloat162*>(lo + i)     = __halves2bfloat162(l[0], l[1]);
        *reinterpret_cast<__nv_bfloat162*>(lo + i + 2) = __halves2bfloat162(l[2], l[3]);
    }
}

__device__ __forceinline__ float4 f4add(float4 a, float4 b) {
    return make_float4(a.x+b.x, a.y+b.y, a.z+b.z, a.w+b.w);
}

__device__ void phase_gru(const float* __restrict__ b_poh, float* bel_out, int gtid, int nthr)
{
    for (int i4 = gtid * 4; i4 < BB * DBEL; i4 += nthr * 4) {
        int m = i4 >> 10, j = i4 & 1023;
        const size_t base = (size_t)m * GRU3 + j;
        float4 gir = f4add(__ldcg((const float4*)(g_gi  + base)),        __ldcg((const float4*)(g_gi2 + base)));
        float4 giz = f4add(__ldcg((const float4*)(g_gi  + base + 1024)), __ldcg((const float4*)(g_gi2 + base + 1024)));
        float4 gin = f4add(__ldcg((const float4*)(g_gi  + base + 2048)), __ldcg((const float4*)(g_gi2 + base + 2048)));
        float4 ghr = f4add(__ldcg((const float4*)(g_gh  + base)),        __ldcg((const float4*)(g_gh2 + base)));
        float4 ghz = f4add(__ldcg((const float4*)(g_gh  + base + 1024)), __ldcg((const float4*)(g_gh2 + base + 1024)));
        float4 ghn = f4add(__ldcg((const float4*)(g_gh  + base + 2048)), __ldcg((const float4*)(g_gh2 + base + 2048)));
        float4 b   = __ldcg((const float4*)(g_belief + i4));
        float4 h;
        { float r = sigf(gir.x + ghr.x), z = sigf(giz.x + ghz.x);
          h.x = (1.f - z) * tanhf(gin.x + r * ghn.x) + z * b.x; }
        { float r = sigf(gir.y + ghr.y), z = sigf(giz.y + ghz.y);
          h.y = (1.f - z) * tanhf(gin.y + r * ghn.y) + z * b.y; }
        { float r = sigf(gir.z + ghr.z), z = sigf(giz.z + ghz.z);
          h.z = (1.f - z) * tanhf(gin.z + r * ghn.z) + z * b.z; }
        { float r = sigf(gir.w + ghr.w), z = sigf(giz.w + ghz.w);
          h.w = (1.f - z) * tanhf(gin.w + r * ghn.w) + z * b.w; }
        *reinterpret_cast<float4*>(g_belief + i4) = h;
        *reinterpret_cast<float4*>(bel_out + i4)  = h;
        // seed hq with posterior-hidden bias for split-K atomic accumulation
        *reinterpret_cast<float4*>(g_hq + i4) = __ldg(reinterpret_cast<const float4*>(b_poh + j));
    }
}

// ================= megakernel =================
struct Params {
    const float *prev_state, *actions, *prev_belief, *observations, *nonterminals,
                *prior_noise, *post_noise;
    const float *b_sa, *b_ih, *b_hh, *b_prh, *b_prs, *b_poh, *b_pos;
    const float *W_sa, *w_ih, *w_hh, *W_prh, *W_prs, *W_poh, *W_pos;
    float* out;
    int nblk;
};

__global__ void __launch_bounds__(THR, 4) mega(Params P)
{
    __shared__ Smem sm;
    const int nblk = P.nblk;
    const int bid  = blockIdx.x;
    const int gtid = bid * THR + threadIdx.x;
    const int nthr = nblk * THR;
    float* out = P.out;

    // ---- phase 0: weight split + init ----
    conv_seg(P.W_sa,  g_wsa_h,  g_wsa_l,  DBEL*(DST+DACT),   gtid, nthr);
    conv_seg(P.w_ih,  g_wih_h,  g_wih_l,  GRU3*DBEL,         gtid, nthr);
    conv_seg(P.w_hh,  g_whh_h,  g_whh_l,  GRU3*DBEL,         gtid, nthr);
    conv_seg(P.W_poh, g_wpoh_h, g_wpoh_l, DHID*(DBEL+DEMB),  gtid, nthr);
    conv_seg(P.W_pos, g_wpos_h, g_wpos_l, 2*DST*DHID,        gtid, nthr);
    conv_seg(P.W_prh, g_wprh_h, g_wprh_l, DHID*DBEL,         gtid, nthr);
    conv_seg(P.W_prs, g_wprs_h, g_wprs_l, 2*DST*DHID,        gtid, nthr);
    for (int i = gtid * 4; i < BB * DBEL; i += nthr * 4)
        *reinterpret_cast<float4*>(g_belief + i) =
            __ldg(reinterpret_cast<const float4*>(P.prev_belief + i));
    {
        float4 z4 = make_float4(0.f, 0.f, 0.f, 0.f);
        for (int i = gtid * 4; i < 2 * TT * BB * DST; i += nthr * 4)
            *reinterpret_cast<float4*>(out + OFF_MQ + i) = z4;
    }
    grid_barrier(nblk);

    // ---- scan ----
    for (int t = 0; t < TT; t++) {
        const float* act = P.actions      + (size_t)t * BB * DACT;
        const float* obs = P.observations + (size_t)t * BB * DEMB;
        const float* snt = P.nonterminals + (size_t)t * BB;
        const float* smq = (t == 0) ? nullptr : out + OFF_MQ + (size_t)(t-1) * BB * DST;
        const float* ssq = (t == 0) ? nullptr : out + OFF_SQ + (size_t)(t-1) * BB * DST;
        const float* sep = (t == 0) ? nullptr : P.post_noise + (size_t)(t-1) * BB * DST;

        // Phase A: X (64 tiles) + GH split-K=2 (384 tiles) = 448 tiles
        for (int tile = bid; tile < 448; tile += nblk) {
            if (tile < 64) {
                int mb = tile >> 4, nb = tile & 15;
                gemm_tile<160, ALOAD_STATE, EPI_BIAS_ELU>(&sm, mb, nb, 0,
                    nullptr, 0, act, DACT, DST,
                    g_wsa_h, g_wsa_l, DST + DACT, P.b_sa, g_x, DBEL, nullptr, nullptr,
                    smq, ssq, sep, snt, P.prev_state);
            } else {
                int g = tile - 64;
                int kc = g >= 192;
                int r = g - 192 * kc;
                int mb = r / 48, nb = r % 48;
                if (kc == 0)
                    gemm_tile<512, ALOAD_PLAIN, EPI_BIAS>(&sm, mb, nb, 0,
                        g_belief, DBEL, nullptr, 0, DBEL,
                        g_whh_h, g_whh_l, DBEL, P.b_hh, g_gh, GRU3, nullptr, nullptr,
                        nullptr, nullptr, nullptr, nullptr, nullptr);
                else
                    gemm_tile<512, ALOAD_PLAIN, EPI_PLAIN>(&sm, mb, nb, 1,
                        g_belief, DBEL, nullptr, 0, DBEL,
                        g_whh_h, g_whh_l, DBEL, nullptr, g_gh2, GRU3, nullptr, nullptr,
                        nullptr, nullptr, nullptr, nullptr, nullptr);
            }
        }
        grid_barrier(nblk);

        // Phase B: GI split-K=2 (384 tiles)
        for (int tile = bid; tile < 384; tile += nblk) {
            int kc = tile >= 192;
            int r = tile - 192 * kc;
            int mb = r / 48, nb = r % 48;
            if (kc == 0)
                gemm_tile<512, ALOAD_PLAIN, EPI_BIAS>(&sm, mb, nb, 0,
                    g_x, DBEL, nullptr, 0, DBEL,
                    g_wih_h, g_wih_l, DBEL, P.b_ih, g_gi, GRU3, nullptr, nullptr,
                    nullptr, nullptr, nullptr, nullptr, nullptr);
            else
                gemm_tile<512, ALOAD_PLAIN, EPI_PLAIN>(&sm, mb, nb, 1,
                    g_x, DBEL, nullptr, 0, DBEL,
                    g_wih_h, g_wih_l, DBEL, nullptr, g_gi2, GRU3, nullptr, nullptr,
                    nullptr, nullptr, nullptr, nullptr, nullptr);
        }
        grid_barrier(nblk);

        // Phase C: GRU combine (+ hq bias seed)
        phase_gru(P.b_poh, out + OFF_BEL + (size_t)t * BB * DBEL, gtid, nthr);
        grid_barrier(nblk);

        // Phase D: HQ split-K=4 (256 tiles, atomic into bias-seeded g_hq)
        for (int tile = bid; tile < 256; tile += nblk) {
            int kc = tile >> 6;
            int r = tile & 63;
            int mb = r >> 4, nb = r & 15;
            gemm_tile<512, ALOAD_PLAIN, EPI_ATOMIC>(&sm, mb, nb, kc,
                g_belief, DBEL, obs, DEMB, DBEL,
                g_wpoh_h, g_wpoh_l, DBEL + DEMB, nullptr, g_hq, DHID, nullptr, nullptr,
                nullptr, nullptr, nullptr, nullptr, nullptr);
        }
        grid_barrier(nblk);

        // Phase E: posterior head split-K=8 (128 tiles) -> mq, sq_raw
        for (int tile = bid; tile < 128; tile += nblk) {
            int kc = tile >> 4;
            int r = tile & 15;
            int mb = r >> 2, nb = r & 3;
            gemm_tile<128, ALOAD_ELU, EPI_HEAD_ATOMIC>(&sm, mb, nb, kc,
                g_hq, DHID, nullptr, 0, DHID,
                g_wpos_h, g_wpos_l, DHID, P.b_pos, nullptr, 0,
                out + OFF_MQ + (size_t)t * BB * DST,
                out + OFF_SQ + (size_t)t * BB * DST,
                nullptr, nullptr, nullptr, nullptr, nullptr);
        }
        grid_barrier(nblk);
    }

    // ---- batched prior hidden (3200 tiles) ----
    for (int tile = bid; tile < 3200; tile += nblk) {
        int mb = tile >> 4, nb = tile & 15;
        gemm_tile<1024, ALOAD_PLAIN, EPI_BIAS_ELU>(&sm, mb, nb, 0,
            out + OFF_BEL, DBEL, nullptr, 0, DBEL,
            g_wprh_h, g_wprh_l, DBEL, P.b_prh, g_hp, DHID, nullptr, nullptr,
            nullptr, nullptr, nullptr, nullptr, nullptr);
    }
    grid_barrier(nblk);

    // ---- batched prior head (800 tiles) ----
    for (int tile = bid; tile < 800; tile += nblk) {
        int mb = tile >> 2, nb = tile & 3;
        gemm_tile<1024, ALOAD_PLAIN, EPI_HEAD_STORE>(&sm, mb, nb, 0,
            g_hp, DHID, nullptr, 0, DHID,
            g_wprs_h, g_wprs_l, DHID, P.b_prs, nullptr, 0,
            out + OFF_MP, out + OFF_SP,
            nullptr, nullptr, nullptr, nullptr, nullptr);
    }
    grid_barrier(nblk);

    // ---- samples ----
    for (int i = gtid * 4; i < TT * BB * DST; i += nthr * 4) {
        float4 mp = *reinterpret_cast<const float4*>(out + OFF_MP + i);
        float4 sp = *reinterpret_cast<const float4*>(out + OFF_SP + i);
        float4 ep = __ldg(reinterpret_cast<const float4*>(P.prior_noise + i));
        float4 mq = __ldcg(reinterpret_cast<const float4*>(out + OFF_MQ + i));
        float4 sq = __ldcg(reinterpret_cast<const float4*>(out + OFF_SQ + i));
        float4 eq = __ldg(reinterpret_cast<const float4*>(P.post_noise + i));
        float4 prs, pos, sqo;
        prs.x = mp.x + sp.x * ep.x; prs.y = mp.y + sp.y * ep.y;
        prs.z = mp.z + sp.z * ep.z; prs.w = mp.w + sp.w * ep.w;
        sqo.x = splusf(sq.x) + 0.1f; sqo.y = splusf(sq.y) + 0.1f;
        sqo.z = splusf(sq.z) + 0.1f; sqo.w = splusf(sq.w) + 0.1f;
        pos.x = mq.x + sqo.x * eq.x; pos.y = mq.y + sqo.y * eq.y;
        pos.z = mq.z + sqo.z * eq.z; pos.w = mq.w + sqo.w * eq.w;
        *reinterpret_cast<float4*>(out + OFF_PRS + i) = prs;
        *reinterpret_cast<float4*>(out + OFF_SQ  + i) = sqo;
        *reinterpret_cast<float4*>(out + OFF_POS + i) = pos;
    }
}

extern "C" void kernel_launch(void* const* d_in, const int* in_sizes, int n_in,
                              void* d_out, int out_size)
{
    (void)in_sizes; (void)n_in; (void)out_size;
    Params P;
    P.prev_state   = (const float*)d_in[0];
    P.actions      = (const float*)d_in[1];
    P.prev_belief  = (const float*)d_in[2];
    P.observations = (const float*)d_in[3];
    P.nonterminals = (const float*)d_in[4];
    P.prior_noise  = (const float*)d_in[5];
    P.post_noise   = (const float*)d_in[6];
    P.W_sa  = (const float*)d_in[7];
    P.b_sa  = (const float*)d_in[8];
    P.w_ih  = (const float*)d_in[9];
    P.b_ih  = (const float*)d_in[10];
    P.w_hh  = (const float*)d_in[11];
    P.b_hh  = (const float*)d_in[12];
    P.W_prh = (const float*)d_in[13];
    P.b_prh = (const float*)d_in[14];
    P.W_prs = (const float*)d_in[15];
    P.b_prs = (const float*)d_in[16];
    P.W_poh = (const float*)d_in[17];
    P.b_poh = (const float*)d_in[18];
    P.W_pos = (const float*)d_in[19];
    P.b_pos = (const float*)d_in[20];
    P.out = (float*)d_out;

    int nsm = 0;
    cudaDeviceGetAttribute(&nsm, cudaDevAttrMultiProcessorCount, 0);
    if (nsm <= 0) nsm = 148;

    int bpm = 0;
    cudaOccupancyMaxActiveBlocksPerMultiprocessor(&bpm, mega, THR, 0);
    if (bpm < 1) bpm = 1;
    if (bpm > 4) bpm = 4;
    P.nblk = nsm * bpm;

    mega<<<P.nblk, THR>>>(P);
}

// round 10
// speedup vs baseline: 1.4459x; 1.4459x over previous
#include <cuda_runtime.h>
#include <cuda_bf16.h>
#include <math.h>
#include <stdint.h>

#define TT 50
#define BB 256
#define DBEL 1024
#define DST 128
#define DACT 32
#define DHID 1024
#define DEMB 1024
#define GRU3 (3*DBEL)

// ---- output layout (beliefs, prior_s, mp, sp, post_s, mq, sq) ----
static constexpr size_t OFF_BEL = 0;
static constexpr size_t OFF_PRS = (size_t)TT*BB*DBEL;
static constexpr size_t OFF_MP  = OFF_PRS + (size_t)TT*BB*DST;
static constexpr size_t OFF_SP  = OFF_MP  + (size_t)TT*BB*DST;
static constexpr size_t OFF_POS = OFF_SP  + (size_t)TT*BB*DST;
static constexpr size_t OFF_MQ  = OFF_POS + (size_t)TT*BB*DST;
static constexpr size_t OFF_SQ  = OFF_MQ  + (size_t)TT*BB*DST;

// ================= device buffers =================
// Tiled bf16 hi/lo planes. Tile = 64 rows x 32 cols, 2048 elements contiguous.
// Index: ((row/64)*(K/32) + col/32)*2048 + (row%64)*32 + (col%32)
__device__ __nv_bfloat16 tWsa_h[DBEL*160],      tWsa_l[DBEL*160];
__device__ __nv_bfloat16 tWih_h[GRU3*DBEL],     tWih_l[GRU3*DBEL];
__device__ __nv_bfloat16 tWhh_h[GRU3*DBEL],     tWhh_l[GRU3*DBEL];
__device__ __nv_bfloat16 tWpoh_h[DHID*2048],    tWpoh_l[DHID*2048];
__device__ __nv_bfloat16 tWpos_h[2*DST*DHID],   tWpos_l[2*DST*DHID];
__device__ __nv_bfloat16 tWprh_h[DHID*DBEL],    tWprh_l[DHID*DBEL];
__device__ __nv_bfloat16 tWprs_h[2*DST*DHID],   tWprs_l[2*DST*DHID];

__device__ __nv_bfloat16 Ax_h[BB*DBEL],    Ax_l[BB*DBEL];       // elu(x) planes
__device__ __nv_bfloat16 AbelI_h[BB*DBEL], AbelI_l[BB*DBEL];    // prev_belief planes
__device__ __nv_bfloat16 Abel_h[(size_t)TT*BB*DBEL], Abel_l[(size_t)TT*BB*DBEL]; // belief(t) planes
__device__ __nv_bfloat16 Aobs_h[(size_t)TT*BB*DEMB], Aobs_l[(size_t)TT*BB*DEMB]; // obs planes
__device__ __nv_bfloat16 Ahp_h[(size_t)TT*BB*DHID],  Ahp_l[(size_t)TT*BB*DHID];  // elu prior hidden planes

__device__ float g_gi[BB*GRU3];
__device__ float g_gh[BB*GRU3];
__device__ float g_hq1[BB*DHID];
__device__ float g_hq2[BB*DHID];
__device__ float g_belief[BB*DBEL];

__device__ __forceinline__ float eluf(float x)   { return x > 0.f ? x : expm1f(x); }
__device__ __forceinline__ float splusf(float x) { return fmaxf(x, 0.f) + log1pf(expf(-fabsf(x))); }
__device__ __forceinline__ float sigf(float x)   { return 1.f / (1.f + expf(-x)); }

// ================= small PTX helpers =================
__device__ __forceinline__ void cp16(uint32_t dst, const void* src) {
    asm volatile("cp.async.cg.shared.global [%0], [%1], 16;" :: "r"(dst), "l"(src));
}
__device__ __forceinline__ void cp_commit() { asm volatile("cp.async.commit_group;"); }
__device__ __forceinline__ void cp_wait0()  { asm volatile("cp.async.wait_group 0;"); }

__device__ __forceinline__ void ldsm4(uint32_t (&r)[4], uint32_t addr) {
    asm volatile("ldmatrix.sync.aligned.m8n8.x4.shared.b16 {%0,%1,%2,%3}, [%4];"
        : "=r"(r[0]), "=r"(r[1]), "=r"(r[2]), "=r"(r[3]) : "r"(addr));
}
__device__ __forceinline__ void mma16816(float (&d)[4], const uint32_t (&a)[4], const uint32_t (&b)[2]) {
    asm volatile("mma.sync.aligned.m16n8k16.row.col.f32.bf16.bf16.f32 "
        "{%0,%1,%2,%3}, {%4,%5,%6,%7}, {%8,%9}, {%0,%1,%2,%3};"
        : "+f"(d[0]), "+f"(d[1]), "+f"(d[2]), "+f"(d[3])
        : "r"(a[0]), "r"(a[1]), "r"(a[2]), "r"(a[3]), "r"(b[0]), "r"(b[1]));
}

__device__ __forceinline__ void split_pack8(const float* r, uint4& h, uint4& l)
{
    uint32_t hw[4], lw[4];
#pragma unroll
    for (int i = 0; i < 4; i++) {
        __nv_bfloat16 h0 = __float2bfloat16_rn(r[2*i]);
        __nv_bfloat16 h1 = __float2bfloat16_rn(r[2*i+1]);
        __nv_bfloat16 l0 = __float2bfloat16_rn(r[2*i]   - __bfloat162float(h0));
        __nv_bfloat16 l1 = __float2bfloat16_rn(r[2*i+1] - __bfloat162float(h1));
        __nv_bfloat162 hp = __halves2bfloat162(h0, h1);
        __nv_bfloat162 lp = __halves2bfloat162(l0, l1);
        hw[i] = *reinterpret_cast<uint32_t*>(&hp);
        lw[i] = *reinterpret_cast<uint32_t*>(&lp);
    }
    h = make_uint4(hw[0], hw[1], hw[2], hw[3]);
    l = make_uint4(lw[0], lw[1], lw[2], lw[3]);
}

// store a float4 value into tiled hi/lo planes (K-per-row = 32 tiling, kspm fixed 32 except weights)
__device__ __forceinline__ void store_planes4(__nv_bfloat16* h, __nv_bfloat16* l, size_t idx, float4 v)
{
    __nv_bfloat16 h0 = __float2bfloat16_rn(v.x), h1 = __float2bfloat16_rn(v.y);
    __nv_bfloat16 h2 = __float2bfloat16_rn(v.z), h3 = __float2bfloat16_rn(v.w);
    __nv_bfloat16 l0 = __float2bfloat16_rn(v.x - __bfloat162float(h0));
    __nv_bfloat16 l1 = __float2bfloat16_rn(v.y - __bfloat162float(h1));
    __nv_bfloat16 l2 = __float2bfloat16_rn(v.z - __bfloat162float(h2));
    __nv_bfloat16 l3 = __float2bfloat16_rn(v.w - __bfloat162float(h3));
    *reinterpret_cast<__nv_bfloat162*>(h + idx)     = __halves2bfloat162(h0, h1);
    *reinterpret_cast<__nv_bfloat162*>(h + idx + 2) = __halves2bfloat162(h2, h3);
    *reinterpret_cast<__nv_bfloat162*>(l + idx)     = __halves2bfloat162(l0, l1);
    *reinterpret_cast<__nv_bfloat162*>(l + idx + 2) = __halves2bfloat162(l2, l3);
}

// ================= GEMM core =================
enum { AT_TILED = 0, AT_TILED2 = 1, AT_STATE = 2, AT_ELUSUM = 3 };
enum { EPI_F32 = 0, EPI_TILEA = 1, EPI_HEADAT = 2, EPI_HEADST = 3 };

template<int ALOAD>
__device__ __forceinline__ void load_a8(
    int gm, int k, float* r,
    const float* A2f, int lda2, int K1,
    const float* st_mq, const float* st_sq, const float* st_eps,
    const float* st_nt, const float* st_prev)
{
    if (ALOAD == AT_ELUSUM) {
        const int base = gm * DHID + k;
#pragma unroll
        for (int i = 0; i < 8; i++)
            r[i] = eluf(g_hq1[base + i] + g_hq2[base + i]);
        return;
    }
    if (ALOAD == AT_STATE) {
        if (k < K1) {
            const float nt = st_nt[gm];
            const int base = gm * DST + k;
            if (st_mq) {
#pragma unroll
                for (int i = 0; i < 8; i++) {
                    float s = splusf(st_sq[base + i]) + 0.1f;
                    r[i] = (st_mq[base + i] + s * st_eps[base + i]) * nt;
                }
            } else {
#pragma unroll
                for (int i = 0; i < 8; i++) r[i] = st_prev[base + i] * nt;
            }
        } else {
            const float* p = A2f + (size_t)gm * lda2 + (k - K1);
            float4 v0 = *reinterpret_cast<const float4*>(p);
            float4 v1 = *reinterpret_cast<const float4*>(p + 4);
            r[0] = v0.x; r[1] = v0.y; r[2] = v0.z; r[3] = v0.w;
            r[4] = v1.x; r[5] = v1.y; r[6] = v1.z; r[7] = v1.w;
        }
        return;
    }
#pragma unroll
    for (int i = 0; i < 8; i++) r[i] = 0.f;   // dead path for tiled instantiations
}

template<int EPI>
__device__ __forceinline__ void epi2(
    int kc, int r, int c, float v0, float v1,
    const float* bias, float* out, int ldout,
    float* mean_out, float* std_out,
    __nv_bfloat16* oah, __nv_bfloat16* oal)
{
    if (EPI == EPI_F32) {
        if (bias) { v0 += __ldg(bias + c); v1 += __ldg(bias + c + 1); }
        *reinterpret_cast<float2*>(out + (size_t)r * ldout + c) = make_float2(v0, v1);
    } else if (EPI == EPI_TILEA) {
        v0 = eluf(v0 + __ldg(bias + c));
        v1 = eluf(v1 + __ldg(bias + c + 1));
        __nv_bfloat16 h0 = __float2bfloat16_rn(v0), h1 = __float2bfloat16_rn(v1);
        __nv_bfloat16 l0 = __float2bfloat16_rn(v0 - __bfloat162float(h0));
        __nv_bfloat16 l1 = __float2bfloat16_rn(v1 - __bfloat162float(h1));
        size_t idx = ((size_t)(r >> 6) * 32 + (c >> 5)) * 2048 + (r & 63) * 32 + (c & 31);
        *reinterpret_cast<__nv_bfloat162*>(oah + idx) = __halves2bfloat162(h0, h1);
        *reinterpret_cast<__nv_bfloat162*>(oal + idx) = __halves2bfloat162(l0, l1);
    } else if (EPI == EPI_HEADAT) {
        float b0 = (kc == 0) ? __ldg(bias + c)     : 0.f;
        float b1 = (kc == 0) ? __ldg(bias + c + 1) : 0.f;
        if (c < DST) {
            atomicAdd(mean_out + (size_t)r * DST + c,     v0 + b0);
            atomicAdd(mean_out + (size_t)r * DST + c + 1, v1 + b1);
        } else {
            atomicAdd(std_out + (size_t)r * DST + (c - DST),     v0 + b0);
            atomicAdd(std_out + (size_t)r * DST + (c - DST) + 1, v1 + b1);
        }
    } else { // EPI_HEADST
        float w0 = v0 + __ldg(bias + c), w1 = v1 + __ldg(bias + c + 1);
        if (c < DST) {
            mean_out[(size_t)r * DST + c]     = w0;
            mean_out[(size_t)r * DST + c + 1] = w1;
        } else {
            std_out[(size_t)r * DST + (c - DST)]     = splusf(w0) + 0.1f;
            std_out[(size_t)r * DST + (c - DST) + 1] = splusf(w1) + 0.1f;
        }
    }
}

// 64x64 block tile, 4 warps of 32x32, BK=32, 2-stage cp.async pipeline.
template<int KC, int ALOAD, int EPI>
__device__ __forceinline__ void gemm64(
    int mb, int nb, int kc,
    const __nv_bfloat16* ah1, const __nv_bfloat16* al1,
    const __nv_bfloat16* ah2, const __nv_bfloat16* al2, int ks1,
    const float* A2f, int lda2, int K1,
    const float* st_mq, const float* st_sq, const float* st_eps,
    const float* st_nt, const float* st_prev,
    const __nv_bfloat16* bh, const __nv_bfloat16* bl, int kspmb,
    const float* bias, float* out, int ldout,
    float* mean_out, float* std_out,
    __nv_bfloat16* oah, __nv_bfloat16* oal)
{
    constexpr int NST = KC / 32;
    __shared__ __align__(16) __nv_bfloat16 sA[2][2][64*40];
    __shared__ __align__(16) __nv_bfloat16 sB[2][2][64*40];

    const int tid  = threadIdx.x;
    const int lane = tid & 31;
    const int wid  = tid >> 5;
    const int wm = (wid >> 1) * 32;
    const int wn = (wid & 1) * 32;
    const int ksbeg = kc * NST;

    const uint32_t aBase = (uint32_t)__cvta_generic_to_shared(&sA[0][0][0]);
    const uint32_t bBase = (uint32_t)__cvta_generic_to_shared(&sB[0][0][0]);
    const uint32_t PLN = 64u * 40 * 2;      // 5120 B per plane
    const uint32_t STG = 2u * PLN;

    // coalesced copy coords (shared by all tiled transfers)
    const int e0 = tid * 8, e1 = e0 + 1024;
    const uint32_t d0 = (uint32_t)(((e0 >> 5) * 40 + (e0 & 31)) * 2);
    const uint32_t d1 = (uint32_t)(((e1 >> 5) * 40 + (e1 & 31)) * 2);

    auto fill = [&](int st, int s) {
        const int ks = ksbeg + s;
        {   // B planes (always tiled)
            const __nv_bfloat16* ph = bh + (size_t)(nb * kspmb + ks) * 2048;
            const __nv_bfloat16* pl = bl + (size_t)(nb * kspmb + ks) * 2048;
            const uint32_t b0 = bBase + st * STG;
            cp16(b0 + d0, ph + e0);       cp16(b0 + d1, ph + e1);
            cp16(b0 + PLN + d0, pl + e0); cp16(b0 + PLN + d1, pl + e1);
        }
        if (ALOAD == AT_TILED || ALOAD == AT_TILED2) {
            const __nv_bfloat16 *ph, *pl;
            if (ALOAD == AT_TILED2 && ks >= ks1) {
                ph = ah2 + (size_t)(mb * 32 + (ks - ks1)) * 2048;
                pl = al2 + (size_t)(mb * 32 + (ks - ks1)) * 2048;
            } else {
                ph = ah1 + (size_t)(mb * 32 + ks) * 2048;
                pl = al1 + (size_t)(mb * 32 + ks) * 2048;
            }
            const uint32_t a0 = aBase + st * STG;
            cp16(a0 + d0, ph + e0);       cp16(a0 + d1, ph + e1);
            cp16(a0 + PLN + d0, pl + e0); cp16(a0 + PLN + d1, pl + e1);
        } else {
            // legacy A: synchronous construct + split + store
            const int lrow = tid >> 1, lkb = (tid & 1) << 4;
            const int gm = mb * 64 + lrow;
#pragma unroll
            for (int j = 0; j < 2; j++) {
                float r8[8];
                load_a8<ALOAD>(gm, ks * 32 + lkb + j * 8, r8,
                               A2f, lda2, K1, st_mq, st_sq, st_eps, st_nt, st_prev);
                uint4 hh, ll; split_pack8(r8, hh, ll);
                *reinterpret_cast<uint4*>(&sA[st][0][lrow*40 + lkb + j*8]) = hh;
                *reinterpret_cast<uint4*>(&sA[st][1][lrow*40 + lkb + j*8]) = ll;
            }
        }
    };

    fill(0, 0);
    cp_commit();
    cp_wait0();
    __syncthreads();

    float acc[2][4][4];
#pragma unroll
    for (int i = 0; i < 2; i++)
#pragma unroll
        for (int j = 0; j < 4; j++)
#pragma unroll
            for (int q = 0; q < 4; q++) acc[i][j][q] = 0.f;

    const int amat = lane >> 3, arin = lane & 7;
    const int arowb = wm + ((amat & 1) << 3) + arin;
    const int acol  = (amat >> 1) << 3;
    const int brow = wn + ((lane >> 4) << 3) + (lane & 7);
    const int bcol = ((lane >> 3) & 1) << 3;

#pragma unroll 1
    for (int s = 0; s < NST; s++) {
        const int cur = s & 1, nxt = cur ^ 1;
        const bool more = (s + 1 < NST);
        if (more) { fill(nxt, s + 1); cp_commit(); }
        const uint32_t aOff = aBase + cur * STG;
        const uint32_t bOff = bBase + cur * STG;
#pragma unroll
        for (int kk = 0; kk < 32; kk += 16) {
            uint32_t Ah[2][4], Al[2][4], Bh[4][2], Bl[4][2];
#pragma unroll
            for (int mf = 0; mf < 2; mf++) {
                uint32_t off = (uint32_t)(((arowb + mf*16) * 40 + kk + acol) * 2);
                ldsm4(Ah[mf], aOff + off);
                ldsm4(Al[mf], aOff + PLN + off);
            }
#pragma unroll
            for (int nfp = 0; nfp < 2; nfp++) {
                uint32_t off = (uint32_t)(((brow + nfp*16) * 40 + kk + bcol) * 2);
                uint32_t rh[4], rl[4];
                ldsm4(rh, bOff + off);
                ldsm4(rl, bOff + PLN + off);
                Bh[nfp*2][0]   = rh[0]; Bh[nfp*2][1]   = rh[1];
                Bh[nfp*2+1][0] = rh[2]; Bh[nfp*2+1][1] = rh[3];
                Bl[nfp*2][0]   = rl[0]; Bl[nfp*2][1]   = rl[1];
                Bl[nfp*2+1][0] = rl[2]; Bl[nfp*2+1][1] = rl[3];
            }
#pragma unroll
            for (int mf = 0; mf < 2; mf++)
#pragma unroll
                for (int nf = 0; nf < 4; nf++) {
                    mma16816(acc[mf][nf], Ah[mf], Bh[nf]);
                    mma16816(acc[mf][nf], Ah[mf], Bl[nf]);
                    mma16816(acc[mf][nf], Al[mf], Bh[nf]);
                }
        }
        if (more) cp_wait0();
        __syncthreads();
    }

    const int gr = lane >> 2, gc = (lane & 3) << 1;
#pragma unroll
    for (int mf = 0; mf < 2; mf++)
#pragma unroll
        for (int nf = 0; nf < 4; nf++) {
            int r = mb * 64 + wm + mf * 16 + gr;
            int c = nb * 64 + wn + nf * 8 + gc;
            epi2<EPI>(kc, r,     c, acc[mf][nf][0], acc[mf][nf][1], bias, out, ldout, mean_out, std_out, oah, oal);
            epi2<EPI>(kc, r + 8, c, acc[mf][nf][2], acc[mf][nf][3], bias, out, ldout, mean_out, std_out, oah, oal);
        }
}

// ================= phase wrappers =================
__global__ void __launch_bounds__(128, 2) k_x(
    const float* act, const float* nt, const float* mq, const float* sq,
    const float* eps, const float* prev, const float* b_sa)
{
    int mb = blockIdx.x >> 4, nb = blockIdx.x & 15;
    gemm64<160, AT_STATE, EPI_TILEA>(mb, nb, 0,
        nullptr, nullptr, nullptr, nullptr, 0,
        act, DACT, DST, mq, sq, eps, nt, prev,
        tWsa_h, tWsa_l, 5,
        b_sa, nullptr, 0, nullptr, nullptr, Ax_h, Ax_l);
}

__global__ void __launch_bounds__(128, 4) k_gigh(
    const float* b_ih, const float* b_hh,
    const __nv_bfloat16* belh, const __nv_bfloat16* bell)
{
    int tile = blockIdx.x;
    if (tile < 192) {
        int mb = tile / 48, nb = tile % 48;
        gemm64<1024, AT_TILED, EPI_F32>(mb, nb, 0,
            Ax_h, Ax_l, nullptr, nullptr, 0,
            nullptr, 0, 0, nullptr, nullptr, nullptr, nullptr, nullptr,
            tWih_h, tWih_l, 32,
            b_ih, g_gi, GRU3, nullptr, nullptr, nullptr, nullptr);
    } else {
        int r = tile - 192;
        int mb = r / 48, nb = r % 48;
        gemm64<1024, AT_TILED, EPI_F32>(mb, nb, 0,
            belh, bell, nullptr, nullptr, 0,
            nullptr, 0, 0, nullptr, nullptr, nullptr, nullptr, nullptr,
            tWhh_h, tWhh_l, 32,
            b_hh, g_gh, GRU3, nullptr, nullptr, nullptr, nullptr);
    }
}

__global__ void __launch_bounds__(128) k_gru(
    float* belout, __nv_bfloat16* abh, __nv_bfloat16* abl)
{
    int i4 = (blockIdx.x * 128 + threadIdx.x) * 4;   // over BB*DBEL
    int m = i4 >> 10, j = i4 & 1023;
    const size_t base = (size_t)m * GRU3 + j;
    float4 gir = *reinterpret_cast<const float4*>(g_gi + base);
    float4 giz = *reinterpret_cast<const float4*>(g_gi + base + 1024);
    float4 gin = *reinterpret_cast<const float4*>(g_gi + base + 2048);
    float4 ghr = *reinterpret_cast<const float4*>(g_gh + base);
    float4 ghz = *reinterpret_cast<const float4*>(g_gh + base + 1024);
    float4 ghn = *reinterpret_cast<const float4*>(g_gh + base + 2048);
    float4 b   = *reinterpret_cast<const float4*>(g_belief + i4);
    float4 h;
    { float r = sigf(gir.x + ghr.x), z = sigf(giz.x + ghz.x);
      h.x = (1.f - z) * tanhf(gin.x + r * ghn.x) + z * b.x; }
    { float r = sigf(gir.y + ghr.y), z = sigf(giz.y + ghz.y);
      h.y = (1.f - z) * tanhf(gin.y + r * ghn.y) + z * b.y; }
    { float r = sigf(gir.z + ghr.z), z = sigf(giz.z + ghz.z);
      h.z = (1.f - z) * tanhf(gin.z + r * ghn.z) + z * b.z; }
    { float r = sigf(gir.w + ghr.w), z = sigf(giz.w + ghz.w);
      h.w = (1.f - z) * tanhf(gin.w + r * ghn.w) + z * b.w; }
    *reinterpret_cast<float4*>(g_belief + i4) = h;
    *reinterpret_cast<float4*>(belout + i4)  = h;
    size_t idx = ((size_t)(m >> 6) * 32 + (j >> 5)) * 2048 + (m & 63) * 32 + (j & 31);
    store_planes4(abh, abl, idx, h);
}

__global__ void __launch_bounds__(128, 4) k_hq(
    const __nv_bfloat16* belh, const __nv_bfloat16* bell,
    const __nv_bfloat16* obsh, const __nv_bfloat16* obsl,
    const float* b_poh)
{
    int tile = blockIdx.x;
    int kc = tile >> 6;
    int r = tile & 63;
    int mb = r >> 4, nb = r & 15;
    gemm64<1024, AT_TILED2, EPI_F32>(mb, nb, kc,
        belh, bell, obsh, obsl, 32,
        nullptr, 0, 0, nullptr, nullptr, nullptr, nullptr, nullptr,
        tWpoh_h, tWpoh_l, 64,
        kc == 0 ? b_poh : nullptr,
        kc == 0 ? g_hq1 : g_hq2, DHID,
        nullptr, nullptr, nullptr, nullptr);
}

__global__ void __launch_bounds__(128, 2) k_head(
    const float* b_pos, float* mqo, float* sqo)
{
    int tile = blockIdx.x;
    int kc = tile >> 4;
    int r = tile & 15;
    int mb = r >> 2, nb = r & 3;
    gemm64<128, AT_ELUSUM, EPI_HEADAT>(mb, nb, kc,
        nullptr, nullptr, nullptr, nullptr, 0,
        nullptr, 0, 0, nullptr, nullptr, nullptr, nullptr, nullptr,
        tWpos_h, tWpos_l, 32,
        b_pos, nullptr, 0, mqo, sqo, nullptr, nullptr);
}

__global__ void __launch_bounds__(128, 4) k_prh(const float* b_prh)
{
    int mb = blockIdx.x >> 4, nb = blockIdx.x & 15;
    gemm64<1024, AT_TILED, EPI_TILEA>(mb, nb, 0,
        Abel_h, Abel_l, nullptr, nullptr, 0,
        nullptr, 0, 0, nullptr, nullptr, nullptr, nullptr, nullptr,
        tWprh_h, tWprh_l, 32,
        b_prh, nullptr, 0, nullptr, nullptr, Ahp_h, Ahp_l);
}

__global__ void __launch_bounds__(128, 4) k_prs(const float* b_prs, float* mp, float* sp)
{
    int mb = blockIdx.x >> 2, nb = blockIdx.x & 3;
    gemm64<1024, AT_TILED, EPI_HEADST>(mb, nb, 0,
        Ahp_h, Ahp_l, nullptr, nullptr, 0,
        nullptr, 0, 0, nullptr, nullptr, nullptr, nullptr, nullptr,
        tWprs_h, tWprs_l, 32,
        b_prs, nullptr, 0, mp, sp, nullptr, nullptr);
}

// ================= elementwise kernels =================
// convert fp32 matrix [N][K] -> tiled hi/lo planes
__global__ void conv_w(const float* __restrict__ W, __nv_bfloat16* th, __nv_bfloat16* tl,
                       int N, int K)
{
    int e4 = (blockIdx.x * 256 + threadIdx.x) * 4;
    if (e4 >= N * K) return;
    int n = e4 / K, k = e4 % K;
    float4 v = __ldg(reinterpret_cast<const float4*>(W + e4));
    size_t idx = ((size_t)(n >> 6) * (K >> 5) + (k >> 5)) * 2048 + (n & 63) * 32 + (k & 31);
    store_planes4(th, tl, idx, v);
}

__global__ void k_init(const float* __restrict__ prevb, float* __restrict__ out)
{
    int i4 = (blockIdx.x * 128 + threadIdx.x) * 4;
    if (i4 < 2 * TT * BB * DST)
        *reinterpret_cast<float4*>(out + OFF_MQ + i4) = make_float4(0.f, 0.f, 0.f, 0.f);
    if (i4 < BB * DBEL) {
        float4 v = __ldg(reinterpret_cast<const float4*>(prevb + i4));
        *reinterpret_cast<float4*>(g_belief + i4) = v;
        int m = i4 >> 10, k = i4 & 1023;
        size_t idx = ((size_t)(m >> 6) * 32 + (k >> 5)) * 2048 + (m & 63) * 32 + (k & 31);
        store_planes4(AbelI_h, AbelI_l, idx, v);
    }
}

__global__ void k_sample(float* __restrict__ out,
                         const float* __restrict__ ep, const float* __restrict__ eq)
{
    int i = (blockIdx.x * 128 + threadIdx.x) * 4;
    if (i >= TT * BB * DST) return;
    float4 mp = *reinterpret_cast<const float4*>(out + OFF_MP + i);
    float4 sp = *reinterpret_cast<const float4*>(out + OFF_SP + i);
    float4 e1 = __ldg(reinterpret_cast<const float4*>(ep + i));
    float4 mq = *reinterpret_cast<const float4*>(out + OFF_MQ + i);
    float4 sq = *reinterpret_cast<const float4*>(out + OFF_SQ + i);
    float4 e2 = __ldg(reinterpret_cast<const float4*>(eq + i));
    float4 prs, pos, sqo;
    prs.x = mp.x + sp.x * e1.x; prs.y = mp.y + sp.y * e1.y;
    prs.z = mp.z + sp.z * e1.z; prs.w = mp.w + sp.w * e1.w;
    sqo.x = splusf(sq.x) + 0.1f; sqo.y = splusf(sq.y) + 0.1f;
    sqo.z = splusf(sq.z) + 0.1f; sqo.w = splusf(sq.w) + 0.1f;
    pos.x = mq.x + sqo.x * e2.x; pos.y = mq.y + sqo.y * e2.y;
    pos.z = mq.z + sqo.z * e2.z; pos.w = mq.w + sqo.w * e2.w;
    *reinterpret_cast<float4*>(out + OFF_PRS + i) = prs;
    *reinterpret_cast<float4*>(out + OFF_SQ  + i) = sqo;
    *reinterpret_cast<float4*>(out + OFF_POS + i) = pos;
}

// ================= host =================
extern "C" void kernel_launch(void* const* d_in, const int* in_sizes, int n_in,
                              void* d_out, int out_size)
{
    (void)in_sizes; (void)n_in; (void)out_size;
    const float* prev_state   = (const float*)d_in[0];
    const float* actions      = (const float*)d_in[1];
    const float* prev_belief  = (const float*)d_in[2];
    const float* observations = (const float*)d_in[3];
    const float* nonterminals = (const float*)d_in[4];
    const float* prior_noise  = (const float*)d_in[5];
    const float* post_noise   = (const float*)d_in[6];
    const float* W_sa  = (const float*)d_in[7];
    const float* b_sa  = (const float*)d_in[8];
    const float* w_ih  = (const float*)d_in[9];
    const float* b_ih  = (const float*)d_in[10];
    const float* w_hh  = (const float*)d_in[11];
    const float* b_hh  = (const float*)d_in[12];
    const float* W_prh = (const float*)d_in[13];
    const float* b_prh = (const float*)d_in[14];
    const float* W_prs = (const float*)d_in[15];
    const float* b_prs = (const float*)d_in[16];
    const float* W_poh = (const float*)d_in[17];
    const float* b_poh = (const float*)d_in[18];
    const float* W_pos = (const float*)d_in[19];
    const float* b_pos = (const float*)d_in[20];
    float* out = (float*)d_out;

    __nv_bfloat16 *wsa_h, *wsa_l, *wih_h, *wih_l, *whh_h, *whh_l, *wpoh_h, *wpoh_l,
                  *wpos_h, *wpos_l, *wprh_h, *wprh_l, *wprs_h, *wprs_l,
                  *abel_h, *abel_l, *abeli_h, *abeli_l, *aobs_h, *aobs_l;
    cudaGetSymbolAddress((void**)&wsa_h,  tWsa_h);  cudaGetSymbolAddress((void**)&wsa_l,  tWsa_l);
    cudaGetSymbolAddress((void**)&wih_h,  tWih_h);  cudaGetSymbolAddress((void**)&wih_l,  tWih_l);
    cudaGetSymbolAddress((void**)&whh_h,  tWhh_h);  cudaGetSymbolAddress((void**)&whh_l,  tWhh_l);
    cudaGetSymbolAddress((void**)&wpoh_h, tWpoh_h); cudaGetSymbolAddress((void**)&wpoh_l, tWpoh_l);
    cudaGetSymbolAddress((void**)&wpos_h, tWpos_h); cudaGetSymbolAddress((void**)&wpos_l, tWpos_l);
    cudaGetSymbolAddress((void**)&wprh_h, tWprh_h); cudaGetSymbolAddress((void**)&wprh_l, tWprh_l);
    cudaGetSymbolAddress((void**)&wprs_h, tWprs_h); cudaGetSymbolAddress((void**)&wprs_l, tWprs_l);
    cudaGetSymbolAddress((void**)&abel_h, Abel_h);  cudaGetSymbolAddress((void**)&abel_l, Abel_l);
    cudaGetSymbolAddress((void**)&abeli_h, AbelI_h); cudaGetSymbolAddress((void**)&abeli_l, AbelI_l);
    cudaGetSymbolAddress((void**)&aobs_h, Aobs_h);  cudaGetSymbolAddress((void**)&aobs_l, Aobs_l);

    auto cw = [](const float* W, __nv_bfloat16* h, __nv_bfloat16* l, int N, int K) {
        conv_w<<<(N * K / 4 + 255) / 256, 256>>>(W, h, l, N, K);
    };
    cw(W_sa,  wsa_h,  wsa_l,  DBEL, 160);
    cw(w_ih,  wih_h,  wih_l,  GRU3, DBEL);
    cw(w_hh,  whh_h,  whh_l,  GRU3, DBEL);
    cw(W_poh, wpoh_h, wpoh_l, DHID, 2048);
    cw(W_pos, wpos_h, wpos_l, 2*DST, DHID);
    cw(W_prh, wprh_h, wprh_l, DHID, DBEL);
    cw(W_prs, wprs_h, wprs_l, 2*DST, DHID);
    // observations for all T: [T*B][EMB] has the same (row= t*256+m → global mb) tiling
    cw(observations, aobs_h, aobs_l, TT * BB, DEMB);

    k_init<<<(2 * TT * BB * DST / 4 + 127) / 128, 128>>>(prev_belief, out);

    const size_t TSTEP = (size_t)BB * DBEL;   // plane elements per step
    for (int t = 0; t < TT; t++) {
        const float* act = actions      + (size_t)t * BB * DACT;
        const float* nt  = nonterminals + (size_t)t * BB;
        const float* mq  = (t == 0) ? nullptr : out + OFF_MQ + (size_t)(t-1) * BB * DST;
        const float* sq  = (t == 0) ? nullptr : out + OFF_SQ + (size_t)(t-1) * BB * DST;
        const float* ep  = (t == 0) ? nullptr : post_noise + (size_t)(t-1) * BB * DST;
        const __nv_bfloat16* bph = (t == 0) ? abeli_h : abel_h + (size_t)(t-1) * TSTEP;
        const __nv_bfloat16* bpl = (t == 0) ? abeli_l : abel_l + (size_t)(t-1) * TSTEP;

        k_x   <<<64, 128>>>(act, nt, mq, sq, ep, prev_state, b_sa);
        k_gigh<<<384, 128>>>(b_ih, b_hh, bph, bpl);
        k_gru <<<512, 128>>>(out + OFF_BEL + (size_t)t * BB * DBEL,
                             abel_h + (size_t)t * TSTEP, abel_l + (size_t)t * TSTEP);
        k_hq  <<<128, 128>>>(abel_h + (size_t)t * TSTEP, abel_l + (size_t)t * TSTEP,
                             aobs_h + (size_t)t * TSTEP, aobs_l + (size_t)t * TSTEP, b_poh);
        k_head<<<128, 128>>>(b_pos,
                             out + OFF_MQ + (size_t)t * BB * DST,
                             out + OFF_SQ + (size_t)t * BB * DST);
    }

    k_prh<<<3200, 128>>>(b_prh);
    k_prs<<<800, 128>>>(b_prs, out + OFF_MP, out + OFF_SP);
    k_sample<<<(TT * BB * DST / 4 + 127) / 128, 128>>>(out, prior_noise, post_noise);
}

// round 11
// speedup vs baseline: 1.4537x; 1.0054x over previous
#include <cuda_runtime.h>
#include <cuda_bf16.h>
#include <math.h>
#include <stdint.h>

#define TT 50
#define BB 256
#define DBEL 1024
#define DST 128
#define DACT 32
#define DHID 1024
#define DEMB 1024
#define GRU3 (3*DBEL)

// ---- output layout (beliefs, prior_s, mp, sp, post_s, mq, sq) ----
static constexpr size_t OFF_BEL = 0;
static constexpr size_t OFF_PRS = (size_t)TT*BB*DBEL;
static constexpr size_t OFF_MP  = OFF_PRS + (size_t)TT*BB*DST;
static constexpr size_t OFF_SP  = OFF_MP  + (size_t)TT*BB*DST;
static constexpr size_t OFF_POS = OFF_SP  + (size_t)TT*BB*DST;
static constexpr size_t OFF_MQ  = OFF_POS + (size_t)TT*BB*DST;
static constexpr size_t OFF_SQ  = OFF_MQ  + (size_t)TT*BB*DST;

// ================= device buffers =================
// Tiled bf16 hi/lo planes. Tile = 64 rows x 32 cols, 2048 elements contiguous.
// Index: ((row/64)*(K/32) + col/32)*2048 + (row%64)*32 + (col%32)
__device__ __nv_bfloat16 tWsa_h[DBEL*160],      tWsa_l[DBEL*160];
__device__ __nv_bfloat16 tWih_h[GRU3*DBEL],     tWih_l[GRU3*DBEL];
__device__ __nv_bfloat16 tWhh_h[GRU3*DBEL],     tWhh_l[GRU3*DBEL];
__device__ __nv_bfloat16 tWpoh_h[DHID*2048],    tWpoh_l[DHID*2048];
__device__ __nv_bfloat16 tWpos_h[2*DST*DHID],   tWpos_l[2*DST*DHID];
__device__ __nv_bfloat16 tWprh_h[DHID*DBEL],    tWprh_l[DHID*DBEL];
__device__ __nv_bfloat16 tWprs_h[2*DST*DHID],   tWprs_l[2*DST*DHID];

__device__ __nv_bfloat16 Ax_h[BB*DBEL],    Ax_l[BB*DBEL];       // elu(x) planes
__device__ __nv_bfloat16 AbelI_h[BB*DBEL], AbelI_l[BB*DBEL];    // prev_belief planes
__device__ __nv_bfloat16 Abel_h[(size_t)TT*BB*DBEL], Abel_l[(size_t)TT*BB*DBEL]; // belief(t) planes
__device__ __nv_bfloat16 Aobs_h[(size_t)TT*BB*DEMB], Aobs_l[(size_t)TT*BB*DEMB]; // obs planes
__device__ __nv_bfloat16 Ahp_h[(size_t)TT*BB*DHID],  Ahp_l[(size_t)TT*BB*DHID];  // elu prior hidden planes

__device__ float g_gi[BB*GRU3];
__device__ float g_gh[BB*GRU3];
__device__ float g_hq1[BB*DHID];
__device__ float g_hq2[BB*DHID];
__device__ float g_belief[BB*DBEL];

__device__ __forceinline__ float eluf(float x)   { return x > 0.f ? x : expm1f(x); }
__device__ __forceinline__ float splusf(float x) { return fmaxf(x, 0.f) + log1pf(expf(-fabsf(x))); }
__device__ __forceinline__ float sigf(float x)   { return 1.f / (1.f + expf(-x)); }

// ================= small PTX helpers =================
__device__ __forceinline__ void cp16(uint32_t dst, const void* src) {
    asm volatile("cp.async.cg.shared.global [%0], [%1], 16;" :: "r"(dst), "l"(src));
}
__device__ __forceinline__ void cp_commit() { asm volatile("cp.async.commit_group;"); }
__device__ __forceinline__ void cp_wait0()  { asm volatile("cp.async.wait_group 0;"); }
__device__ __forceinline__ void cp_wait1()  { asm volatile("cp.async.wait_group 1;"); }
__device__ __forceinline__ void cp_wait2()  { asm volatile("cp.async.wait_group 2;"); }

__device__ __forceinline__ void ldsm4(uint32_t (&r)[4], uint32_t addr) {
    asm volatile("ldmatrix.sync.aligned.m8n8.x4.shared.b16 {%0,%1,%2,%3}, [%4];"
        : "=r"(r[0]), "=r"(r[1]), "=r"(r[2]), "=r"(r[3]) : "r"(addr));
}
__device__ __forceinline__ void mma16816(float (&d)[4], const uint32_t (&a)[4], const uint32_t (&b)[2]) {
    asm volatile("mma.sync.aligned.m16n8k16.row.col.f32.bf16.bf16.f32 "
        "{%0,%1,%2,%3}, {%4,%5,%6,%7}, {%8,%9}, {%0,%1,%2,%3};"
        : "+f"(d[0]), "+f"(d[1]), "+f"(d[2]), "+f"(d[3])
        : "r"(a[0]), "r"(a[1]), "r"(a[2]), "r"(a[3]), "r"(b[0]), "r"(b[1]));
}

__device__ __forceinline__ void split_pack8(const float* r, uint4& h, uint4& l)
{
    uint32_t hw[4], lw[4];
#pragma unroll
    for (int i = 0; i < 4; i++) {
        __nv_bfloat16 h0 = __float2bfloat16_rn(r[2*i]);
        __nv_bfloat16 h1 = __float2bfloat16_rn(r[2*i+1]);
        __nv_bfloat16 l0 = __float2bfloat16_rn(r[2*i]   - __bfloat162float(h0));
        __nv_bfloat16 l1 = __float2bfloat16_rn(r[2*i+1] - __bfloat162float(h1));
        __nv_bfloat162 hp = __halves2bfloat162(h0, h1);
        __nv_bfloat162 lp = __halves2bfloat162(l0, l1);
        hw[i] = *reinterpret_cast<uint32_t*>(&hp);
        lw[i] = *reinterpret_cast<uint32_t*>(&lp);
    }
    h = make_uint4(hw[0], hw[1], hw[2], hw[3]);
    l = make_uint4(lw[0], lw[1], lw[2], lw[3]);
}

// store a float4 value into tiled hi/lo planes
__device__ __forceinline__ void store_planes4(__nv_bfloat16* h, __nv_bfloat16* l, size_t idx, float4 v)
{
    __nv_bfloat16 h0 = __float2bfloat16_rn(v.x), h1 = __float2bfloat16_rn(v.y);
    __nv_bfloat16 h2 = __float2bfloat16_rn(v.z), h3 = __float2bfloat16_rn(v.w);
    __nv_bfloat16 l0 = __float2bfloat16_rn(v.x - __bfloat162float(h0));
    __nv_bfloat16 l1 = __float2bfloat16_rn(v.y - __bfloat162float(h1));
    __nv_bfloat16 l2 = __float2bfloat16_rn(v.z - __bfloat162float(h2));
    __nv_bfloat16 l3 = __float2bfloat16_rn(v.w - __bfloat162float(h3));
    *reinterpret_cast<__nv_bfloat162*>(h + idx)     = __halves2bfloat162(h0, h1);
    *reinterpret_cast<__nv_bfloat162*>(h + idx + 2) = __halves2bfloat162(h2, h3);
    *reinterpret_cast<__nv_bfloat162*>(l + idx)     = __halves2bfloat162(l0, l1);
    *reinterpret_cast<__nv_bfloat162*>(l + idx + 2) = __halves2bfloat162(l2, l3);
}

// ================= GEMM core =================
enum { AT_TILED = 0, AT_TILED2 = 1, AT_STATE = 2, AT_ELUSUM = 3 };
enum { EPI_F32 = 0, EPI_TILEA = 1, EPI_HEADAT = 2, EPI_HEADST = 3 };

template<int ALOAD>
__device__ __forceinline__ void load_a8(
    int gm, int k, float* r,
    const float* A2f, int lda2, int K1,
    const float* st_mq, const float* st_sq, const float* st_eps,
    const float* st_nt, const float* st_prev)
{
    if (ALOAD == AT_ELUSUM) {
        const int base = gm * DHID + k;
#pragma unroll
        for (int i = 0; i < 8; i++)
            r[i] = eluf(g_hq1[base + i] + g_hq2[base + i]);
        return;
    }
    if (ALOAD == AT_STATE) {
        if (k < K1) {
            const float nt = st_nt[gm];
            const int base = gm * DST + k;
            if (st_mq) {
#pragma unroll
                for (int i = 0; i < 8; i++) {
                    float s = splusf(st_sq[base + i]) + 0.1f;
                    r[i] = (st_mq[base + i] + s * st_eps[base + i]) * nt;
                }
            } else {
#pragma unroll
                for (int i = 0; i < 8; i++) r[i] = st_prev[base + i] * nt;
            }
        } else {
            const float* p = A2f + (size_t)gm * lda2 + (k - K1);
            float4 v0 = *reinterpret_cast<const float4*>(p);
            float4 v1 = *reinterpret_cast<const float4*>(p + 4);
            r[0] = v0.x; r[1] = v0.y; r[2] = v0.z; r[3] = v0.w;
            r[4] = v1.x; r[5] = v1.y; r[6] = v1.z; r[7] = v1.w;
        }
        return;
    }
#pragma unroll
    for (int i = 0; i < 8; i++) r[i] = 0.f;   // dead path for tiled instantiations
}

template<int EPI>
__device__ __forceinline__ void epi2(
    int kc, int r, int c, float v0, float v1,
    const float* bias, float* out, int ldout,
    float* mean_out, float* std_out,
    __nv_bfloat16* oah, __nv_bfloat16* oal)
{
    if (EPI == EPI_F32) {
        if (bias) { v0 += __ldg(bias + c); v1 += __ldg(bias + c + 1); }
        *reinterpret_cast<float2*>(out + (size_t)r * ldout + c) = make_float2(v0, v1);
    } else if (EPI == EPI_TILEA) {
        v0 = eluf(v0 + __ldg(bias + c));
        v1 = eluf(v1 + __ldg(bias + c + 1));
        __nv_bfloat16 h0 = __float2bfloat16_rn(v0), h1 = __float2bfloat16_rn(v1);
        __nv_bfloat16 l0 = __float2bfloat16_rn(v0 - __bfloat162float(h0));
        __nv_bfloat16 l1 = __float2bfloat16_rn(v1 - __bfloat162float(h1));
        size_t idx = ((size_t)(r >> 6) * 32 + (c >> 5)) * 2048 + (r & 63) * 32 + (c & 31);
        *reinterpret_cast<__nv_bfloat162*>(oah + idx) = __halves2bfloat162(h0, h1);
        *reinterpret_cast<__nv_bfloat162*>(oal + idx) = __halves2bfloat162(l0, l1);
    } else if (EPI == EPI_HEADAT) {
        float b0 = (kc == 0) ? __ldg(bias + c)     : 0.f;
        float b1 = (kc == 0) ? __ldg(bias + c + 1) : 0.f;
        if (c < DST) {
            atomicAdd(mean_out + (size_t)r * DST + c,     v0 + b0);
            atomicAdd(mean_out + (size_t)r * DST + c + 1, v1 + b1);
        } else {
            atomicAdd(std_out + (size_t)r * DST + (c - DST),     v0 + b0);
            atomicAdd(std_out + (size_t)r * DST + (c - DST) + 1, v1 + b1);
        }
    } else { // EPI_HEADST
        float w0 = v0 + __ldg(bias + c), w1 = v1 + __ldg(bias + c + 1);
        if (c < DST) {
            mean_out[(size_t)r * DST + c]     = w0;
            mean_out[(size_t)r * DST + c + 1] = w1;
        } else {
            std_out[(size_t)r * DST + (c - DST)]     = splusf(w0) + 0.1f;
            std_out[(size_t)r * DST + (c - DST) + 1] = splusf(w1) + 0.1f;
        }
    }
}

// 64x64 block tile, 4 warps of 32x32, BK=32, 3-stage cp.async pipeline (2 in flight).
// Dynamic shared memory: 3 stages x (A,B) x (hi,lo) x 64x40 bf16 = 61440 B.
#define GEMM_SMEM 61440
template<int KC, int ALOAD, int EPI>
__device__ __forceinline__ void gemm64(
    int mb, int nb, int kc,
    const __nv_bfloat16* ah1, const __nv_bfloat16* al1,
    const __nv_bfloat16* ah2, const __nv_bfloat16* al2, int ks1,
    const float* A2f, int lda2, int K1,
    const float* st_mq, const float* st_sq, const float* st_eps,
    const float* st_nt, const float* st_prev,
    const __nv_bfloat16* bh, const __nv_bfloat16* bl, int kspmb,
    const float* bias, float* out, int ldout,
    float* mean_out, float* std_out,
    __nv_bfloat16* oah, __nv_bfloat16* oal)
{
    constexpr int NST = KC / 32;
    extern __shared__ __align__(16) char dsm[];
    __nv_bfloat16* smA = reinterpret_cast<__nv_bfloat16*>(dsm);            // 3 stages x 2 planes x 64*40
    __nv_bfloat16* smB = reinterpret_cast<__nv_bfloat16*>(dsm + 30720);

    const int tid  = threadIdx.x;
    const int lane = tid & 31;
    const int wid  = tid >> 5;
    const int wm = (wid >> 1) * 32;
    const int wn = (wid & 1) * 32;
    const int ksbeg = kc * NST;

    const uint32_t aBase = (uint32_t)__cvta_generic_to_shared(smA);
    const uint32_t bBase = (uint32_t)__cvta_generic_to_shared(smB);
    const uint32_t PLN = 64u * 40 * 2;      // 5120 B per plane
    const uint32_t STG = 2u * PLN;          // 10240 B per stage (2 planes)

    // coalesced copy coords (tiled transfers)
    const int e0 = tid * 8, e1 = e0 + 1024;
    const uint32_t d0 = (uint32_t)(((e0 >> 5) * 40 + (e0 & 31)) * 2);
    const uint32_t d1 = (uint32_t)(((e1 >> 5) * 40 + (e1 & 31)) * 2);

    auto fill = [&](int st, int s) {
        const int ks = ksbeg + s;
        {   // B planes (always tiled)
            const __nv_bfloat16* ph = bh + (size_t)(nb * kspmb + ks) * 2048;
            const __nv_bfloat16* pl = bl + (size_t)(nb * kspmb + ks) * 2048;
            const uint32_t b0 = bBase + st * STG;
            cp16(b0 + d0, ph + e0);       cp16(b0 + d1, ph + e1);
            cp16(b0 + PLN + d0, pl + e0); cp16(b0 + PLN + d1, pl + e1);
        }
        if (ALOAD == AT_TILED || ALOAD == AT_TILED2) {
            const __nv_bfloat16 *ph, *pl;
            if (ALOAD == AT_TILED2 && ks >= ks1) {
                ph = ah2 + (size_t)(mb * 32 + (ks - ks1)) * 2048;
                pl = al2 + (size_t)(mb * 32 + (ks - ks1)) * 2048;
            } else {
                ph = ah1 + (size_t)(mb * 32 + ks) * 2048;
                pl = al1 + (size_t)(mb * 32 + ks) * 2048;
            }
            const uint32_t a0 = aBase + st * STG;
            cp16(a0 + d0, ph + e0);       cp16(a0 + d1, ph + e1);
            cp16(a0 + PLN + d0, pl + e0); cp16(a0 + PLN + d1, pl + e1);
        } else {
            // legacy A: synchronous construct + split + store
            const int lrow = tid >> 1, lkb = (tid & 1) << 4;
            const int gm = mb * 64 + lrow;
            __nv_bfloat16* ah_s = smA + (st * STG) / 2;
            __nv_bfloat16* al_s = smA + (st * STG + PLN) / 2;
#pragma unroll
            for (int j = 0; j < 2; j++) {
                float r8[8];
                load_a8<ALOAD>(gm, ks * 32 + lkb + j * 8, r8,
                               A2f, lda2, K1, st_mq, st_sq, st_eps, st_nt, st_prev);
                uint4 hh, ll; split_pack8(r8, hh, ll);
                *reinterpret_cast<uint4*>(&ah_s[lrow*40 + lkb + j*8]) = hh;
                *reinterpret_cast<uint4*>(&al_s[lrow*40 + lkb + j*8]) = ll;
            }
        }
    };

    // ---- prologue: fill stages 0,1 ----
    fill(0, 0); cp_commit();
    if (NST > 1) { fill(1, 1); cp_commit(); }

    float acc[2][4][4];
#pragma unroll
    for (int i = 0; i < 2; i++)
#pragma unroll
        for (int j = 0; j < 4; j++)
#pragma unroll
            for (int q = 0; q < 4; q++) acc[i][j][q] = 0.f;

    const int amat = lane >> 3, arin = lane & 7;
    const int arowb = wm + ((amat & 1) << 3) + arin;
    const int acol  = (amat >> 1) << 3;
    const int brow = wn + ((lane >> 4) << 3) + (lane & 7);
    const int bcol = ((lane >> 3) & 1) << 3;

#pragma unroll 1
    for (int s = 0; s < NST; s++) {
        const int cur = s % 3;
        if (s + 2 < NST) { fill((s + 2) % 3, s + 2); cp_commit(); }
        // wait for stage s: allow up to (committed - (s+1)) groups pending
        if (s + 3 <= NST)      cp_wait2();
        else if (s + 2 <= NST) cp_wait1();
        else                   cp_wait0();
        __syncthreads();

        const uint32_t aOff = aBase + cur * STG;
        const uint32_t bOff = bBase + cur * STG;
#pragma unroll
        for (int kk = 0; kk < 32; kk += 16) {
            uint32_t Ah[2][4], Al[2][4], Bh[4][2], Bl[4][2];
#pragma unroll
            for (int mf = 0; mf < 2; mf++) {
                uint32_t off = (uint32_t)(((arowb + mf*16) * 40 + kk + acol) * 2);
                ldsm4(Ah[mf], aOff + off);
                ldsm4(Al[mf], aOff + PLN + off);
            }
#pragma unroll
            for (int nfp = 0; nfp < 2; nfp++) {
                uint32_t off = (uint32_t)(((brow + nfp*16) * 40 + kk + bcol) * 2);
                uint32_t rh[4], rl[4];
                ldsm4(rh, bOff + off);
                ldsm4(rl, bOff + PLN + off);
                Bh[nfp*2][0]   = rh[0]; Bh[nfp*2][1]   = rh[1];
                Bh[nfp*2+1][0] = rh[2]; Bh[nfp*2+1][1] = rh[3];
                Bl[nfp*2][0]   = rl[0]; Bl[nfp*2][1]   = rl[1];
                Bl[nfp*2+1][0] = rl[2]; Bl[nfp*2+1][1] = rl[3];
            }
#pragma unroll
            for (int mf = 0; mf < 2; mf++)
#pragma unroll
                for (int nf = 0; nf < 4; nf++) {
                    mma16816(acc[mf][nf], Ah[mf], Bh[nf]);
                    mma16816(acc[mf][nf], Ah[mf], Bl[nf]);
                    mma16816(acc[mf][nf], Al[mf], Bh[nf]);
                }
        }
        __syncthreads();   // stage buffer safe to refill next iterations
    }

    const int gr = lane >> 2, gc = (lane & 3) << 1;
#pragma unroll
    for (int mf = 0; mf < 2; mf++)
#pragma unroll
        for (int nf = 0; nf < 4; nf++) {
            int r = mb * 64 + wm + mf * 16 + gr;
            int c = nb * 64 + wn + nf * 8 + gc;
            epi2<EPI>(kc, r,     c, acc[mf][nf][0], acc[mf][nf][1], bias, out, ldout, mean_out, std_out, oah, oal);
            epi2<EPI>(kc, r + 8, c, acc[mf][nf][2], acc[mf][nf][3], bias, out, ldout, mean_out, std_out, oah, oal);
        }
}

// ================= phase wrappers =================
__global__ void __launch_bounds__(128) k_x(
    const float* act, const float* nt, const float* mq, const float* sq,
    const float* eps, const float* prev, const float* b_sa)
{
    int mb = blockIdx.x >> 4, nb = blockIdx.x & 15;
    gemm64<160, AT_STATE, EPI_TILEA>(mb, nb, 0,
        nullptr, nullptr, nullptr, nullptr, 0,
        act, DACT, DST, mq, sq, eps, nt, prev,
        tWsa_h, tWsa_l, 5,
        b_sa, nullptr, 0, nullptr, nullptr, Ax_h, Ax_l);
}

__global__ void __launch_bounds__(128) k_gigh(
    const float* b_ih, const float* b_hh,
    const __nv_bfloat16* belh, const __nv_bfloat16* bell)
{
    int tile = blockIdx.x;
    if (tile < 192) {
        int mb = tile / 48, nb = tile % 48;
        gemm64<1024, AT_TILED, EPI_F32>(mb, nb, 0,
            Ax_h, Ax_l, nullptr, nullptr, 0,
            nullptr, 0, 0, nullptr, nullptr, nullptr, nullptr, nullptr,
            tWih_h, tWih_l, 32,
            b_ih, g_gi, GRU3, nullptr, nullptr, nullptr, nullptr);
    } else {
        int r = tile - 192;
        int mb = r / 48, nb = r % 48;
        gemm64<1024, AT_TILED, EPI_F32>(mb, nb, 0,
            belh, bell, nullptr, nullptr, 0,
            nullptr, 0, 0, nullptr, nullptr, nullptr, nullptr, nullptr,
            tWhh_h, tWhh_l, 32,
            b_hh, g_gh, GRU3, nullptr, nullptr, nullptr, nullptr);
    }
}

__global__ void __launch_bounds__(128) k_gru(
    float* belout, __nv_bfloat16* abh, __nv_bfloat16* abl)
{
    int i4 = (blockIdx.x * 128 + threadIdx.x) * 4;   // over BB*DBEL
    int m = i4 >> 10, j = i4 & 1023;
    const size_t base = (size_t)m * GRU3 + j;
    float4 gir = *reinterpret_cast<const float4*>(g_gi + base);
    float4 giz = *reinterpret_cast<const float4*>(g_gi + base + 1024);
    float4 gin = *reinterpret_cast<const float4*>(g_gi + base + 2048);
    float4 ghr = *reinterpret_cast<const float4*>(g_gh + base);
    float4 ghz = *reinterpret_cast<const float4*>(g_gh + base + 1024);
    float4 ghn = *reinterpret_cast<const float4*>(g_gh + base + 2048);
    float4 b   = *reinterpret_cast<const float4*>(g_belief + i4);
    float4 h;
    { float r = sigf(gir.x + ghr.x), z = sigf(giz.x + ghz.x);
      h.x = (1.f - z) * tanhf(gin.x + r * ghn.x) + z * b.x; }
    { float r = sigf(gir.y + ghr.y), z = sigf(giz.y + ghz.y);
      h.y = (1.f - z) * tanhf(gin.y + r * ghn.y) + z * b.y; }
    { float r = sigf(gir.z + ghr.z), z = sigf(giz.z + ghz.z);
      h.z = (1.f - z) * tanhf(gin.z + r * ghn.z) + z * b.z; }
    { float r = sigf(gir.w + ghr.w), z = sigf(giz.w + ghz.w);
      h.w = (1.f - z) * tanhf(gin.w + r * ghn.w) + z * b.w; }
    *reinterpret_cast<float4*>(g_belief + i4) = h;
    *reinterpret_cast<float4*>(belout + i4)  = h;
    size_t idx = ((size_t)(m >> 6) * 32 + (j >> 5)) * 2048 + (m & 63) * 32 + (j & 31);
    store_planes4(abh, abl, idx, h);
}

__global__ void __launch_bounds__(128) k_hq(
    const __nv_bfloat16* belh, const __nv_bfloat16* bell,
    const __nv_bfloat16* obsh, const __nv_bfloat16* obsl,
    const float* b_poh)
{
    int tile = blockIdx.x;
    int kc = tile >> 6;
    int r = tile & 63;
    int mb = r >> 4, nb = r & 15;
    gemm64<1024, AT_TILED2, EPI_F32>(mb, nb, kc,
        belh, bell, obsh, obsl, 32,
        nullptr, 0, 0, nullptr, nullptr, nullptr, nullptr, nullptr,
        tWpoh_h, tWpoh_l, 64,
        kc == 0 ? b_poh : nullptr,
        kc == 0 ? g_hq1 : g_hq2, DHID,
        nullptr, nullptr, nullptr, nullptr);
}

__global__ void __launch_bounds__(128) k_head(
    const float* b_pos, float* mqo, float* sqo)
{
    int tile = blockIdx.x;
    int kc = tile >> 4;
    int r = tile & 15;
    int mb = r >> 2, nb = r & 3;
    gemm64<128, AT_ELUSUM, EPI_HEADAT>(mb, nb, kc,
        nullptr, nullptr, nullptr, nullptr, 0,
        nullptr, 0, 0, nullptr, nullptr, nullptr, nullptr, nullptr,
        tWpos_h, tWpos_l, 32,
        b_pos, nullptr, 0, mqo, sqo, nullptr, nullptr);
}

__global__ void __launch_bounds__(128) k_prh(const float* b_prh)
{
    int mb = blockIdx.x >> 4, nb = blockIdx.x & 15;
    gemm64<1024, AT_TILED, EPI_TILEA>(mb, nb, 0,
        Abel_h, Abel_l, nullptr, nullptr, 0,
        nullptr, 0, 0, nullptr, nullptr, nullptr, nullptr, nullptr,
        tWprh_h, tWprh_l, 32,
        b_prh, nullptr, 0, nullptr, nullptr, Ahp_h, Ahp_l);
}

__global__ void __launch_bounds__(128) k_prs(const float* b_prs, float* mp, float* sp)
{
    int mb = blockIdx.x >> 2, nb = blockIdx.x & 3;
    gemm64<1024, AT_TILED, EPI_HEADST>(mb, nb, 0,
        Ahp_h, Ahp_l, nullptr, nullptr, 0,
        nullptr, 0, 0, nullptr, nullptr, nullptr, nullptr, nullptr,
        tWprs_h, tWprs_l, 32,
        b_prs, nullptr, 0, mp, sp, nullptr, nullptr);
}

// ================= elementwise kernels =================
__global__ void conv_w(const float* __restrict__ W, __nv_bfloat16* th, __nv_bfloat16* tl,
                       int N, int K)
{
    int e4 = (blockIdx.x * 256 + threadIdx.x) * 4;
    if (e4 >= N * K) return;
    int n = e4 / K, k = e4 % K;
    float4 v = __ldg(reinterpret_cast<const float4*>(W + e4));
    size_t idx = ((size_t)(n >> 6) * (K >> 5) + (k >> 5)) * 2048 + (n & 63) * 32 + (k & 31);
    store_planes4(th, tl, idx, v);
}

__global__ void k_init(const float* __restrict__ prevb, float* __restrict__ out)
{
    int i4 = (blockIdx.x * 128 + threadIdx.x) * 4;
    if (i4 < 2 * TT * BB * DST)
        *reinterpret_cast<float4*>(out + OFF_MQ + i4) = make_float4(0.f, 0.f, 0.f, 0.f);
    if (i4 < BB * DBEL) {
        float4 v = __ldg(reinterpret_cast<const float4*>(prevb + i4));
        *reinterpret_cast<float4*>(g_belief + i4) = v;
        int m = i4 >> 10, k = i4 & 1023;
        size_t idx = ((size_t)(m >> 6) * 32 + (k >> 5)) * 2048 + (m & 63) * 32 + (k & 31);
        store_planes4(AbelI_h, AbelI_l, idx, v);
    }
}

__global__ void k_sample(float* __restrict__ out,
                         const float* __restrict__ ep, const float* __restrict__ eq)
{
    int i = (blockIdx.x * 128 + threadIdx.x) * 4;
    if (i >= TT * BB * DST) return;
    float4 mp = *reinterpret_cast<const float4*>(out + OFF_MP + i);
    float4 sp = *reinterpret_cast<const float4*>(out + OFF_SP + i);
    float4 e1 = __ldg(reinterpret_cast<const float4*>(ep + i));
    float4 mq = *reinterpret_cast<const float4*>(out + OFF_MQ + i);
    float4 sq = *reinterpret_cast<const float4*>(out + OFF_SQ + i);
    float4 e2 = __ldg(reinterpret_cast<const float4*>(eq + i));
    float4 prs, pos, sqo;
    prs.x = mp.x + sp.x * e1.x; prs.y = mp.y + sp.y * e1.y;
    prs.z = mp.z + sp.z * e1.z; prs.w = mp.w + sp.w * e1.w;
    sqo.x = splusf(sq.x) + 0.1f; sqo.y = splusf(sq.y) + 0.1f;
    sqo.z = splusf(sq.z) + 0.1f; sqo.w = splusf(sq.w) + 0.1f;
    pos.x = mq.x + sqo.x * e2.x; pos.y = mq.y + sqo.y * e2.y;
    pos.z = mq.z + sqo.z * e2.z; pos.w = mq.w + sqo.w * e2.w;
    *reinterpret_cast<float4*>(out + OFF_PRS + i) = prs;
    *reinterpret_cast<float4*>(out + OFF_SQ  + i) = sqo;
    *reinterpret_cast<float4*>(out + OFF_POS + i) = pos;
}

// ================= host =================
extern "C" void kernel_launch(void* const* d_in, const int* in_sizes, int n_in,
                              void* d_out, int out_size)
{
    (void)in_sizes; (void)n_in; (void)out_size;
    const float* prev_state   = (const float*)d_in[0];
    const float* actions      = (const float*)d_in[1];
    const float* prev_belief  = (const float*)d_in[2];
    const float* observations = (const float*)d_in[3];
    const float* nonterminals = (const float*)d_in[4];
    const float* prior_noise  = (const float*)d_in[5];
    const float* post_noise   = (const float*)d_in[6];
    const float* W_sa  = (const float*)d_in[7];
    const float* b_sa  = (const float*)d_in[8];
    const float* w_ih  = (const float*)d_in[9];
    const float* b_ih  = (const float*)d_in[10];
    const float* w_hh  = (const float*)d_in[11];
    const float* b_hh  = (const float*)d_in[12];
    const float* W_prh = (const float*)d_in[13];
    const float* b_prh = (const float*)d_in[14];
    const float* W_prs = (const float*)d_in[15];
    const float* b_prs = (const float*)d_in[16];
    const float* W_poh = (const float*)d_in[17];
    const float* b_poh = (const float*)d_in[18];
    const float* W_pos = (const float*)d_in[19];
    const float* b_pos = (const float*)d_in[20];
    float* out = (float*)d_out;

    // allow 60KB dynamic smem on GEMM kernels (idempotent; host-side, capture-safe)
    cudaFuncSetAttribute(k_x,    cudaFuncAttributeMaxDynamicSharedMemorySize, GEMM_SMEM);
    cudaFuncSetAttribute(k_gigh, cudaFuncAttributeMaxDynamicSharedMemorySize, GEMM_SMEM);
    cudaFuncSetAttribute(k_hq,   cudaFuncAttributeMaxDynamicSharedMemorySize, GEMM_SMEM);
    cudaFuncSetAttribute(k_head, cudaFuncAttributeMaxDynamicSharedMemorySize, GEMM_SMEM);
    cudaFuncSetAttribute(k_prh,  cudaFuncAttributeMaxDynamicSharedMemorySize, GEMM_SMEM);
    cudaFuncSetAttribute(k_prs,  cudaFuncAttributeMaxDynamicSharedMemorySize, GEMM_SMEM);

    __nv_bfloat16 *wsa_h, *wsa_l, *wih_h, *wih_l, *whh_h, *whh_l, *wpoh_h, *wpoh_l,
                  *wpos_h, *wpos_l, *wprh_h, *wprh_l, *wprs_h, *wprs_l,
                  *abel_h, *abel_l, *abeli_h, *abeli_l, *aobs_h, *aobs_l;
    cudaGetSymbolAddress((void**)&wsa_h,  tWsa_h);  cudaGetSymbolAddress((void**)&wsa_l,  tWsa_l);
    cudaGetSymbolAddress((void**)&wih_h,  tWih_h);  cudaGetSymbolAddress((void**)&wih_l,  tWih_l);
    cudaGetSymbolAddress((void**)&whh_h,  tWhh_h);  cudaGetSymbolAddress((void**)&whh_l,  tWhh_l);
    cudaGetSymbolAddress((void**)&wpoh_h, tWpoh_h); cudaGetSymbolAddress((void**)&wpoh_l, tWpoh_l);
    cudaGetSymbolAddress((void**)&wpos_h, tWpos_h); cudaGetSymbolAddress((void**)&wpos_l, tWpos_l);
    cudaGetSymbolAddress((void**)&wprh_h, tWprh_h); cudaGetSymbolAddress((void**)&wprh_l, tWprh_l);
    cudaGetSymbolAddress((void**)&wprs_h, tWprs_h); cudaGetSymbolAddress((void**)&wprs_l, tWprs_l);
    cudaGetSymbolAddress((void**)&abel_h, Abel_h);  cudaGetSymbolAddress((void**)&abel_l, Abel_l);
    cudaGetSymbolAddress((void**)&abeli_h, AbelI_h); cudaGetSymbolAddress((void**)&abeli_l, AbelI_l);
    cudaGetSymbolAddress((void**)&aobs_h, Aobs_h);  cudaGetSymbolAddress((void**)&aobs_l, Aobs_l);

    auto cw = [](const float* W, __nv_bfloat16* h, __nv_bfloat16* l, int N, int K) {
        conv_w<<<(N * K / 4 + 255) / 256, 256>>>(W, h, l, N, K);
    };
    cw(W_sa,  wsa_h,  wsa_l,  DBEL, 160);
    cw(w_ih,  wih_h,  wih_l,  GRU3, DBEL);
    cw(w_hh,  whh_h,  whh_l,  GRU3, DBEL);
    cw(W_poh, wpoh_h, wpoh_l, DHID, 2048);
    cw(W_pos, wpos_h, wpos_l, 2*DST, DHID);
    cw(W_prh, wprh_h, wprh_l, DHID, DBEL);
    cw(W_prs, wprs_h, wprs_l, 2*DST, DHID);
    cw(observations, aobs_h, aobs_l, TT * BB, DEMB);

    k_init<<<(2 * TT * BB * DST / 4 + 127) / 128, 128>>>(prev_belief, out);

    const size_t TSTEP = (size_t)BB * DBEL;   // plane elements per step
    for (int t = 0; t < TT; t++) {
        const float* act = actions      + (size_t)t * BB * DACT;
        const float* nt  = nonterminals + (size_t)t * BB;
        const float* mq  = (t == 0) ? nullptr : out + OFF_MQ + (size_t)(t-1) * BB * DST;
        const float* sq  = (t == 0) ? nullptr : out + OFF_SQ + (size_t)(t-1) * BB * DST;
        const float* ep  = (t == 0) ? nullptr : post_noise + (size_t)(t-1) * BB * DST;
        const __nv_bfloat16* bph = (t == 0) ? abeli_h : abel_h + (size_t)(t-1) * TSTEP;
        const __nv_bfloat16* bpl = (t == 0) ? abeli_l : abel_l + (size_t)(t-1) * TSTEP;

        k_x   <<<64, 128, GEMM_SMEM>>>(act, nt, mq, sq, ep, prev_state, b_sa);
        k_gigh<<<384, 128, GEMM_SMEM>>>(b_ih, b_hh, bph, bpl);
        k_gru <<<512, 128>>>(out + OFF_BEL + (size_t)t * BB * DBEL,
                             abel_h + (size_t)t * TSTEP, abel_l + (size_t)t * TSTEP);
        k_hq  <<<128, 128, GEMM_SMEM>>>(abel_h + (size_t)t * TSTEP, abel_l + (size_t)t * TSTEP,
                             aobs_h + (size_t)t * TSTEP, aobs_l + (size_t)t * TSTEP, b_poh);
        k_head<<<128, 128, GEMM_SMEM>>>(b_pos,
                             out + OFF_MQ + (size_t)t * BB * DST,
                             out + OFF_SQ + (size_t)t * BB * DST);
    }

    k_prh<<<3200, 128, GEMM_SMEM>>>(b_prh);
    k_prs<<<800, 128, GEMM_SMEM>>>(b_prs, out + OFF_MP, out + OFF_SP);
    k_sample<<<(TT * BB * DST / 4 + 127) / 128, 128>>>(out, prior_noise, post_noise);
}

// round 12
// speedup vs baseline: 1.4549x; 1.0008x over previous
#include <cuda_runtime.h>
#include <cuda_bf16.h>
#include <math.h>
#include <stdint.h>

#define TT 50
#define BB 256
#define DBEL 1024
#define DST 128
#define DACT 32
#define DHID 1024
#define DEMB 1024
#define GRU3 (3*DBEL)

// ---- output layout (beliefs, prior_s, mp, sp, post_s, mq, sq) ----
static constexpr size_t OFF_BEL = 0;
static constexpr size_t OFF_PRS = (size_t)TT*BB*DBEL;
static constexpr size_t OFF_MP  = OFF_PRS + (size_t)TT*BB*DST;
static constexpr size_t OFF_SP  = OFF_MP  + (size_t)TT*BB*DST;
static constexpr size_t OFF_POS = OFF_SP  + (size_t)TT*BB*DST;
static constexpr size_t OFF_MQ  = OFF_POS + (size_t)TT*BB*DST;
static constexpr size_t OFF_SQ  = OFF_MQ  + (size_t)TT*BB*DST;

// ================= device buffers =================
// Tiled bf16 hi/lo planes. Tile = 64 rows x 32 cols, 2048 elements contiguous.
// Index: ((row/64)*(K/32) + col/32)*2048 + (row%64)*32 + (col%32)
__device__ __nv_bfloat16 tWsa_h[DBEL*160],      tWsa_l[DBEL*160];
__device__ __nv_bfloat16 tWih_h[GRU3*DBEL],     tWih_l[GRU3*DBEL];
__device__ __nv_bfloat16 tWhh_h[GRU3*DBEL],     tWhh_l[GRU3*DBEL];
__device__ __nv_bfloat16 tWpoh_h[DHID*2048],    tWpoh_l[DHID*2048];
__device__ __nv_bfloat16 tWpos_h[2*DST*DHID],   tWpos_l[2*DST*DHID];
__device__ __nv_bfloat16 tWprh_h[DHID*DBEL],    tWprh_l[DHID*DBEL];
__device__ __nv_bfloat16 tWprs_h[2*DST*DHID],   tWprs_l[2*DST*DHID];

__device__ __nv_bfloat16 Ax_h[BB*DBEL],    Ax_l[BB*DBEL];       // elu(x) planes
__device__ __nv_bfloat16 AbelI_h[BB*DBEL], AbelI_l[BB*DBEL];    // prev_belief planes
__device__ __nv_bfloat16 Abel_h[(size_t)TT*BB*DBEL], Abel_l[(size_t)TT*BB*DBEL]; // belief(t) planes
__device__ __nv_bfloat16 Aobs_h[(size_t)TT*BB*DEMB], Aobs_l[(size_t)TT*BB*DEMB]; // obs planes
__device__ __nv_bfloat16 Ahp_h[(size_t)TT*BB*DHID],  Ahp_l[(size_t)TT*BB*DHID];  // elu prior hidden planes

__device__ float g_gi[BB*GRU3];
__device__ float g_gh[BB*GRU3];
__device__ float g_hq1[BB*DHID];
__device__ float g_hq2[BB*DHID];
__device__ float g_belief[BB*DBEL];

__device__ __forceinline__ float eluf(float x)   { return x > 0.f ? x : expm1f(x); }
__device__ __forceinline__ float splusf(float x) { return fmaxf(x, 0.f) + log1pf(expf(-fabsf(x))); }
__device__ __forceinline__ float sigf(float x)   { return 1.f / (1.f + expf(-x)); }

// ================= small PTX helpers =================
__device__ __forceinline__ void cp16(uint32_t dst, const void* src) {
    asm volatile("cp.async.cg.shared.global [%0], [%1], 16;" :: "r"(dst), "l"(src));
}
__device__ __forceinline__ void cp_commit() { asm volatile("cp.async.commit_group;"); }
__device__ __forceinline__ void cp_wait0()  { asm volatile("cp.async.wait_group 0;"); }
__device__ __forceinline__ void cp_wait1()  { asm volatile("cp.async.wait_group 1;"); }
__device__ __forceinline__ void cp_wait2()  { asm volatile("cp.async.wait_group 2;"); }

__device__ __forceinline__ void ldsm4(uint32_t (&r)[4], uint32_t addr) {
    asm volatile("ldmatrix.sync.aligned.m8n8.x4.shared.b16 {%0,%1,%2,%3}, [%4];"
        : "=r"(r[0]), "=r"(r[1]), "=r"(r[2]), "=r"(r[3]) : "r"(addr));
}
__device__ __forceinline__ void mma16816(float (&d)[4], const uint32_t (&a)[4], const uint32_t (&b)[2]) {
    asm volatile("mma.sync.aligned.m16n8k16.row.col.f32.bf16.bf16.f32 "
        "{%0,%1,%2,%3}, {%4,%5,%6,%7}, {%8,%9}, {%0,%1,%2,%3};"
        : "+f"(d[0]), "+f"(d[1]), "+f"(d[2]), "+f"(d[3])
        : "r"(a[0]), "r"(a[1]), "r"(a[2]), "r"(a[3]), "r"(b[0]), "r"(b[1]));
}

__device__ __forceinline__ void split_pack8(const float* r, uint4& h, uint4& l)
{
    uint32_t hw[4], lw[4];
#pragma unroll
    for (int i = 0; i < 4; i++) {
        __nv_bfloat16 h0 = __float2bfloat16_rn(r[2*i]);
        __nv_bfloat16 h1 = __float2bfloat16_rn(r[2*i+1]);
        __nv_bfloat16 l0 = __float2bfloat16_rn(r[2*i]   - __bfloat162float(h0));
        __nv_bfloat16 l1 = __float2bfloat16_rn(r[2*i+1] - __bfloat162float(h1));
        __nv_bfloat162 hp = __halves2bfloat162(h0, h1);
        __nv_bfloat162 lp = __halves2bfloat162(l0, l1);
        hw[i] = *reinterpret_cast<uint32_t*>(&hp);
        lw[i] = *reinterpret_cast<uint32_t*>(&lp);
    }
    h = make_uint4(hw[0], hw[1], hw[2], hw[3]);
    l = make_uint4(lw[0], lw[1], lw[2], lw[3]);
}

// store a float4 value into tiled hi/lo planes
__device__ __forceinline__ void store_planes4(__nv_bfloat16* h, __nv_bfloat16* l, size_t idx, float4 v)
{
    __nv_bfloat16 h0 = __float2bfloat16_rn(v.x), h1 = __float2bfloat16_rn(v.y);
    __nv_bfloat16 h2 = __float2bfloat16_rn(v.z), h3 = __float2bfloat16_rn(v.w);
    __nv_bfloat16 l0 = __float2bfloat16_rn(v.x - __bfloat162float(h0));
    __nv_bfloat16 l1 = __float2bfloat16_rn(v.y - __bfloat162float(h1));
    __nv_bfloat16 l2 = __float2bfloat16_rn(v.z - __bfloat162float(h2));
    __nv_bfloat16 l3 = __float2bfloat16_rn(v.w - __bfloat162float(h3));
    *reinterpret_cast<__nv_bfloat162*>(h + idx)     = __halves2bfloat162(h0, h1);
    *reinterpret_cast<__nv_bfloat162*>(h + idx + 2) = __halves2bfloat162(h2, h3);
    *reinterpret_cast<__nv_bfloat162*>(l + idx)     = __halves2bfloat162(l0, l1);
    *reinterpret_cast<__nv_bfloat162*>(l + idx + 2) = __halves2bfloat162(l2, l3);
}

// ================= GEMM core =================
enum { AT_TILED = 0, AT_TILED2 = 1, AT_STATE = 2, AT_ELUSUM = 3 };
enum { EPI_F32 = 0, EPI_TILEA = 1, EPI_HEADAT = 2, EPI_HEADST = 3 };

template<int ALOAD>
__device__ __forceinline__ void load_a8(
    int gm, int k, float* r,
    const float* A2f, int lda2, int K1,
    const float* st_mq, const float* st_sq, const float* st_eps,
    const float* st_nt, const float* st_prev)
{
    if (ALOAD == AT_ELUSUM) {
        const int base = gm * DHID + k;
#pragma unroll
        for (int i = 0; i < 8; i++)
            r[i] = eluf(g_hq1[base + i] + g_hq2[base + i]);
        return;
    }
    if (ALOAD == AT_STATE) {
        if (k < K1) {
            const float nt = st_nt[gm];
            const int base = gm * DST + k;
            if (st_mq) {
#pragma unroll
                for (int i = 0; i < 8; i++) {
                    float s = splusf(st_sq[base + i]) + 0.1f;
                    r[i] = (st_mq[base + i] + s * st_eps[base + i]) * nt;
                }
            } else {
#pragma unroll
                for (int i = 0; i < 8; i++) r[i] = st_prev[base + i] * nt;
            }
        } else {
            const float* p = A2f + (size_t)gm * lda2 + (k - K1);
            float4 v0 = *reinterpret_cast<const float4*>(p);
            float4 v1 = *reinterpret_cast<const float4*>(p + 4);
            r[0] = v0.x; r[1] = v0.y; r[2] = v0.z; r[3] = v0.w;
            r[4] = v1.x; r[5] = v1.y; r[6] = v1.z; r[7] = v1.w;
        }
        return;
    }
#pragma unroll
    for (int i = 0; i < 8; i++) r[i] = 0.f;   // dead path for tiled instantiations
}

template<int EPI>
__device__ __forceinline__ void epi2(
    int kc, int r, int c, float v0, float v1,
    const float* bias, float* out, int ldout,
    float* mean_out, float* std_out,
    __nv_bfloat16* oah, __nv_bfloat16* oal)
{
    if (EPI == EPI_F32) {
        if (bias) { v0 += __ldg(bias + c); v1 += __ldg(bias + c + 1); }
        *reinterpret_cast<float2*>(out + (size_t)r * ldout + c) = make_float2(v0, v1);
    } else if (EPI == EPI_TILEA) {
        v0 = eluf(v0 + __ldg(bias + c));
        v1 = eluf(v1 + __ldg(bias + c + 1));
        __nv_bfloat16 h0 = __float2bfloat16_rn(v0), h1 = __float2bfloat16_rn(v1);
        __nv_bfloat16 l0 = __float2bfloat16_rn(v0 - __bfloat162float(h0));
        __nv_bfloat16 l1 = __float2bfloat16_rn(v1 - __bfloat162float(h1));
        size_t idx = ((size_t)(r >> 6) * 32 + (c >> 5)) * 2048 + (r & 63) * 32 + (c & 31);
        *reinterpret_cast<__nv_bfloat162*>(oah + idx) = __halves2bfloat162(h0, h1);
        *reinterpret_cast<__nv_bfloat162*>(oal + idx) = __halves2bfloat162(l0, l1);
    } else if (EPI == EPI_HEADAT) {
        float b0 = (kc == 0) ? __ldg(bias + c)     : 0.f;
        float b1 = (kc == 0) ? __ldg(bias + c + 1) : 0.f;
        if (c < DST) {
            atomicAdd(mean_out + (size_t)r * DST + c,     v0 + b0);
            atomicAdd(mean_out + (size_t)r * DST + c + 1, v1 + b1);
        } else {
            atomicAdd(std_out + (size_t)r * DST + (c - DST),     v0 + b0);
            atomicAdd(std_out + (size_t)r * DST + (c - DST) + 1, v1 + b1);
        }
    } else { // EPI_HEADST
        float w0 = v0 + __ldg(bias + c), w1 = v1 + __ldg(bias + c + 1);
        if (c < DST) {
            mean_out[(size_t)r * DST + c]     = w0;
            mean_out[(size_t)r * DST + c + 1] = w1;
        } else {
            std_out[(size_t)r * DST + (c - DST)]     = splusf(w0) + 0.1f;
            std_out[(size_t)r * DST + (c - DST) + 1] = splusf(w1) + 0.1f;
        }
    }
}

// 64x64 block tile, 4 warps of 32x32, BK=32, 3-stage cp.async pipeline (2 in flight).
// Dynamic shared memory: 3 stages x (A,B) x (hi,lo) x 64x40 bf16 = 61440 B.
#define GEMM_SMEM 61440
template<int KC, int ALOAD, int EPI>
__device__ __forceinline__ void gemm64(
    int mb, int nb, int kc,
    const __nv_bfloat16* ah1, const __nv_bfloat16* al1,
    const __nv_bfloat16* ah2, const __nv_bfloat16* al2, int ks1,
    const float* A2f, int lda2, int K1,
    const float* st_mq, const float* st_sq, const float* st_eps,
    const float* st_nt, const float* st_prev,
    const __nv_bfloat16* bh, const __nv_bfloat16* bl, int kspmb,
    const float* bias, float* out, int ldout,
    float* mean_out, float* std_out,
    __nv_bfloat16* oah, __nv_bfloat16* oal)
{
    constexpr int NST = KC / 32;
    extern __shared__ __align__(16) char dsm[];
    __nv_bfloat16* smA = reinterpret_cast<__nv_bfloat16*>(dsm);            // 3 stages x 2 planes x 64*40
    __nv_bfloat16* smB = reinterpret_cast<__nv_bfloat16*>(dsm + 30720);

    const int tid  = threadIdx.x;
    const int lane = tid & 31;
    const int wid  = tid >> 5;
    const int wm = (wid >> 1) * 32;
    const int wn = (wid & 1) * 32;
    const int ksbeg = kc * NST;

    const uint32_t aBase = (uint32_t)__cvta_generic_to_shared(smA);
    const uint32_t bBase = (uint32_t)__cvta_generic_to_shared(smB);
    const uint32_t PLN = 64u * 40 * 2;      // 5120 B per plane
    const uint32_t STG = 2u * PLN;          // 10240 B per stage (2 planes)

    // coalesced copy coords (tiled transfers)
    const int e0 = tid * 8, e1 = e0 + 1024;
    const uint32_t d0 = (uint32_t)(((e0 >> 5) * 40 + (e0 & 31)) * 2);
    const uint32_t d1 = (uint32_t)(((e1 >> 5) * 40 + (e1 & 31)) * 2);

    auto fill = [&](int st, int s) {
        const int ks = ksbeg + s;
        {   // B planes (always tiled)
            const __nv_bfloat16* ph = bh + (size_t)(nb * kspmb + ks) * 2048;
            const __nv_bfloat16* pl = bl + (size_t)(nb * kspmb + ks) * 2048;
            const uint32_t b0 = bBase + st * STG;
            cp16(b0 + d0, ph + e0);       cp16(b0 + d1, ph + e1);
            cp16(b0 + PLN + d0, pl + e0); cp16(b0 + PLN + d1, pl + e1);
        }
        if (ALOAD == AT_TILED || ALOAD == AT_TILED2) {
            const __nv_bfloat16 *ph, *pl;
            if (ALOAD == AT_TILED2 && ks >= ks1) {
                ph = ah2 + (size_t)(mb * 32 + (ks - ks1)) * 2048;
                pl = al2 + (size_t)(mb * 32 + (ks - ks1)) * 2048;
            } else {
                ph = ah1 + (size_t)(mb * 32 + ks) * 2048;
                pl = al1 + (size_t)(mb * 32 + ks) * 2048;
            }
            const uint32_t a0 = aBase + st * STG;
            cp16(a0 + d0, ph + e0);       cp16(a0 + d1, ph + e1);
            cp16(a0 + PLN + d0, pl + e0); cp16(a0 + PLN + d1, pl + e1);
        } else {
            // legacy A: synchronous construct + split + store
            const int lrow = tid >> 1, lkb = (tid & 1) << 4;
            const int gm = mb * 64 + lrow;
            __nv_bfloat16* ah_s = smA + (st * STG) / 2;
            __nv_bfloat16* al_s = smA + (st * STG + PLN) / 2;
#pragma unroll
            for (int j = 0; j < 2; j++) {
                float r8[8];
                load_a8<ALOAD>(gm, ks * 32 + lkb + j * 8, r8,
                               A2f, lda2, K1, st_mq, st_sq, st_eps, st_nt, st_prev);
                uint4 hh, ll; split_pack8(r8, hh, ll);
                *reinterpret_cast<uint4*>(&ah_s[lrow*40 + lkb + j*8]) = hh;
                *reinterpret_cast<uint4*>(&al_s[lrow*40 + lkb + j*8]) = ll;
            }
        }
    };

    // ---- prologue: fill stages 0,1 ----
    fill(0, 0); cp_commit();
    if (NST > 1) { fill(1, 1); cp_commit(); }

    float acc[2][4][4];
#pragma unroll
    for (int i = 0; i < 2; i++)
#pragma unroll
        for (int j = 0; j < 4; j++)
#pragma unroll
            for (int q = 0; q < 4; q++) acc[i][j][q] = 0.f;

    const int amat = lane >> 3, arin = lane & 7;
    const int arowb = wm + ((amat & 1) << 3) + arin;
    const int acol  = (amat >> 1) << 3;
    const int brow = wn + ((lane >> 4) << 3) + (lane & 7);
    const int bcol = ((lane >> 3) & 1) << 3;

#pragma unroll 1
    for (int s = 0; s < NST; s++) {
        const int cur = s % 3;
        if (s + 2 < NST) { fill((s + 2) % 3, s + 2); cp_commit(); }
        // wait for stage s: allow up to (committed - (s+1)) groups pending
        if (s + 3 <= NST)      cp_wait2();
        else if (s + 2 <= NST) cp_wait1();
        else                   cp_wait0();
        __syncthreads();

        const uint32_t aOff = aBase + cur * STG;
        const uint32_t bOff = bBase + cur * STG;
#pragma unroll
        for (int kk = 0; kk < 32; kk += 16) {
            uint32_t Ah[2][4], Al[2][4], Bh[4][2], Bl[4][2];
#pragma unroll
            for (int mf = 0; mf < 2; mf++) {
                uint32_t off = (uint32_t)(((arowb + mf*16) * 40 + kk + acol) * 2);
                ldsm4(Ah[mf], aOff + off);
                ldsm4(Al[mf], aOff + PLN + off);
            }
#pragma unroll
            for (int nfp = 0; nfp < 2; nfp++) {
                uint32_t off = (uint32_t)(((brow + nfp*16) * 40 + kk + bcol) * 2);
                uint32_t rh[4], rl[4];
                ldsm4(rh, bOff + off);
                ldsm4(rl, bOff + PLN + off);
                Bh[nfp*2][0]   = rh[0]; Bh[nfp*2][1]   = rh[1];
                Bh[nfp*2+1][0] = rh[2]; Bh[nfp*2+1][1] = rh[3];
                Bl[nfp*2][0]   = rl[0]; Bl[nfp*2][1]   = rl[1];
                Bl[nfp*2+1][0] = rl[2]; Bl[nfp*2+1][1] = rl[3];
            }
#pragma unroll
            for (int mf = 0; mf < 2; mf++)
#pragma unroll
                for (int nf = 0; nf < 4; nf++) {
                    mma16816(acc[mf][nf], Ah[mf], Bh[nf]);
                    mma16816(acc[mf][nf], Ah[mf], Bl[nf]);
                    mma16816(acc[mf][nf], Al[mf], Bh[nf]);
                }
        }
        __syncthreads();   // stage buffer safe to refill next iterations
    }

    const int gr = lane >> 2, gc = (lane & 3) << 1;
#pragma unroll
    for (int mf = 0; mf < 2; mf++)
#pragma unroll
        for (int nf = 0; nf < 4; nf++) {
            int r = mb * 64 + wm + mf * 16 + gr;
            int c = nb * 64 + wn + nf * 8 + gc;
            epi2<EPI>(kc, r,     c, acc[mf][nf][0], acc[mf][nf][1], bias, out, ldout, mean_out, std_out, oah, oal);
            epi2<EPI>(kc, r + 8, c, acc[mf][nf][2], acc[mf][nf][3], bias, out, ldout, mean_out, std_out, oah, oal);
        }
}

// ================= phase wrappers =================
__global__ void __launch_bounds__(128) k_x(
    const float* act, const float* nt, const float* mq, const float* sq,
    const float* eps, const float* prev, const float* b_sa)
{
    int mb = blockIdx.x >> 4, nb = blockIdx.x & 15;
    gemm64<160, AT_STATE, EPI_TILEA>(mb, nb, 0,
        nullptr, nullptr, nullptr, nullptr, 0,
        act, DACT, DST, mq, sq, eps, nt, prev,
        tWsa_h, tWsa_l, 5,
        b_sa, nullptr, 0, nullptr, nullptr, Ax_h, Ax_l);
}

__global__ void __launch_bounds__(128) k_gigh(
    const float* b_ih, const float* b_hh,
    const __nv_bfloat16* belh, const __nv_bfloat16* bell)
{
    int tile = blockIdx.x;
    if (tile < 192) {
        int mb = tile / 48, nb = tile % 48;
        gemm64<1024, AT_TILED, EPI_F32>(mb, nb, 0,
            Ax_h, Ax_l, nullptr, nullptr, 0,
            nullptr, 0, 0, nullptr, nullptr, nullptr, nullptr, nullptr,
            tWih_h, tWih_l, 32,
            b_ih, g_gi, GRU3, nullptr, nullptr, nullptr, nullptr);
    } else {
        int r = tile - 192;
        int mb = r / 48, nb = r % 48;
        gemm64<1024, AT_TILED, EPI_F32>(mb, nb, 0,
            belh, bell, nullptr, nullptr, 0,
            nullptr, 0, 0, nullptr, nullptr, nullptr, nullptr, nullptr,
            tWhh_h, tWhh_l, 32,
            b_hh, g_gh, GRU3, nullptr, nullptr, nullptr, nullptr);
    }
}

__global__ void __launch_bounds__(128) k_gru(
    float* belout, __nv_bfloat16* abh, __nv_bfloat16* abl)
{
    int i4 = (blockIdx.x * 128 + threadIdx.x) * 4;   // over BB*DBEL
    int m = i4 >> 10, j = i4 & 1023;
    const size_t base = (size_t)m * GRU3 + j;
    float4 gir = *reinterpret_cast<const float4*>(g_gi + base);
    float4 giz = *reinterpret_cast<const float4*>(g_gi + base + 1024);
    float4 gin = *reinterpret_cast<const float4*>(g_gi + base + 2048);
    float4 ghr = *reinterpret_cast<const float4*>(g_gh + base);
    float4 ghz = *reinterpret_cast<const float4*>(g_gh + base + 1024);
    float4 ghn = *reinterpret_cast<const float4*>(g_gh + base + 2048);
    float4 b   = *reinterpret_cast<const float4*>(g_belief + i4);
    float4 h;
    { float r = sigf(gir.x + ghr.x), z = sigf(giz.x + ghz.x);
      h.x = (1.f - z) * tanhf(gin.x + r * ghn.x) + z * b.x; }
    { float r = sigf(gir.y + ghr.y), z = sigf(giz.y + ghz.y);
      h.y = (1.f - z) * tanhf(gin.y + r * ghn.y) + z * b.y; }
    { float r = sigf(gir.z + ghr.z), z = sigf(giz.z + ghz.z);
      h.z = (1.f - z) * tanhf(gin.z + r * ghn.z) + z * b.z; }
    { float r = sigf(gir.w + ghr.w), z = sigf(giz.w + ghz.w);
      h.w = (1.f - z) * tanhf(gin.w + r * ghn.w) + z * b.w; }
    *reinterpret_cast<float4*>(g_belief + i4) = h;
    *reinterpret_cast<float4*>(belout + i4)  = h;
    size_t idx = ((size_t)(m >> 6) * 32 + (j >> 5)) * 2048 + (m & 63) * 32 + (j & 31);
    store_planes4(abh, abl, idx, h);
}

__global__ void __launch_bounds__(128) k_hq(
    const __nv_bfloat16* belh, const __nv_bfloat16* bell,
    const __nv_bfloat16* obsh, const __nv_bfloat16* obsl,
    const float* b_poh)
{
    int tile = blockIdx.x;
    int kc = tile >> 6;
    int r = tile & 63;
    int mb = r >> 4, nb = r & 15;
    gemm64<1024, AT_TILED2, EPI_F32>(mb, nb, kc,
        belh, bell, obsh, obsl, 32,
        nullptr, 0, 0, nullptr, nullptr, nullptr, nullptr, nullptr,
        tWpoh_h, tWpoh_l, 64,
        kc == 0 ? b_poh : nullptr,
        kc == 0 ? g_hq1 : g_hq2, DHID,
        nullptr, nullptr, nullptr, nullptr);
}

__global__ void __launch_bounds__(128) k_head(
    const float* b_pos, float* mqo, float* sqo)
{
    int tile = blockIdx.x;
    int kc = tile >> 4;
    int r = tile & 15;
    int mb = r >> 2, nb = r & 3;
    gemm64<128, AT_ELUSUM, EPI_HEADAT>(mb, nb, kc,
        nullptr, nullptr, nullptr, nullptr, 0,
        nullptr, 0, 0, nullptr, nullptr, nullptr, nullptr, nullptr,
        tWpos_h, tWpos_l, 32,
        b_pos, nullptr, 0, mqo, sqo, nullptr, nullptr);
}

__global__ void __launch_bounds__(128) k_prh(const float* b_prh)
{
    int mb = blockIdx.x >> 4, nb = blockIdx.x & 15;
    gemm64<1024, AT_TILED, EPI_TILEA>(mb, nb, 0,
        Abel_h, Abel_l, nullptr, nullptr, 0,
        nullptr, 0, 0, nullptr, nullptr, nullptr, nullptr, nullptr,
        tWprh_h, tWprh_l, 32,
        b_prh, nullptr, 0, nullptr, nullptr, Ahp_h, Ahp_l);
}

__global__ void __launch_bounds__(128) k_prs(const float* b_prs, float* mp, float* sp)
{
    int mb = blockIdx.x >> 2, nb = blockIdx.x & 3;
    gemm64<1024, AT_TILED, EPI_HEADST>(mb, nb, 0,
        Ahp_h, Ahp_l, nullptr, nullptr, 0,
        nullptr, 0, 0, nullptr, nullptr, nullptr, nullptr, nullptr,
        tWprs_h, tWprs_l, 32,
        b_prs, nullptr, 0, mp, sp, nullptr, nullptr);
}

// ================= elementwise kernels =================
__global__ void conv_w(const float* __restrict__ W, __nv_bfloat16* th, __nv_bfloat16* tl,
                       int N, int K)
{
    int e4 = (blockIdx.x * 256 + threadIdx.x) * 4;
    if (e4 >= N * K) return;
    int n = e4 / K, k = e4 % K;
    float4 v = __ldg(reinterpret_cast<const float4*>(W + e4));
    size_t idx = ((size_t)(n >> 6) * (K >> 5) + (k >> 5)) * 2048 + (n & 63) * 32 + (k & 31);
    store_planes4(th, tl, idx, v);
}

__global__ void k_init(const float* __restrict__ prevb, float* __restrict__ out)
{
    int i4 = (blockIdx.x * 128 + threadIdx.x) * 4;
    if (i4 < 2 * TT * BB * DST)
        *reinterpret_cast<float4*>(out + OFF_MQ + i4) = make_float4(0.f, 0.f, 0.f, 0.f);
    if (i4 < BB * DBEL) {
        float4 v = __ldg(reinterpret_cast<const float4*>(prevb + i4));
        *reinterpret_cast<float4*>(g_belief + i4) = v;
        int m = i4 >> 10, k = i4 & 1023;
        size_t idx = ((size_t)(m >> 6) * 32 + (k >> 5)) * 2048 + (m & 63) * 32 + (k & 31);
        store_planes4(AbelI_h, AbelI_l, idx, v);
    }
}

__global__ void k_sample(float* __restrict__ out,
                         const float* __restrict__ ep, const float* __restrict__ eq)
{
    int i = (blockIdx.x * 128 + threadIdx.x) * 4;
    if (i >= TT * BB * DST) return;
    float4 mp = *reinterpret_cast<const float4*>(out + OFF_MP + i);
    float4 sp = *reinterpret_cast<const float4*>(out + OFF_SP + i);
    float4 e1 = __ldg(reinterpret_cast<const float4*>(ep + i));
    float4 mq = *reinterpret_cast<const float4*>(out + OFF_MQ + i);
    float4 sq = *reinterpret_cast<const float4*>(out + OFF_SQ + i);
    float4 e2 = __ldg(reinterpret_cast<const float4*>(eq + i));
    float4 prs, pos, sqo;
    prs.x = mp.x + sp.x * e1.x; prs.y = mp.y + sp.y * e1.y;
    prs.z = mp.z + sp.z * e1.z; prs.w = mp.w + sp.w * e1.w;
    sqo.x = splusf(sq.x) + 0.1f; sqo.y = splusf(sq.y) + 0.1f;
    sqo.z = splusf(sq.z) + 0.1f; sqo.w = splusf(sq.w) + 0.1f;
    pos.x = mq.x + sqo.x * e2.x; pos.y = mq.y + sqo.y * e2.y;
    pos.z = mq.z + sqo.z * e2.z; pos.w = mq.w + sqo.w * e2.w;
    *reinterpret_cast<float4*>(out + OFF_PRS + i) = prs;
    *reinterpret_cast<float4*>(out + OFF_SQ  + i) = sqo;
    *reinterpret_cast<float4*>(out + OFF_POS + i) = pos;
}

// ================= host =================
extern "C" void kernel_launch(void* const* d_in, const int* in_sizes, int n_in,
                              void* d_out, int out_size)
{
    (void)in_sizes; (void)n_in; (void)out_size;
    const float* prev_state   = (const float*)d_in[0];
    const float* actions      = (const float*)d_in[1];
    const float* prev_belief  = (const float*)d_in[2];
    const float* observations = (const float*)d_in[3];
    const float* nonterminals = (const float*)d_in[4];
    const float* prior_noise  = (const float*)d_in[5];
    const float* post_noise   = (const float*)d_in[6];
    const float* W_sa  = (const float*)d_in[7];
    const float* b_sa  = (const float*)d_in[8];
    const float* w_ih  = (const float*)d_in[9];
    const float* b_ih  = (const float*)d_in[10];
    const float* w_hh  = (const float*)d_in[11];
    const float* b_hh  = (const float*)d_in[12];
    const float* W_prh = (const float*)d_in[13];
    const float* b_prh = (const float*)d_in[14];
    const float* W_prs = (const float*)d_in[15];
    const float* b_prs = (const float*)d_in[16];
    const float* W_poh = (const float*)d_in[17];
    const float* b_poh = (const float*)d_in[18];
    const float* W_pos = (const float*)d_in[19];
    const float* b_pos = (const float*)d_in[20];
    float* out = (float*)d_out;

    // allow 60KB dynamic smem on GEMM kernels (idempotent; host-side, capture-safe)
    cudaFuncSetAttribute(k_x,    cudaFuncAttributeMaxDynamicSharedMemorySize, GEMM_SMEM);
    cudaFuncSetAttribute(k_gigh, cudaFuncAttributeMaxDynamicSharedMemorySize, GEMM_SMEM);
    cudaFuncSetAttribute(k_hq,   cudaFuncAttributeMaxDynamicSharedMemorySize, GEMM_SMEM);
    cudaFuncSetAttribute(k_head, cudaFuncAttributeMaxDynamicSharedMemorySize, GEMM_SMEM);
    cudaFuncSetAttribute(k_prh,  cudaFuncAttributeMaxDynamicSharedMemorySize, GEMM_SMEM);
    cudaFuncSetAttribute(k_prs,  cudaFuncAttributeMaxDynamicSharedMemorySize, GEMM_SMEM);

    __nv_bfloat16 *wsa_h, *wsa_l, *wih_h, *wih_l, *whh_h, *whh_l, *wpoh_h, *wpoh_l,
                  *wpos_h, *wpos_l, *wprh_h, *wprh_l, *wprs_h, *wprs_l,
                  *abel_h, *abel_l, *abeli_h, *abeli_l, *aobs_h, *aobs_l;
    cudaGetSymbolAddress((void**)&wsa_h,  tWsa_h);  cudaGetSymbolAddress((void**)&wsa_l,  tWsa_l);
    cudaGetSymbolAddress((void**)&wih_h,  tWih_h);  cudaGetSymbolAddress((void**)&wih_l,  tWih_l);
    cudaGetSymbolAddress((void**)&whh_h,  tWhh_h);  cudaGetSymbolAddress((void**)&whh_l,  tWhh_l);
    cudaGetSymbolAddress((void**)&wpoh_h, tWpoh_h); cudaGetSymbolAddress((void**)&wpoh_l, tWpoh_l);
    cudaGetSymbolAddress((void**)&wpos_h, tWpos_h); cudaGetSymbolAddress((void**)&wpos_l, tWpos_l);
    cudaGetSymbolAddress((void**)&wprh_h, tWprh_h); cudaGetSymbolAddress((void**)&wprh_l, tWprh_l);
    cudaGetSymbolAddress((void**)&wprs_h, tWprs_h); cudaGetSymbolAddress((void**)&wprs_l, tWprs_l);
    cudaGetSymbolAddress((void**)&abel_h, Abel_h);  cudaGetSymbolAddress((void**)&abel_l, Abel_l);
    cudaGetSymbolAddress((void**)&abeli_h, AbelI_h); cudaGetSymbolAddress((void**)&abeli_l, AbelI_l);
    cudaGetSymbolAddress((void**)&aobs_h, Aobs_h);  cudaGetSymbolAddress((void**)&aobs_l, Aobs_l);

    auto cw = [](const float* W, __nv_bfloat16* h, __nv_bfloat16* l, int N, int K) {
        conv_w<<<(N * K / 4 + 255) / 256, 256>>>(W, h, l, N, K);
    };
    cw(W_sa,  wsa_h,  wsa_l,  DBEL, 160);
    cw(w_ih,  wih_h,  wih_l,  GRU3, DBEL);
    cw(w_hh,  whh_h,  whh_l,  GRU3, DBEL);
    cw(W_poh, wpoh_h, wpoh_l, DHID, 2048);
    cw(W_pos, wpos_h, wpos_l, 2*DST, DHID);
    cw(W_prh, wprh_h, wprh_l, DHID, DBEL);
    cw(W_prs, wprs_h, wprs_l, 2*DST, DHID);
    cw(observations, aobs_h, aobs_l, TT * BB, DEMB);

    k_init<<<(2 * TT * BB * DST / 4 + 127) / 128, 128>>>(prev_belief, out);

    const size_t TSTEP = (size_t)BB * DBEL;   // plane elements per step
    for (int t = 0; t < TT; t++) {
        const float* act = actions      + (size_t)t * BB * DACT;
        const float* nt  = nonterminals + (size_t)t * BB;
        const float* mq  = (t == 0) ? nullptr : out + OFF_MQ + (size_t)(t-1) * BB * DST;
        const float* sq  = (t == 0) ? nullptr : out + OFF_SQ + (size_t)(t-1) * BB * DST;
        const float* ep  = (t == 0) ? nullptr : post_noise + (size_t)(t-1) * BB * DST;
        const __nv_bfloat16* bph = (t == 0) ? abeli_h : abel_h + (size_t)(t-1) * TSTEP;
        const __nv_bfloat16* bpl = (t == 0) ? abeli_l : abel_l + (size_t)(t-1) * TSTEP;

        k_x   <<<64, 128, GEMM_SMEM>>>(act, nt, mq, sq, ep, prev_state, b_sa);
        k_gigh<<<384, 128, GEMM_SMEM>>>(b_ih, b_hh, bph, bpl);
        k_gru <<<512, 128>>>(out + OFF_BEL + (size_t)t * BB * DBEL,
                             abel_h + (size_t)t * TSTEP, abel_l + (size_t)t * TSTEP);
        k_hq  <<<128, 128, GEMM_SMEM>>>(abel_h + (size_t)t * TSTEP, abel_l + (size_t)t * TSTEP,
                             aobs_h + (size_t)t * TSTEP, aobs_l + (size_t)t * TSTEP, b_poh);
        k_head<<<128, 128, GEMM_SMEM>>>(b_pos,
                             out + OFF_MQ + (size_t)t * BB * DST,
                             out + OFF_SQ + (size_t)t * BB * DST);
    }

    k_prh<<<3200, 128, GEMM_SMEM>>>(b_prh);
    k_prs<<<800, 128, GEMM_SMEM>>>(b_prs, out + OFF_MP, out + OFF_SP);
    k_sample<<<(TT * BB * DST / 4 + 127) / 128, 128>>>(out, prior_noise, post_noise);
}

// round 14
// speedup vs baseline: 1.5706x; 1.0795x over previous
#include <cuda_runtime.h>
#include <cuda_fp16.h>
#include <math.h>
#include <stdint.h>

#define TT 50
#define BB 256
#define DBEL 1024
#define DST 128
#define DACT 32
#define DHID 1024
#define DEMB 1024
#define GRU3 (3*DBEL)

static constexpr size_t OFF_BEL = 0;
static constexpr size_t OFF_PRS = (size_t)TT*BB*DBEL;
static constexpr size_t OFF_MP  = OFF_PRS + (size_t)TT*BB*DST;
static constexpr size_t OFF_SP  = OFF_MP  + (size_t)TT*BB*DST;
static constexpr size_t OFF_POS = OFF_SP  + (size_t)TT*BB*DST;
static constexpr size_t OFF_MQ  = OFF_POS + (size_t)TT*BB*DST;
static constexpr size_t OFF_SQ  = OFF_MQ  + (size_t)TT*BB*DST;

// ---- tiled fp16 planes. Tile = 64 rows x 32 cols, 2048 elems contiguous.
// idx = ((row/64)*(K/32) + col/32)*2048 + (row%64)*32 + (col%32)
// B (weights): hi + lo planes (22-bit effective). A (activations): single fp16 plane.
__device__ __half tWsa_h[DBEL*160],      tWsa_l[DBEL*160];
__device__ __half tWih_h[GRU3*DBEL],     tWih_l[GRU3*DBEL];
__device__ __half tWhh_h[GRU3*DBEL],     tWhh_l[GRU3*DBEL];
__device__ __half tWpoh_h[DHID*2048],    tWpoh_l[DHID*2048];
__device__ __half tWpos_h[2*DST*DHID],   tWpos_l[2*DST*DHID];
__device__ __half tWprh_h[DHID*DBEL],    tWprh_l[DHID*DBEL];
__device__ __half tWprs_h[2*DST*DHID],   tWprs_l[2*DST*DHID];

__device__ __half Ax_p[BB*DBEL];
__device__ __half AbelI_p[BB*DBEL];
__device__ __half Abel_p[(size_t)TT*BB*DBEL];
__device__ __half Aobs_p[(size_t)TT*BB*DEMB];
__device__ __half Ahp_p[(size_t)TT*BB*DHID];

__device__ float g_gi[BB*GRU3];
__device__ float g_gh[BB*GRU3];
__device__ float g_hq1[BB*DHID];
__device__ float g_hq2[BB*DHID];
__device__ float g_belief[BB*DBEL];

__device__ __forceinline__ float eluf(float x)   { return x > 0.f ? x : expm1f(x); }
__device__ __forceinline__ float splusf(float x) { return fmaxf(x, 0.f) + log1pf(expf(-fabsf(x))); }
__device__ __forceinline__ float sigf(float x)   { return 1.f / (1.f + expf(-x)); }

// ---- PTX ----
__device__ __forceinline__ void cp16(uint32_t dst, const void* src) {
    asm volatile("cp.async.cg.shared.global [%0], [%1], 16;" :: "r"(dst), "l"(src));
}
__device__ __forceinline__ void cp_commit() { asm volatile("cp.async.commit_group;"); }
__device__ __forceinline__ void cp_wait0()  { asm volatile("cp.async.wait_group 0;"); }

__device__ __forceinline__ void ldsm4(uint32_t (&r)[4], uint32_t addr) {
    asm volatile("ldmatrix.sync.aligned.m8n8.x4.shared.b16 {%0,%1,%2,%3}, [%4];"
        : "=r"(r[0]), "=r"(r[1]), "=r"(r[2]), "=r"(r[3]) : "r"(addr));
}
__device__ __forceinline__ void mmah(float (&d)[4], const uint32_t (&a)[4], const uint32_t (&b)[2]) {
    asm volatile("mma.sync.aligned.m16n8k16.row.col.f32.f16.f16.f32 "
        "{%0,%1,%2,%3}, {%4,%5,%6,%7}, {%8,%9}, {%0,%1,%2,%3};"
        : "+f"(d[0]), "+f"(d[1]), "+f"(d[2]), "+f"(d[3])
        : "r"(a[0]), "r"(a[1]), "r"(a[2]), "r"(a[3]), "r"(b[0]), "r"(b[1]));
}

__device__ __forceinline__ void pack8h(const float* r, uint4& o)
{
    __half2 p0 = __floats2half2_rn(r[0], r[1]);
    __half2 p1 = __floats2half2_rn(r[2], r[3]);
    __half2 p2 = __floats2half2_rn(r[4], r[5]);
    __half2 p3 = __floats2half2_rn(r[6], r[7]);
    o = make_uint4(*reinterpret_cast<uint32_t*>(&p0), *reinterpret_cast<uint32_t*>(&p1),
                   *reinterpret_cast<uint32_t*>(&p2), *reinterpret_cast<uint32_t*>(&p3));
}

// store float4 into a single tiled fp16 plane
__device__ __forceinline__ void store_a4(__half* p, size_t idx, float4 v)
{
    __half2 p0 = __floats2half2_rn(v.x, v.y);
    __half2 p1 = __floats2half2_rn(v.z, v.w);
    *reinterpret_cast<__half2*>(p + idx)     = p0;
    *reinterpret_cast<__half2*>(p + idx + 2) = p1;
}

// ---- GEMM core: 64x64 block, 4 warps of 32x32, BK=32, 2-stage cp.async pipeline ----
// A single fp16 plane; B hi/lo fp16 planes; D += A*Bh + A*Bl (2 MMAs per 16x8x16)
enum { AT_TILED = 0, AT_TILED2 = 1, AT_STATE = 2, AT_ELUSUM = 3 };
enum { EPI_F32 = 0, EPI_TILEA = 1, EPI_HEADAT = 2, EPI_HEADST = 3 };

template<int ALOAD>
__device__ __forceinline__ void load_a8(
    int gm, int k, float* r,
    const float* A2f, int lda2, int K1,
    const float* st_mq, const float* st_sq, const float* st_eps,
    const float* st_nt, const float* st_prev)
{
    if (ALOAD == AT_ELUSUM) {
        const int base = gm * DHID + k;
#pragma unroll
        for (int i = 0; i < 8; i++)
            r[i] = eluf(g_hq1[base + i] + g_hq2[base + i]);
        return;
    }
    if (ALOAD == AT_STATE) {
        if (k < K1) {
            const float nt = st_nt[gm];
            const int base = gm * DST + k;
            if (st_mq) {
#pragma unroll
                for (int i = 0; i < 8; i++) {
                    float s = splusf(st_sq[base + i]) + 0.1f;
                    r[i] = (st_mq[base + i] + s * st_eps[base + i]) * nt;
                }
            } else {
#pragma unroll
                for (int i = 0; i < 8; i++) r[i] = st_prev[base + i] * nt;
            }
        } else {
            const float* p = A2f + (size_t)gm * lda2 + (k - K1);
            float4 v0 = *reinterpret_cast<const float4*>(p);
            float4 v1 = *reinterpret_cast<const float4*>(p + 4);
            r[0] = v0.x; r[1] = v0.y; r[2] = v0.z; r[3] = v0.w;
            r[4] = v1.x; r[5] = v1.y; r[6] = v1.z; r[7] = v1.w;
        }
    }
}

template<int EPI>
__device__ __forceinline__ void epi2(
    int kc, int r, int c, float v0, float v1,
    const float* bias, float* out, int ldout,
    float* mean_out, float* std_out, __half* oap)
{
    if (EPI == EPI_F32) {
        if (bias) { v0 += __ldg(bias + c); v1 += __ldg(bias + c + 1); }
        *reinterpret_cast<float2*>(out + (size_t)r * ldout + c) = make_float2(v0, v1);
    } else if (EPI == EPI_TILEA) {
        v0 = eluf(v0 + __ldg(bias + c));
        v1 = eluf(v1 + __ldg(bias + c + 1));
        size_t idx = ((size_t)(r >> 6) * 32 + (c >> 5)) * 2048 + (r & 63) * 32 + (c & 31);
        __half2 p = __floats2half2_rn(v0, v1);
        *reinterpret_cast<__half2*>(oap + idx) = p;
    } else if (EPI == EPI_HEADAT) {
        float b0 = (kc == 0) ? __ldg(bias + c)     : 0.f;
        float b1 = (kc == 0) ? __ldg(bias + c + 1) : 0.f;
        if (c < DST) {
            atomicAdd(mean_out + (size_t)r * DST + c,     v0 + b0);
            atomicAdd(mean_out + (size_t)r * DST + c + 1, v1 + b1);
        } else {
            atomicAdd(std_out + (size_t)r * DST + (c - DST),     v0 + b0);
            atomicAdd(std_out + (size_t)r * DST + (c - DST) + 1, v1 + b1);
        }
    } else { // EPI_HEADST
        float w0 = v0 + __ldg(bias + c), w1 = v1 + __ldg(bias + c + 1);
        if (c < DST) {
            mean_out[(size_t)r * DST + c]     = w0;
            mean_out[(size_t)r * DST + c + 1] = w1;
        } else {
            std_out[(size_t)r * DST + (c - DST)]     = splusf(w0) + 0.1f;
            std_out[(size_t)r * DST + (c - DST) + 1] = splusf(w1) + 0.1f;
        }
    }
}

// smem: A 2 stages x 5120 B, then B 2 stages x (hi 5120 + lo 5120) = 30720 B total
#define GEMM_SMEM 30720
template<int KC, int ALOAD, int EPI>
__device__ __forceinline__ void gemm64(
    int mb, int nb, int kc,
    const __half* ap1, const __half* ap2, int ks1,
    const float* A2f, int lda2, int K1,
    const float* st_mq, const float* st_sq, const float* st_eps,
    const float* st_nt, const float* st_prev,
    const __half* bh, const __half* bl, int kspmb,
    const float* bias, float* out, int ldout,
    float* mean_out, float* std_out, __half* oap)
{
    constexpr int NST = KC / 32;
    extern __shared__ __align__(16) char dsm[];
    __half* smA = reinterpret_cast<__half*>(dsm);           // 2 x 2560 halfs
    __half* smB = reinterpret_cast<__half*>(dsm + 10240);   // 2 x (2560+2560) halfs

    const int tid  = threadIdx.x;
    const int lane = tid & 31;
    const int wid  = tid >> 5;
    const int wm = (wid >> 1) * 32;
    const int wn = (wid & 1) * 32;
    const int ksbeg = kc * NST;

    const uint32_t aBase = (uint32_t)__cvta_generic_to_shared(smA);
    const uint32_t bBase = (uint32_t)__cvta_generic_to_shared(smB);
    const uint32_t PLN = 64u * 40 * 2;      // 5120 B
    const uint32_t BSTG = 2u * PLN;

    const int e0 = tid * 8, e1 = e0 + 1024;
    const uint32_t d0 = (uint32_t)(((e0 >> 5) * 40 + (e0 & 31)) * 2);
    const uint32_t d1 = (uint32_t)(((e1 >> 5) * 40 + (e1 & 31)) * 2);

    auto fill = [&](int st, int s) {
        const int ks = ksbeg + s;
        {   // B hi/lo planes
            const __half* ph = bh + (size_t)(nb * kspmb + ks) * 2048;
            const __half* pl = bl + (size_t)(nb * kspmb + ks) * 2048;
            const uint32_t b0 = bBase + st * BSTG;
            cp16(b0 + d0, ph + e0);       cp16(b0 + d1, ph + e1);
            cp16(b0 + PLN + d0, pl + e0); cp16(b0 + PLN + d1, pl + e1);
        }
        if (ALOAD == AT_TILED || ALOAD == AT_TILED2) {
            const __half* pa;
            if (ALOAD == AT_TILED2 && ks >= ks1) pa = ap2 + (size_t)(mb * 32 + (ks - ks1)) * 2048;
            else                                  pa = ap1 + (size_t)(mb * 32 + ks) * 2048;
            const uint32_t a0 = aBase + st * PLN;
            cp16(a0 + d0, pa + e0); cp16(a0 + d1, pa + e1);
        } else {
            const int lrow = tid >> 1, lkb = (tid & 1) << 4;
            const int gm = mb * 64 + lrow;
            __half* as = smA + st * 2560;
#pragma unroll
            for (int j = 0; j < 2; j++) {
                float r8[8];
                load_a8<ALOAD>(gm, ks * 32 + lkb + j * 8, r8,
                               A2f, lda2, K1, st_mq, st_sq, st_eps, st_nt, st_prev);
                uint4 pk; pack8h(r8, pk);
                *reinterpret_cast<uint4*>(&as[lrow*40 + lkb + j*8]) = pk;
            }
        }
    };

    fill(0, 0);
    cp_commit();
    cp_wait0();
    __syncthreads();

    float acc[2][4][4];
#pragma unroll
    for (int i = 0; i < 2; i++)
#pragma unroll
        for (int j = 0; j < 4; j++)
#pragma unroll
            for (int q = 0; q < 4; q++) acc[i][j][q] = 0.f;

    const int amat = lane >> 3, arin = lane & 7;
    const int arowb = wm + ((amat & 1) << 3) + arin;
    const int acol  = (amat >> 1) << 3;
    const int brow = wn + ((lane >> 4) << 3) + (lane & 7);
    const int bcol = ((lane >> 3) & 1) << 3;

#pragma unroll 1
    for (int s = 0; s < NST; s++) {
        const int cur = s & 1;
        const bool more = (s + 1 < NST);
        if (more) { fill(cur ^ 1, s + 1); cp_commit(); }
        const uint32_t aOff = aBase + cur * PLN;
        const uint32_t bOff = bBase + cur * BSTG;
#pragma unroll
        for (int kk = 0; kk < 32; kk += 16) {
            uint32_t Am[2][4], Bh[4][2], Bl[4][2];
#pragma unroll
            for (int mf = 0; mf < 2; mf++) {
                uint32_t off = (uint32_t)(((arowb + mf*16) * 40 + kk + acol) * 2);
                ldsm4(Am[mf], aOff + off);
            }
#pragma unroll
            for (int nfp = 0; nfp < 2; nfp++) {
                uint32_t off = (uint32_t)(((brow + nfp*16) * 40 + kk + bcol) * 2);
                uint32_t rh[4], rl[4];
                ldsm4(rh, bOff + off);
                ldsm4(rl, bOff + PLN + off);
                Bh[nfp*2][0]   = rh[0]; Bh[nfp*2][1]   = rh[1];
                Bh[nfp*2+1][0] = rh[2]; Bh[nfp*2+1][1] = rh[3];
                Bl[nfp*2][0]   = rl[0]; Bl[nfp*2][1]   = rl[1];
                Bl[nfp*2+1][0] = rl[2]; Bl[nfp*2+1][1] = rl[3];
            }
#pragma unroll
            for (int mf = 0; mf < 2; mf++)
#pragma unroll
                for (int nf = 0; nf < 4; nf++) {
                    mmah(acc[mf][nf], Am[mf], Bh[nf]);
                    mmah(acc[mf][nf], Am[mf], Bl[nf]);
                }
        }
        if (more) { cp_wait0(); }
        __syncthreads();
    }

    const int gr = lane >> 2, gc = (lane & 3) << 1;
#pragma unroll
    for (int mf = 0; mf < 2; mf++)
#pragma unroll
        for (int nf = 0; nf < 4; nf++) {
            int r = mb * 64 + wm + mf * 16 + gr;
            int c = nb * 64 + wn + nf * 8 + gc;
            epi2<EPI>(kc, r,     c, acc[mf][nf][0], acc[mf][nf][1], bias, out, ldout, mean_out, std_out, oap);
            epi2<EPI>(kc, r + 8, c, acc[mf][nf][2], acc[mf][nf][3], bias, out, ldout, mean_out, std_out, oap);
        }
}

// ---- phase kernels ----
__global__ void __launch_bounds__(128) k_x(
    const float* act, const float* nt, const float* mq, const float* sq,
    const float* eps, const float* prev, const float* b_sa)
{
    int mb = blockIdx.x >> 4, nb = blockIdx.x & 15;
    gemm64<160, AT_STATE, EPI_TILEA>(mb, nb, 0,
        nullptr, nullptr, 0, act, DACT, DST, mq, sq, eps, nt, prev,
        tWsa_h, tWsa_l, 5,
        b_sa, nullptr, 0, nullptr, nullptr, Ax_p);
}

__global__ void __launch_bounds__(128) k_gigh(
    const float* b_ih, const float* b_hh, const __half* belp)
{
    int tile = blockIdx.x;
    if (tile < 192) {
        int mb = tile / 48, nb = tile % 48;
        gemm64<1024, AT_TILED, EPI_F32>(mb, nb, 0,
            Ax_p, nullptr, 0, nullptr, 0, 0, nullptr, nullptr, nullptr, nullptr, nullptr,
            tWih_h, tWih_l, 32,
            b_ih, g_gi, GRU3, nullptr, nullptr, nullptr);
    } else {
        int r = tile - 192;
        int mb = r / 48, nb = r % 48;
        gemm64<1024, AT_TILED, EPI_F32>(mb, nb, 0,
            belp, nullptr, 0, nullptr, 0, 0, nullptr, nullptr, nullptr, nullptr, nullptr,
            tWhh_h, tWhh_l, 32,
            b_hh, g_gh, GRU3, nullptr, nullptr, nullptr);
    }
}

__global__ void __launch_bounds__(128) k_gru(float* belout, __half* abp)
{
    int i4 = (blockIdx.x * 128 + threadIdx.x) * 4;
    int m = i4 >> 10, j = i4 & 1023;
    const size_t base = (size_t)m * GRU3 + j;
    float4 gir = *reinterpret_cast<const float4*>(g_gi + base);
    float4 giz = *reinterpret_cast<const float4*>(g_gi + base + 1024);
    float4 gin = *reinterpret_cast<const float4*>(g_gi + base + 2048);
    float4 ghr = *reinterpret_cast<const float4*>(g_gh + base);
    float4 ghz = *reinterpret_cast<const float4*>(g_gh + base + 1024);
    float4 ghn = *reinterpret_cast<const float4*>(g_gh + base + 2048);
    float4 b   = *reinterpret_cast<const float4*>(g_belief + i4);
    float4 h;
    { float r = sigf(gir.x + ghr.x), z = sigf(giz.x + ghz.x);
      h.x = (1.f - z) * tanhf(gin.x + r * ghn.x) + z * b.x; }
    { float r = sigf(gir.y + ghr.y), z = sigf(giz.y + ghz.y);
      h.y = (1.f - z) * tanhf(gin.y + r * ghn.y) + z * b.y; }
    { float r = sigf(gir.z + ghr.z), z = sigf(giz.z + ghz.z);
      h.z = (1.f - z) * tanhf(gin.z + r * ghn.z) + z * b.z; }
    { float r = sigf(gir.w + ghr.w), z = sigf(giz.w + ghz.w);
      h.w = (1.f - z) * tanhf(gin.w + r * ghn.w) + z * b.w; }
    *reinterpret_cast<float4*>(g_belief + i4) = h;
    *reinterpret_cast<float4*>(belout + i4)  = h;
    size_t idx = ((size_t)(m >> 6) * 32 + (j >> 5)) * 2048 + (m & 63) * 32 + (j & 31);
    store_a4(abp, idx, h);
}

__global__ void __launch_bounds__(128) k_hq(
    const __half* belp, const __half* obsp, const float* b_poh)
{
    int tile = blockIdx.x;
    int kc = tile >> 6;
    int r = tile & 63;
    int mb = r >> 4, nb = r & 15;
    gemm64<1024, AT_TILED2, EPI_F32>(mb, nb, kc,
        belp, obsp, 32, nullptr, 0, 0, nullptr, nullptr, nullptr, nullptr, nullptr,
        tWpoh_h, tWpoh_l, 64,
        kc == 0 ? b_poh : nullptr,
        kc == 0 ? g_hq1 : g_hq2, DHID,
        nullptr, nullptr, nullptr);
}

__global__ void __launch_bounds__(128) k_head(
    const float* b_pos, float* mqo, float* sqo)
{
    int tile = blockIdx.x;
    int kc = tile >> 4;
    int r = tile & 15;
    int mb = r >> 2, nb = r & 3;
    gemm64<128, AT_ELUSUM, EPI_HEADAT>(mb, nb, kc,
        nullptr, nullptr, 0, nullptr, 0, 0, nullptr, nullptr, nullptr, nullptr, nullptr,
        tWpos_h, tWpos_l, 32,
        b_pos, nullptr, 0, mqo, sqo, nullptr);
}

__global__ void __launch_bounds__(128) k_prh(const float* b_prh)
{
    int mb = blockIdx.x >> 4, nb = blockIdx.x & 15;
    gemm64<1024, AT_TILED, EPI_TILEA>(mb, nb, 0,
        Abel_p, nullptr, 0, nullptr, 0, 0, nullptr, nullptr, nullptr, nullptr, nullptr,
        tWprh_h, tWprh_l, 32,
        b_prh, nullptr, 0, nullptr, nullptr, Ahp_p);
}

__global__ void __launch_bounds__(128) k_prs(const float* b_prs, float* mp, float* sp)
{
    int mb = blockIdx.x >> 2, nb = blockIdx.x & 3;
    gemm64<1024, AT_TILED, EPI_HEADST>(mb, nb, 0,
        Ahp_p, nullptr, 0, nullptr, 0, 0, nullptr, nullptr, nullptr, nullptr, nullptr,
        tWprs_h, tWprs_l, 32,
        b_prs, nullptr, 0, mp, sp, nullptr);
}

// ---- elementwise ----
__global__ void conv_w(const float* __restrict__ W, __half* th, __half* tl, int N, int K)
{
    int e2 = (blockIdx.x * 256 + threadIdx.x) * 2;
    if (e2 >= N * K) return;
    int n = e2 / K, k = e2 % K;
    float v0 = __ldg(W + e2), v1 = __ldg(W + e2 + 1);
    __half h0 = __float2half_rn(v0), h1 = __float2half_rn(v1);
    __half l0 = __float2half_rn(v0 - __half2float(h0));
    __half l1 = __float2half_rn(v1 - __half2float(h1));
    size_t idx = ((size_t)(n >> 6) * (K >> 5) + (k >> 5)) * 2048 + (n & 63) * 32 + (k & 31);
    *reinterpret_cast<__half2*>(th + idx) = __halves2half2(h0, h1);
    *reinterpret_cast<__half2*>(tl + idx) = __halves2half2(l0, l1);
}

__global__ void conv_a(const float* __restrict__ X, __half* tp, int N, int K)
{
    int e4 = (blockIdx.x * 256 + threadIdx.x) * 4;
    if (e4 >= N * K) return;
    int n = e4 / K, k = e4 % K;
    float4 v = __ldg(reinterpret_cast<const float4*>(X + e4));
    size_t idx = ((size_t)(n >> 6) * (K >> 5) + (k >> 5)) * 2048 + (n & 63) * 32 + (k & 31);
    store_a4(tp, idx, v);
}

__global__ void k_init(const float* __restrict__ prevb, float* __restrict__ out)
{
    int i4 = (blockIdx.x * 128 + threadIdx.x) * 4;
    if (i4 < 2 * TT * BB * DST)
        *reinterpret_cast<float4*>(out + OFF_MQ + i4) = make_float4(0.f, 0.f, 0.f, 0.f);
    if (i4 < BB * DBEL) {
        float4 v = __ldg(reinterpret_cast<const float4*>(prevb + i4));
        *reinterpret_cast<float4*>(g_belief + i4) = v;
        int m = i4 >> 10, k = i4 & 1023;
        size_t idx = ((size_t)(m >> 6) * 32 + (k >> 5)) * 2048 + (m & 63) * 32 + (k & 31);
        store_a4(AbelI_p, idx, v);
    }
}

__global__ void k_sample(float* __restrict__ out,
                         const float* __restrict__ ep, const float* __restrict__ eq)
{
    int i = (blockIdx.x * 128 + threadIdx.x) * 4;
    if (i >= TT * BB * DST) return;
    float4 mp = *reinterpret_cast<const float4*>(out + OFF_MP + i);
    float4 sp = *reinterpret_cast<const float4*>(out + OFF_SP + i);
    float4 e1 = __ldg(reinterpret_cast<const float4*>(ep + i));
    float4 mq = *reinterpret_cast<const float4*>(out + OFF_MQ + i);
    float4 sq = *reinterpret_cast<const float4*>(out + OFF_SQ + i);
    float4 e2 = __ldg(reinterpret_cast<const float4*>(eq + i));
    float4 prs, pos, sqo;
    prs.x = mp.x + sp.x * e1.x; prs.y = mp.y + sp.y * e1.y;
    prs.z = mp.z + sp.z * e1.z; prs.w = mp.w + sp.w * e1.w;
    sqo.x = splusf(sq.x) + 0.1f; sqo.y = splusf(sq.y) + 0.1f;
    sqo.z = splusf(sq.z) + 0.1f; sqo.w = splusf(sq.w) + 0.1f;
    pos.x = mq.x + sqo.x * e2.x; pos.y = mq.y + sqo.y * e2.y;
    pos.z = mq.z + sqo.z * e2.z; pos.w = mq.w + sqo.w * e2.w;
    *reinterpret_cast<float4*>(out + OFF_PRS + i) = prs;
    *reinterpret_cast<float4*>(out + OFF_SQ  + i) = sqo;
    *reinterpret_cast<float4*>(out + OFF_POS + i) = pos;
}

// ---- host ----
extern "C" void kernel_launch(void* const* d_in, const int* in_sizes, int n_in,
                              void* d_out, int out_size)
{
    (void)in_sizes; (void)n_in; (void)out_size;
    const float* prev_state   = (const float*)d_in[0];
    const float* actions      = (const float*)d_in[1];
    const float* prev_belief  = (const float*)d_in[2];
    const float* observations = (const float*)d_in[3];
    const float* nonterminals = (const float*)d_in[4];
    const float* prior_noise  = (const float*)d_in[5];
    const float* post_noise   = (const float*)d_in[6];
    const float* W_sa  = (const float*)d_in[7];
    const float* b_sa  = (const float*)d_in[8];
    const float* w_ih  = (const float*)d_in[9];
    const float* b_ih  = (const float*)d_in[10];
    const float* w_hh  = (const float*)d_in[11];
    const float* b_hh  = (const float*)d_in[12];
    const float* W_prh = (const float*)d_in[13];
    const float* b_prh = (const float*)d_in[14];
    const float* W_prs = (const float*)d_in[15];
    const float* b_prs = (const float*)d_in[16];
    const float* W_poh = (const float*)d_in[17];
    const float* b_poh = (const float*)d_in[18];
    const float* W_pos = (const float*)d_in[19];
    const float* b_pos = (const float*)d_in[20];
    float* out = (float*)d_out;

    __half *p_wsa_h, *p_wsa_l, *p_wih_h, *p_wih_l, *p_whh_h, *p_whh_l,
           *p_wpoh_h, *p_wpoh_l, *p_wpos_h, *p_wpos_l, *p_wprh_h, *p_wprh_l,
           *p_wprs_h, *p_wprs_l, *p_abel, *p_abeli, *p_aobs;
    cudaGetSymbolAddress((void**)&p_wsa_h,  tWsa_h);  cudaGetSymbolAddress((void**)&p_wsa_l,  tWsa_l);
    cudaGetSymbolAddress((void**)&p_wih_h,  tWih_h);  cudaGetSymbolAddress((void**)&p_wih_l,  tWih_l);
    cudaGetSymbolAddress((void**)&p_whh_h,  tWhh_h);  cudaGetSymbolAddress((void**)&p_whh_l,  tWhh_l);
    cudaGetSymbolAddress((void**)&p_wpoh_h, tWpoh_h); cudaGetSymbolAddress((void**)&p_wpoh_l, tWpoh_l);
    cudaGetSymbolAddress((void**)&p_wpos_h, tWpos_h); cudaGetSymbolAddress((void**)&p_wpos_l, tWpos_l);
    cudaGetSymbolAddress((void**)&p_wprh_h, tWprh_h); cudaGetSymbolAddress((void**)&p_wprh_l, tWprh_l);
    cudaGetSymbolAddress((void**)&p_wprs_h, tWprs_h); cudaGetSymbolAddress((void**)&p_wprs_l, tWprs_l);
    cudaGetSymbolAddress((void**)&p_abel,  Abel_p);
    cudaGetSymbolAddress((void**)&p_abeli, AbelI_p);
    cudaGetSymbolAddress((void**)&p_aobs,  Aobs_p);

    auto cw = [](const float* W, __half* h, __half* l, int N, int K) {
        conv_w<<<(N * K / 2 + 255) / 256, 256>>>(W, h, l, N, K);
    };
    cw(W_sa,  p_wsa_h,  p_wsa_l,  DBEL, 160);
    cw(w_ih,  p_wih_h,  p_wih_l,  GRU3, DBEL);
    cw(w_hh,  p_whh_h,  p_whh_l,  GRU3, DBEL);
    cw(W_poh, p_wpoh_h, p_wpoh_l, DHID, 2048);
    cw(W_pos, p_wpos_h, p_wpos_l, 2*DST, DHID);
    cw(W_prh, p_wprh_h, p_wprh_l, DHID, DBEL);
    cw(W_prs, p_wprs_h, p_wprs_l, 2*DST, DHID);
    conv_a<<<(TT * BB * DEMB / 4 + 255) / 256, 256>>>(observations, p_aobs, TT * BB, DEMB);

    k_init<<<(2 * TT * BB * DST / 4 + 127) / 128, 128>>>(prev_belief, out);

    const size_t TSTEP = (size_t)BB * DBEL;
    for (int t = 0; t < TT; t++) {
        const float* act = actions      + (size_t)t * BB * DACT;
        const float* nt  = nonterminals + (size_t)t * BB;
        const float* mq  = (t == 0) ? nullptr : out + OFF_MQ + (size_t)(t-1) * BB * DST;
        const float* sq  = (t == 0) ? nullptr : out + OFF_SQ + (size_t)(t-1) * BB * DST;
        const float* ep  = (t == 0) ? nullptr : post_noise + (size_t)(t-1) * BB * DST;
        const __half* bpp = (t == 0) ? p_abeli : p_abel + (size_t)(t-1) * TSTEP;

        k_x   <<<64, 128, GEMM_SMEM>>>(act, nt, mq, sq, ep, prev_state, b_sa);
        k_gigh<<<384, 128, GEMM_SMEM>>>(b_ih, b_hh, bpp);
        k_gru <<<512, 128>>>(out + OFF_BEL + (size_t)t * TSTEP, p_abel + (size_t)t * TSTEP);
        k_hq  <<<128, 128, GEMM_SMEM>>>(p_abel + (size_t)t * TSTEP,
                                        p_aobs + (size_t)t * TSTEP, b_poh);
        k_head<<<128, 128, GEMM_SMEM>>>(b_pos,
                                        out + OFF_MQ + (size_t)t * BB * DST,
                                        out + OFF_SQ + (size_t)t * BB * DST);
    }

    k_prh<<<3200, 128, GEMM_SMEM>>>(b_prh);
    k_prs<<<800, 128, GEMM_SMEM>>>(b_prs, out + OFF_MP, out + OFF_SP);
    k_sample<<<(TT * BB * DST / 4 + 127) / 128, 128>>>(out, prior_noise, post_noise);
}

// round 15
// speedup vs baseline: 1.9886x; 1.2661x over previous
#include <cuda_runtime.h>
#include <cuda_fp16.h>
#include <math.h>
#include <stdint.h>

#define TT 50
#define BB 256
#define DBEL 1024
#define DST 128
#define DACT 32
#define DHID 1024
#define DEMB 1024
#define GRU3 (3*DBEL)

static constexpr size_t OFF_BEL = 0;
static constexpr size_t OFF_PRS = (size_t)TT*BB*DBEL;
static constexpr size_t OFF_MP  = OFF_PRS + (size_t)TT*BB*DST;
static constexpr size_t OFF_SP  = OFF_MP  + (size_t)TT*BB*DST;
static constexpr size_t OFF_POS = OFF_SP  + (size_t)TT*BB*DST;
static constexpr size_t OFF_MQ  = OFF_POS + (size_t)TT*BB*DST;
static constexpr size_t OFF_SQ  = OFF_MQ  + (size_t)TT*BB*DST;

// ---- PADTILE format: 64-row x 32-col chunk stored as 64 x 40 halfs (5120 B, padded
// row image identical to the smem tile). chunk = (row/64)*(K/32) + (col/32);
// half-offset = chunk*2560 + (row%64)*40 + (col%32). Pads never read.
#define PT(N, K) ((size_t)((N)/64) * ((K)/32) * 2560)

__device__ __align__(128) __half tWsa_h[PT(DBEL,160)],    tWsa_l[PT(DBEL,160)];
__device__ __align__(128) __half tWih_h[PT(GRU3,DBEL)],   tWih_l[PT(GRU3,DBEL)];
__device__ __align__(128) __half tWhh_h[PT(GRU3,DBEL)],   tWhh_l[PT(GRU3,DBEL)];
__device__ __align__(128) __half tWpoh_h[PT(DHID,2048)],  tWpoh_l[PT(DHID,2048)];
__device__ __align__(128) __half tWpos_h[PT(2*DST,DHID)], tWpos_l[PT(2*DST,DHID)];
__device__ __align__(128) __half tWprh_h[PT(DHID,DBEL)],  tWprh_l[PT(DHID,DBEL)];
__device__ __align__(128) __half tWprs_h[PT(2*DST,DHID)], tWprs_l[PT(2*DST,DHID)];

__device__ __align__(128) __half Ax_p[PT(BB,DBEL)];
__device__ __align__(128) __half AbelI_p[PT(BB,DBEL)];
__device__ __align__(128) __half Abel_p[(size_t)TT*PT(BB,DBEL)];
__device__ __align__(128) __half Aobs_p[(size_t)TT*PT(BB,DEMB)];
__device__ __align__(128) __half Ahp_p[(size_t)TT*PT(BB,DHID)];

__device__ float g_gi[BB*GRU3];
__device__ float g_gh[BB*GRU3];
__device__ float g_hq1[BB*DHID];
__device__ float g_hq2[BB*DHID];
__device__ float g_belief[BB*DBEL];

__device__ __forceinline__ float eluf(float x)   { return x > 0.f ? x : expm1f(x); }
__device__ __forceinline__ float splusf(float x) { return fmaxf(x, 0.f) + log1pf(expf(-fabsf(x))); }
__device__ __forceinline__ float sigf(float x)   { return 1.f / (1.f + expf(-x)); }

// ---- PTX ----
__device__ __forceinline__ void bulkcp(uint32_t dst, const void* src, uint32_t bytes, uint32_t mbar) {
    asm volatile("cp.async.bulk.shared::cluster.global.mbarrier::complete_tx::bytes [%0], [%1], %2, [%3];"
        :: "r"(dst), "l"(src), "r"(bytes), "r"(mbar) : "memory");
}
#define MBAR_INIT(a, c) \
    asm volatile("mbarrier.init.shared.b64 [%0], %1;" :: "r"((uint32_t)(a)), "r"((uint32_t)(c)) : "memory")
#define MBAR_EXPECT(a, b) \
    asm volatile("mbarrier.arrive.expect_tx.shared.b64 _, [%0], %1;" :: "r"((uint32_t)(a)), "r"((uint32_t)(b)) : "memory")
#define MBAR_WAIT(a, p) do { \
    uint32_t _m = (uint32_t)(a); uint32_t _p = (uint32_t)(p); uint32_t _d; \
    asm volatile("{\n\t.reg .pred q;\n\tmbarrier.try_wait.parity.acquire.cta.shared::cta.b64 q, [%1], %2;\n\tselp.b32 %0, 1, 0, q;\n\t}" \
        : "=r"(_d) : "r"(_m), "r"(_p) : "memory"); \
    if (!_d) { \
        asm volatile("{\n\t.reg .pred Q;\n\tWL_%=:\n\tmbarrier.try_wait.parity.acquire.cta.shared::cta.b64 Q, [%0], %1, 0x989680;\n\t@Q bra.uni WD_%=;\n\tbra.uni WL_%=;\n\tWD_%=:\n\t}" \
            :: "r"(_m), "r"(_p) : "memory"); \
    } } while (0)

__device__ __forceinline__ void ldsm4(uint32_t (&r)[4], uint32_t addr) {
    asm volatile("ldmatrix.sync.aligned.m8n8.x4.shared.b16 {%0,%1,%2,%3}, [%4];"
        : "=r"(r[0]), "=r"(r[1]), "=r"(r[2]), "=r"(r[3]) : "r"(addr));
}
__device__ __forceinline__ void mmah(float (&d)[4], const uint32_t (&a)[4], const uint32_t (&b)[2]) {
    asm volatile("mma.sync.aligned.m16n8k16.row.col.f32.f16.f16.f32 "
        "{%0,%1,%2,%3}, {%4,%5,%6,%7}, {%8,%9}, {%0,%1,%2,%3};"
        : "+f"(d[0]), "+f"(d[1]), "+f"(d[2]), "+f"(d[3])
        : "r"(a[0]), "r"(a[1]), "r"(a[2]), "r"(a[3]), "r"(b[0]), "r"(b[1]));
}

__device__ __forceinline__ void pack8h(const float* r, uint4& o)
{
    __half2 p0 = __floats2half2_rn(r[0], r[1]);
    __half2 p1 = __floats2half2_rn(r[2], r[3]);
    __half2 p2 = __floats2half2_rn(r[4], r[5]);
    __half2 p3 = __floats2half2_rn(r[6], r[7]);
    o = make_uint4(*reinterpret_cast<uint32_t*>(&p0), *reinterpret_cast<uint32_t*>(&p1),
                   *reinterpret_cast<uint32_t*>(&p2), *reinterpret_cast<uint32_t*>(&p3));
}

// PADTILE index for (row, col) with aktpr K-chunks per row-tile
__device__ __forceinline__ size_t pt_idx(int ktpr, int row, int col)
{
    return ((size_t)(row >> 6) * ktpr + (col >> 5)) * 2560 + (row & 63) * 40 + (col & 31);
}
__device__ __forceinline__ void store_a4(__half* p, size_t idx, float4 v)
{
    *reinterpret_cast<__half2*>(p + idx)     = __floats2half2_rn(v.x, v.y);
    *reinterpret_cast<__half2*>(p + idx + 2) = __floats2half2_rn(v.z, v.w);
}

// ---- GEMM core: 64x64 block, 4 warps of 32x32, BK=32, double-buffered bulk-copy ----
enum { AT_TILED = 0, AT_TILED2 = 1, AT_STATE = 2, AT_ELUSUM = 3 };
enum { EPI_F32 = 0, EPI_TILEA = 1, EPI_HEADAT = 2, EPI_HEADST = 3 };

template<int ALOAD>
__device__ __forceinline__ void load_a8(
    int gm, int k, float* r,
    const float* A2f, int lda2, int K1,
    const float* st_mq, const float* st_sq, const float* st_eps,
    const float* st_nt, const float* st_prev)
{
    if (ALOAD == AT_ELUSUM) {
        const int base = gm * DHID + k;
#pragma unroll
        for (int i = 0; i < 8; i++)
            r[i] = eluf(g_hq1[base + i] + g_hq2[base + i]);
        return;
    }
    if (ALOAD == AT_STATE) {
        if (k < K1) {
            const float nt = st_nt[gm];
            const int base = gm * DST + k;
            if (st_mq) {
#pragma unroll
                for (int i = 0; i < 8; i++) {
                    float s = splusf(st_sq[base + i]) + 0.1f;
                    r[i] = (st_mq[base + i] + s * st_eps[base + i]) * nt;
                }
            } else {
#pragma unroll
                for (int i = 0; i < 8; i++) r[i] = st_prev[base + i] * nt;
            }
        } else {
            const float* p = A2f + (size_t)gm * lda2 + (k - K1);
            float4 v0 = *reinterpret_cast<const float4*>(p);
            float4 v1 = *reinterpret_cast<const float4*>(p + 4);
            r[0] = v0.x; r[1] = v0.y; r[2] = v0.z; r[3] = v0.w;
            r[4] = v1.x; r[5] = v1.y; r[6] = v1.z; r[7] = v1.w;
        }
    }
}

template<int EPI>
__device__ __forceinline__ void epi2(
    int kc, int r, int c, float v0, float v1,
    const float* bias, float* out, int ldout,
    float* mean_out, float* std_out, __half* oap)
{
    if (EPI == EPI_F32) {
        if (bias) { v0 += __ldg(bias + c); v1 += __ldg(bias + c + 1); }
        *reinterpret_cast<float2*>(out + (size_t)r * ldout + c) = make_float2(v0, v1);
    } else if (EPI == EPI_TILEA) {
        v0 = eluf(v0 + __ldg(bias + c));
        v1 = eluf(v1 + __ldg(bias + c + 1));
        *reinterpret_cast<__half2*>(oap + pt_idx(32, r, c)) = __floats2half2_rn(v0, v1);
    } else if (EPI == EPI_HEADAT) {
        float b0 = (kc == 0) ? __ldg(bias + c)     : 0.f;
        float b1 = (kc == 0) ? __ldg(bias + c + 1) : 0.f;
        if (c < DST) {
            atomicAdd(mean_out + (size_t)r * DST + c,     v0 + b0);
            atomicAdd(mean_out + (size_t)r * DST + c + 1, v1 + b1);
        } else {
            atomicAdd(std_out + (size_t)r * DST + (c - DST),     v0 + b0);
            atomicAdd(std_out + (size_t)r * DST + (c - DST) + 1, v1 + b1);
        }
    } else { // EPI_HEADST
        float w0 = v0 + __ldg(bias + c), w1 = v1 + __ldg(bias + c + 1);
        if (c < DST) {
            mean_out[(size_t)r * DST + c]     = w0;
            mean_out[(size_t)r * DST + c + 1] = w1;
        } else {
            std_out[(size_t)r * DST + (c - DST)]     = splusf(w0) + 0.1f;
            std_out[(size_t)r * DST + (c - DST) + 1] = splusf(w1) + 0.1f;
        }
    }
}

// smem: 2 buffers x (A 5120 | Bh 5120 | Bl 5120) = 30720 B, then 2 mbarriers
#define GEMM_SMEM 30752
template<int KC, int ALOAD, int EPI>
__device__ __forceinline__ void gemm64(
    int mb, int nb, int kc,
    const __half* ap1, const __half* ap2, int ks1,
    const float* A2f, int lda2, int K1,
    const float* st_mq, const float* st_sq, const float* st_eps,
    const float* st_nt, const float* st_prev,
    const __half* bh, const __half* bl, int kspmb,
    const float* bias, float* out, int ldout,
    float* mean_out, float* std_out, __half* oap)
{
    constexpr int NST = KC / 32;
    constexpr bool TILEDA = (ALOAD == AT_TILED || ALOAD == AT_TILED2);
    constexpr uint32_t TXB = TILEDA ? 15360u : 10240u;
    extern __shared__ __align__(16) char dsm[];

    const int tid  = threadIdx.x;
    const int lane = tid & 31;
    const int wid  = tid >> 5;
    const int wm = (wid >> 1) * 32;
    const int wn = (wid & 1) * 32;
    const int ksbeg = kc * NST;

    const uint32_t sb = (uint32_t)__cvta_generic_to_shared(dsm);
    const uint32_t PLN = 5120u;
    const uint32_t STG = 15360u;
    const uint32_t mb0 = sb + 30720u;

    if (tid == 0) { MBAR_INIT(mb0, 1); MBAR_INIT(mb0 + 8, 1); }
    __syncthreads();

    // issue bulk copies for stage s into buffer (s&1)
    auto issue = [&](int s) {
        const int st = s & 1;
        const int ks = ksbeg + s;
        const uint32_t buf = sb + st * STG, mbar = mb0 + st * 8;
        MBAR_EXPECT(mbar, TXB);
        if (TILEDA) {
            const __half* pa;
            if (ALOAD == AT_TILED2 && ks >= ks1) pa = ap2 + (size_t)(mb * 32 + (ks - ks1)) * 2560;
            else                                  pa = ap1 + (size_t)(mb * 32 + ks) * 2560;
            bulkcp(buf, pa, 5120u, mbar);
        }
        bulkcp(buf + PLN,     bh + (size_t)(nb * kspmb + ks) * 2560, 5120u, mbar);
        bulkcp(buf + 2 * PLN, bl + (size_t)(nb * kspmb + ks) * 2560, 5120u, mbar);
    };
    // computed-A fill for stage s (all threads)
    auto fillA = [&](int s) {
        if (TILEDA) return;
        const int st = s & 1;
        const int lrow = tid >> 1, lkb = (tid & 1) << 4;
        const int gm = mb * 64 + lrow;
        __half* as = reinterpret_cast<__half*>(dsm + st * STG);
#pragma unroll
        for (int j = 0; j < 2; j++) {
            float r8[8];
            load_a8<ALOAD>(gm, (ksbeg + s) * 32 + lkb + j * 8, r8,
                           A2f, lda2, K1, st_mq, st_sq, st_eps, st_nt, st_prev);
            uint4 pk; pack8h(r8, pk);
            *reinterpret_cast<uint4*>(&as[lrow * 40 + lkb + j * 8]) = pk;
        }
    };

    if (tid == 0) { issue(0); if (NST > 1) issue(1); }
    fillA(0);
    if (NST > 1) fillA(1);
    __syncthreads();                 // A writes + mbar init visible

    float acc[2][4][4];
#pragma unroll
    for (int i = 0; i < 2; i++)
#pragma unroll
        for (int j = 0; j < 4; j++)
#pragma unroll
            for (int q = 0; q < 4; q++) acc[i][j][q] = 0.f;

    const int amat = lane >> 3, arin = lane & 7;
    const int arowb = wm + ((amat & 1) << 3) + arin;
    const int acol  = (amat >> 1) << 3;
    const int brow = wn + ((lane >> 4) << 3) + (lane & 7);
    const int bcol = ((lane >> 3) & 1) << 3;

    int ph[2] = {0, 0};
#pragma unroll 1
    for (int s = 0; s < NST; s++) {
        const int cur = s & 1;
        MBAR_WAIT(mb0 + cur * 8, ph[cur]); ph[cur] ^= 1;

        const uint32_t aOff = sb + cur * STG;
        const uint32_t bOff = aOff + PLN;
#pragma unroll
        for (int kk = 0; kk < 32; kk += 16) {
            uint32_t Am[2][4], Bh[4][2], Bl[4][2];
#pragma unroll
            for (int mf = 0; mf < 2; mf++) {
                uint32_t off = (uint32_t)(((arowb + mf*16) * 40 + kk + acol) * 2);
                ldsm4(Am[mf], aOff + off);
            }
#pragma unroll
            for (int nfp = 0; nfp < 2; nfp++) {
                uint32_t off = (uint32_t)(((brow + nfp*16) * 40 + kk + bcol) * 2);
                uint32_t rh[4], rl[4];
                ldsm4(rh, bOff + off);
                ldsm4(rl, bOff + PLN + off);
                Bh[nfp*2][0]   = rh[0]; Bh[nfp*2][1]   = rh[1];
                Bh[nfp*2+1][0] = rh[2]; Bh[nfp*2+1][1] = rh[3];
                Bl[nfp*2][0]   = rl[0]; Bl[nfp*2][1]   = rl[1];
                Bl[nfp*2+1][0] = rl[2]; Bl[nfp*2+1][1] = rl[3];
            }
#pragma unroll
            for (int mf = 0; mf < 2; mf++)
#pragma unroll
                for (int nf = 0; nf < 4; nf++) {
                    mmah(acc[mf][nf], Am[mf], Bh[nf]);
                    mmah(acc[mf][nf], Am[mf], Bl[nf]);
                }
        }
        __syncthreads();             // all warps done reading buffer cur
        if (s + 2 < NST) {
            fillA(s + 2);
            if (tid == 0) issue(s + 2);
        }
    }

    const int gr = lane >> 2, gc = (lane & 3) << 1;
#pragma unroll
    for (int mf = 0; mf < 2; mf++)
#pragma unroll
        for (int nf = 0; nf < 4; nf++) {
            int r = mb * 64 + wm + mf * 16 + gr;
            int c = nb * 64 + wn + nf * 8 + gc;
            epi2<EPI>(kc, r,     c, acc[mf][nf][0], acc[mf][nf][1], bias, out, ldout, mean_out, std_out, oap);
            epi2<EPI>(kc, r + 8, c, acc[mf][nf][2], acc[mf][nf][3], bias, out, ldout, mean_out, std_out, oap);
        }
}

// ---- phase kernels ----
__global__ void __launch_bounds__(128) k_x(
    const float* act, const float* nt, const float* mq, const float* sq,
    const float* eps, const float* prev, const float* b_sa)
{
    int mb = blockIdx.x >> 4, nb = blockIdx.x & 15;
    gemm64<160, AT_STATE, EPI_TILEA>(mb, nb, 0,
        nullptr, nullptr, 0, act, DACT, DST, mq, sq, eps, nt, prev,
        tWsa_h, tWsa_l, 5,
        b_sa, nullptr, 0, nullptr, nullptr, Ax_p);
}

__global__ void __launch_bounds__(128) k_gigh(
    const float* b_ih, const float* b_hh, const __half* belp)
{
    int tile = blockIdx.x;
    if (tile < 192) {
        int mb = tile / 48, nb = tile % 48;
        gemm64<1024, AT_TILED, EPI_F32>(mb, nb, 0,
            Ax_p, nullptr, 0, nullptr, 0, 0, nullptr, nullptr, nullptr, nullptr, nullptr,
            tWih_h, tWih_l, 32,
            b_ih, g_gi, GRU3, nullptr, nullptr, nullptr);
    } else {
        int r = tile - 192;
        int mb = r / 48, nb = r % 48;
        gemm64<1024, AT_TILED, EPI_F32>(mb, nb, 0,
            belp, nullptr, 0, nullptr, 0, 0, nullptr, nullptr, nullptr, nullptr, nullptr,
            tWhh_h, tWhh_l, 32,
            b_hh, g_gh, GRU3, nullptr, nullptr, nullptr);
    }
}

__global__ void __launch_bounds__(128) k_gru(float* belout, __half* abp)
{
    int i4 = (blockIdx.x * 128 + threadIdx.x) * 4;
    int m = i4 >> 10, j = i4 & 1023;
    const size_t base = (size_t)m * GRU3 + j;
    float4 gir = *reinterpret_cast<const float4*>(g_gi + base);
    float4 giz = *reinterpret_cast<const float4*>(g_gi + base + 1024);
    float4 gin = *reinterpret_cast<const float4*>(g_gi + base + 2048);
    float4 ghr = *reinterpret_cast<const float4*>(g_gh + base);
    float4 ghz = *reinterpret_cast<const float4*>(g_gh + base + 1024);
    float4 ghn = *reinterpret_cast<const float4*>(g_gh + base + 2048);
    float4 b   = *reinterpret_cast<const float4*>(g_belief + i4);
    float4 h;
    { float r = sigf(gir.x + ghr.x), z = sigf(giz.x + ghz.x);
      h.x = (1.f - z) * tanhf(gin.x + r * ghn.x) + z * b.x; }
    { float r = sigf(gir.y + ghr.y), z = sigf(giz.y + ghz.y);
      h.y = (1.f - z) * tanhf(gin.y + r * ghn.y) + z * b.y; }
    { float r = sigf(gir.z + ghr.z), z = sigf(giz.z + ghz.z);
      h.z = (1.f - z) * tanhf(gin.z + r * ghn.z) + z * b.z; }
    { float r = sigf(gir.w + ghr.w), z = sigf(giz.w + ghz.w);
      h.w = (1.f - z) * tanhf(gin.w + r * ghn.w) + z * b.w; }
    *reinterpret_cast<float4*>(g_belief + i4) = h;
    *reinterpret_cast<float4*>(belout + i4)  = h;
    store_a4(abp, pt_idx(32, m, j), h);
}

__global__ void __launch_bounds__(128) k_hq(
    const __half* belp, const __half* obsp, const float* b_poh)
{
    int tile = blockIdx.x;
    int kc = tile >> 6;
    int r = tile & 63;
    int mb = r >> 4, nb = r & 15;
    gemm64<1024, AT_TILED2, EPI_F32>(mb, nb, kc,
        belp, obsp, 32, nullptr, 0, 0, nullptr, nullptr, nullptr, nullptr, nullptr,
        tWpoh_h, tWpoh_l, 64,
        kc == 0 ? b_poh : nullptr,
        kc == 0 ? g_hq1 : g_hq2, DHID,
        nullptr, nullptr, nullptr);
}

__global__ void __launch_bounds__(128) k_head(
    const float* b_pos, float* mqo, float* sqo)
{
    int tile = blockIdx.x;
    int kc = tile >> 4;
    int r = tile & 15;
    int mb = r >> 2, nb = r & 3;
    gemm64<128, AT_ELUSUM, EPI_HEADAT>(mb, nb, kc,
        nullptr, nullptr, 0, nullptr, 0, 0, nullptr, nullptr, nullptr, nullptr, nullptr,
        tWpos_h, tWpos_l, 32,
        b_pos, nullptr, 0, mqo, sqo, nullptr);
}

__global__ void __launch_bounds__(128) k_prh(const float* b_prh)
{
    int mb = blockIdx.x >> 4, nb = blockIdx.x & 15;
    gemm64<1024, AT_TILED, EPI_TILEA>(mb, nb, 0,
        Abel_p, nullptr, 0, nullptr, 0, 0, nullptr, nullptr, nullptr, nullptr, nullptr,
        tWprh_h, tWprh_l, 32,
        b_prh, nullptr, 0, nullptr, nullptr, Ahp_p);
}

__global__ void __launch_bounds__(128) k_prs(const float* b_prs, float* mp, float* sp)
{
    int mb = blockIdx.x >> 2, nb = blockIdx.x & 3;
    gemm64<1024, AT_TILED, EPI_HEADST>(mb, nb, 0,
        Ahp_p, nullptr, 0, nullptr, 0, 0, nullptr, nullptr, nullptr, nullptr, nullptr,
        tWprs_h, tWprs_l, 32,
        b_prs, nullptr, 0, mp, sp, nullptr);
}

// ---- elementwise ----
__global__ void conv_w(const float* __restrict__ W, __half* th, __half* tl, int N, int K)
{
    int e2 = (blockIdx.x * 256 + threadIdx.x) * 2;
    if (e2 >= N * K) return;
    int n = e2 / K, k = e2 % K;
    float v0 = __ldg(W + e2), v1 = __ldg(W + e2 + 1);
    __half h0 = __float2half_rn(v0), h1 = __float2half_rn(v1);
    __half l0 = __float2half_rn(v0 - __half2float(h0));
    __half l1 = __float2half_rn(v1 - __half2float(h1));
    size_t idx = ((size_t)(n >> 6) * (K >> 5) + (k >> 5)) * 2560 + (n & 63) * 40 + (k & 31);
    *reinterpret_cast<__half2*>(th + idx) = __halves2half2(h0, h1);
    *reinterpret_cast<__half2*>(tl + idx) = __halves2half2(l0, l1);
}

__global__ void conv_a(const float* __restrict__ X, __half* tp, int N, int K)
{
    int e4 = (blockIdx.x * 256 + threadIdx.x) * 4;
    if (e4 >= N * K) return;
    int n = e4 / K, k = e4 % K;
    float4 v = __ldg(reinterpret_cast<const float4*>(X + e4));
    size_t idx = ((size_t)(n >> 6) * (K >> 5) + (k >> 5)) * 2560 + (n & 63) * 40 + (k & 31);
    store_a4(tp, idx, v);
}

__global__ void k_init(const float* __restrict__ prevb, float* __restrict__ out)
{
    int i4 = (blockIdx.x * 128 + threadIdx.x) * 4;
    if (i4 < 2 * TT * BB * DST)
        *reinterpret_cast<float4*>(out + OFF_MQ + i4) = make_float4(0.f, 0.f, 0.f, 0.f);
    if (i4 < BB * DBEL) {
        float4 v = __ldg(reinterpret_cast<const float4*>(prevb + i4));
        *reinterpret_cast<float4*>(g_belief + i4) = v;
        int m = i4 >> 10, k = i4 & 1023;
        store_a4(AbelI_p, pt_idx(32, m, k), v);
    }
}

__global__ void k_sample(float* __restrict__ out,
                         const float* __restrict__ ep, const float* __restrict__ eq)
{
    int i = (blockIdx.x * 128 + threadIdx.x) * 4;
    if (i >= TT * BB * DST) return;
    float4 mp = *reinterpret_cast<const float4*>(out + OFF_MP + i);
    float4 sp = *reinterpret_cast<const float4*>(out + OFF_SP + i);
    float4 e1 = __ldg(reinterpret_cast<const float4*>(ep + i));
    float4 mq = *reinterpret_cast<const float4*>(out + OFF_MQ + i);
    float4 sq = *reinterpret_cast<const float4*>(out + OFF_SQ + i);
    float4 e2 = __ldg(reinterpret_cast<const float4*>(eq + i));
    float4 prs, pos, sqo;
    prs.x = mp.x + sp.x * e1.x; prs.y = mp.y + sp.y * e1.y;
    prs.z = mp.z + sp.z * e1.z; prs.w = mp.w + sp.w * e1.w;
    sqo.x = splusf(sq.x) + 0.1f; sqo.y = splusf(sq.y) + 0.1f;
    sqo.z = splusf(sq.z) + 0.1f; sqo.w = splusf(sq.w) + 0.1f;
    pos.x = mq.x + sqo.x * e2.x; pos.y = mq.y + sqo.y * e2.y;
    pos.z = mq.z + sqo.z * e2.z; pos.w = mq.w + sqo.w * e2.w;
    *reinterpret_cast<float4*>(out + OFF_PRS + i) = prs;
    *reinterpret_cast<float4*>(out + OFF_SQ  + i) = sqo;
    *reinterpret_cast<float4*>(out + OFF_POS + i) = pos;
}

// ---- host ----
extern "C" void kernel_launch(void* const* d_in, const int* in_sizes, int n_in,
                              void* d_out, int out_size)
{
    (void)in_sizes; (void)n_in; (void)out_size;
    const float* prev_state   = (const float*)d_in[0];
    const float* actions      = (const float*)d_in[1];
    const float* prev_belief  = (const float*)d_in[2];
    const float* observations = (const float*)d_in[3];
    const float* nonterminals = (const float*)d_in[4];
    const float* prior_noise  = (const float*)d_in[5];
    const float* post_noise   = (const float*)d_in[6];
    const float* W_sa  = (const float*)d_in[7];
    const float* b_sa  = (const float*)d_in[8];
    const float* w_ih  = (const float*)d_in[9];
    const float* b_ih  = (const float*)d_in[10];
    const float* w_hh  = (const float*)d_in[11];
    const float* b_hh  = (const float*)d_in[12];
    const float* W_prh = (const float*)d_in[13];
    const float* b_prh = (const float*)d_in[14];
    const float* W_prs = (const float*)d_in[15];
    const float* b_prs = (const float*)d_in[16];
    const float* W_poh = (const float*)d_in[17];
    const float* b_poh = (const float*)d_in[18];
    const float* W_pos = (const float*)d_in[19];
    const float* b_pos = (const float*)d_in[20];
    float* out = (float*)d_out;

    __half *p_wsa_h, *p_wsa_l, *p_wih_h, *p_wih_l, *p_whh_h, *p_whh_l,
           *p_wpoh_h, *p_wpoh_l, *p_wpos_h, *p_wpos_l, *p_wprh_h, *p_wprh_l,
           *p_wprs_h, *p_wprs_l, *p_abel, *p_abeli, *p_aobs;
    cudaGetSymbolAddress((void**)&p_wsa_h,  tWsa_h);  cudaGetSymbolAddress((void**)&p_wsa_l,  tWsa_l);
    cudaGetSymbolAddress((void**)&p_wih_h,  tWih_h);  cudaGetSymbolAddress((void**)&p_wih_l,  tWih_l);
    cudaGetSymbolAddress((void**)&p_whh_h,  tWhh_h);  cudaGetSymbolAddress((void**)&p_whh_l,  tWhh_l);
    cudaGetSymbolAddress((void**)&p_wpoh_h, tWpoh_h); cudaGetSymbolAddress((void**)&p_wpoh_l, tWpoh_l);
    cudaGetSymbolAddress((void**)&p_wpos_h, tWpos_h); cudaGetSymbolAddress((void**)&p_wpos_l, tWpos_l);
    cudaGetSymbolAddress((void**)&p_wprh_h, tWprh_h); cudaGetSymbolAddress((void**)&p_wprh_l, tWprh_l);
    cudaGetSymbolAddress((void**)&p_wprs_h, tWprs_h); cudaGetSymbolAddress((void**)&p_wprs_l, tWprs_l);
    cudaGetSymbolAddress((void**)&p_abel,  Abel_p);
    cudaGetSymbolAddress((void**)&p_abeli, AbelI_p);
    cudaGetSymbolAddress((void**)&p_aobs,  Aobs_p);

    auto cw = [](const float* W, __half* h, __half* l, int N, int K) {
        conv_w<<<(N * K / 2 + 255) / 256, 256>>>(W, h, l, N, K);
    };
    cw(W_sa,  p_wsa_h,  p_wsa_l,  DBEL, 160);
    cw(w_ih,  p_wih_h,  p_wih_l,  GRU3, DBEL);
    cw(w_hh,  p_whh_h,  p_whh_l,  GRU3, DBEL);
    cw(W_poh, p_wpoh_h, p_wpoh_l, DHID, 2048);
    cw(W_pos, p_wpos_h, p_wpos_l, 2*DST, DHID);
    cw(W_prh, p_wprh_h, p_wprh_l, DHID, DBEL);
    cw(W_prs, p_wprs_h, p_wprs_l, 2*DST, DHID);
    conv_a<<<(TT * BB * DEMB / 4 + 255) / 256, 256>>>(observations, p_aobs, TT * BB, DEMB);

    k_init<<<(2 * TT * BB * DST / 4 + 127) / 128, 128>>>(prev_belief, out);

    const size_t TSTEP = PT(BB, DBEL);
    for (int t = 0; t < TT; t++) {
        const float* act = actions      + (size_t)t * BB * DACT;
        const float* nt  = nonterminals + (size_t)t * BB;
        const float* mq  = (t == 0) ? nullptr : out + OFF_MQ + (size_t)(t-1) * BB * DST;
        const float* sq  = (t == 0) ? nullptr : out + OFF_SQ + (size_t)(t-1) * BB * DST;
        const float* ep  = (t == 0) ? nullptr : post_noise + (size_t)(t-1) * BB * DST;
        const __half* bpp = (t == 0) ? p_abeli : p_abel + (size_t)(t-1) * TSTEP;

        k_x   <<<64, 128, GEMM_SMEM>>>(act, nt, mq, sq, ep, prev_state, b_sa);
        k_gigh<<<384, 128, GEMM_SMEM>>>(b_ih, b_hh, bpp);
        k_gru <<<512, 128>>>(out + OFF_BEL + (size_t)t * BB * DBEL, p_abel + (size_t)t * TSTEP);
        k_hq  <<<128, 128, GEMM_SMEM>>>(p_abel + (size_t)t * TSTEP,
                                        p_aobs + (size_t)t * TSTEP, b_poh);
        k_head<<<128, 128, GEMM_SMEM>>>(b_pos,
                                        out + OFF_MQ + (size_t)t * BB * DST,
                                        out + OFF_SQ + (size_t)t * BB * DST);
    }

    k_prh<<<3200, 128, GEMM_SMEM>>>(b_prh);
    k_prs<<<800, 128, GEMM_SMEM>>>(b_prs, out + OFF_MP, out + OFF_SP);
    k_sample<<<(TT * BB * DST / 4 + 127) / 128, 128>>>(out, prior_noise, post_noise);
}

// round 16
// speedup vs baseline: 2.2325x; 1.1227x over previous
#include <cuda_runtime.h>
#include <cuda_fp16.h>
#include <math.h>
#include <stdint.h>

#define TT 50
#define BB 256
#define DBEL 1024
#define DST 128
#define DACT 32
#define DHID 1024
#define DEMB 1024
#define GRU3 (3*DBEL)

static constexpr size_t OFF_BEL = 0;
static constexpr size_t OFF_PRS = (size_t)TT*BB*DBEL;
static constexpr size_t OFF_MP  = OFF_PRS + (size_t)TT*BB*DST;
static constexpr size_t OFF_SP  = OFF_MP  + (size_t)TT*BB*DST;
static constexpr size_t OFF_POS = OFF_SP  + (size_t)TT*BB*DST;
static constexpr size_t OFF_MQ  = OFF_POS + (size_t)TT*BB*DST;
static constexpr size_t OFF_SQ  = OFF_MQ  + (size_t)TT*BB*DST;

// ---- PADTILE format: 64-row x 32-col chunk stored as 64 x 40 halfs (5120 B, padded
// row image identical to the smem tile). chunk = (row/64)*(K/32) + (col/32);
// half-offset = chunk*2560 + (row%64)*40 + (col%32). Pads never read.
#define PT(N, K) ((size_t)((N)/64) * ((K)/32) * 2560)

__device__ __align__(128) __half tWsa_h[PT(DBEL,160)],    tWsa_l[PT(DBEL,160)];
__device__ __align__(128) __half tWih_h[PT(GRU3,DBEL)],   tWih_l[PT(GRU3,DBEL)];
__device__ __align__(128) __half tWhh_h[PT(GRU3,DBEL)],   tWhh_l[PT(GRU3,DBEL)];
__device__ __align__(128) __half tWpoh_h[PT(DHID,2048)],  tWpoh_l[PT(DHID,2048)];
__device__ __align__(128) __half tWpos_h[PT(2*DST,DHID)], tWpos_l[PT(2*DST,DHID)];
__device__ __align__(128) __half tWprh_h[PT(DHID,DBEL)],  tWprh_l[PT(DHID,DBEL)];
__device__ __align__(128) __half tWprs_h[PT(2*DST,DHID)], tWprs_l[PT(2*DST,DHID)];

__device__ __align__(128) __half Ax_p[PT(BB,DBEL)];
__device__ __align__(128) __half AbelI_p[PT(BB,DBEL)];
__device__ __align__(128) __half Abel_p[(size_t)TT*PT(BB,DBEL)];
__device__ __align__(128) __half Aobs_p[(size_t)TT*PT(BB,DEMB)];
__device__ __align__(128) __half Ahp_p[(size_t)TT*PT(BB,DHID)];

__device__ float g_gi[BB*GRU3];
__device__ float g_gh[BB*GRU3];
__device__ float g_hq1[BB*DHID];
__device__ float g_hq2[BB*DHID];
__device__ float g_belief[BB*DBEL];

__device__ __forceinline__ float eluf(float x)   { return x > 0.f ? x : expm1f(x); }
__device__ __forceinline__ float splusf(float x) { return fmaxf(x, 0.f) + log1pf(expf(-fabsf(x))); }
__device__ __forceinline__ float sigf(float x)   { return 1.f / (1.f + expf(-x)); }

// ---- PTX ----
__device__ __forceinline__ void bulkcp(uint32_t dst, const void* src, uint32_t bytes, uint32_t mbar) {
    asm volatile("cp.async.bulk.shared::cluster.global.mbarrier::complete_tx::bytes [%0], [%1], %2, [%3];"
        :: "r"(dst), "l"(src), "r"(bytes), "r"(mbar) : "memory");
}
#define MBAR_INIT(a, c) \
    asm volatile("mbarrier.init.shared.b64 [%0], %1;" :: "r"((uint32_t)(a)), "r"((uint32_t)(c)) : "memory")
#define MBAR_EXPECT(a, b) \
    asm volatile("mbarrier.arrive.expect_tx.shared.b64 _, [%0], %1;" :: "r"((uint32_t)(a)), "r"((uint32_t)(b)) : "memory")
#define MBAR_WAIT(a, p) do { \
    uint32_t _m = (uint32_t)(a); uint32_t _p = (uint32_t)(p); uint32_t _d; \
    asm volatile("{\n\t.reg .pred q;\n\tmbarrier.try_wait.parity.acquire.cta.shared::cta.b64 q, [%1], %2;\n\tselp.b32 %0, 1, 0, q;\n\t}" \
        : "=r"(_d) : "r"(_m), "r"(_p) : "memory"); \
    if (!_d) { \
        asm volatile("{\n\t.reg .pred Q;\n\tWL_%=:\n\tmbarrier.try_wait.parity.acquire.cta.shared::cta.b64 Q, [%0], %1, 0x989680;\n\t@Q bra.uni WD_%=;\n\tbra.uni WL_%=;\n\tWD_%=:\n\t}" \
            :: "r"(_m), "r"(_p) : "memory"); \
    } } while (0)

__device__ __forceinline__ void ldsm4(uint32_t (&r)[4], uint32_t addr) {
    asm volatile("ldmatrix.sync.aligned.m8n8.x4.shared.b16 {%0,%1,%2,%3}, [%4];"
        : "=r"(r[0]), "=r"(r[1]), "=r"(r[2]), "=r"(r[3]) : "r"(addr));
}
__device__ __forceinline__ void mmah(float (&d)[4], const uint32_t (&a)[4], const uint32_t (&b)[2]) {
    asm volatile("mma.sync.aligned.m16n8k16.row.col.f32.f16.f16.f32 "
        "{%0,%1,%2,%3}, {%4,%5,%6,%7}, {%8,%9}, {%0,%1,%2,%3};"
        : "+f"(d[0]), "+f"(d[1]), "+f"(d[2]), "+f"(d[3])
        : "r"(a[0]), "r"(a[1]), "r"(a[2]), "r"(a[3]), "r"(b[0]), "r"(b[1]));
}

__device__ __forceinline__ void pack8h(const float* r, uint4& o)
{
    __half2 p0 = __floats2half2_rn(r[0], r[1]);
    __half2 p1 = __floats2half2_rn(r[2], r[3]);
    __half2 p2 = __floats2half2_rn(r[4], r[5]);
    __half2 p3 = __floats2half2_rn(r[6], r[7]);
    o = make_uint4(*reinterpret_cast<uint32_t*>(&p0), *reinterpret_cast<uint32_t*>(&p1),
                   *reinterpret_cast<uint32_t*>(&p2), *reinterpret_cast<uint32_t*>(&p3));
}

__device__ __forceinline__ size_t pt_idx(int ktpr, int row, int col)
{
    return ((size_t)(row >> 6) * ktpr + (col >> 5)) * 2560 + (row & 63) * 40 + (col & 31);
}
__device__ __forceinline__ void store_a4(__half* p, size_t idx, float4 v)
{
    *reinterpret_cast<__half2*>(p + idx)     = __floats2half2_rn(v.x, v.y);
    *reinterpret_cast<__half2*>(p + idx + 2) = __floats2half2_rn(v.z, v.w);
}

// ---- GEMM core: 64x64 block, 4 warps of 32x32, BK=64 stages (2 chunks/stage) ----
enum { AT_TILED = 0, AT_TILED2 = 1, AT_STATE = 2, AT_ELUSUM = 3 };
enum { EPI_F32 = 0, EPI_TILEA = 1, EPI_HEADAT = 2, EPI_HEADST = 3 };

template<int ALOAD>
__device__ __forceinline__ void load_a8(
    int gm, int k, float* r,
    const float* A2f, int lda2, int K1,
    const float* st_mq, const float* st_sq, const float* st_eps,
    const float* st_nt, const float* st_prev)
{
    if (ALOAD == AT_ELUSUM) {
        const int base = gm * DHID + k;
#pragma unroll
        for (int i = 0; i < 8; i++)
            r[i] = eluf(g_hq1[base + i] + g_hq2[base + i]);
        return;
    }
    if (ALOAD == AT_STATE) {
        if (k < K1) {
            const float nt = st_nt[gm];
            const int base = gm * DST + k;
            if (st_mq) {
#pragma unroll
                for (int i = 0; i < 8; i++) {
                    float s = splusf(st_sq[base + i]) + 0.1f;
                    r[i] = (st_mq[base + i] + s * st_eps[base + i]) * nt;
                }
            } else {
#pragma unroll
                for (int i = 0; i < 8; i++) r[i] = st_prev[base + i] * nt;
            }
        } else {
            const float* p = A2f + (size_t)gm * lda2 + (k - K1);
            float4 v0 = *reinterpret_cast<const float4*>(p);
            float4 v1 = *reinterpret_cast<const float4*>(p + 4);
            r[0] = v0.x; r[1] = v0.y; r[2] = v0.z; r[3] = v0.w;
            r[4] = v1.x; r[5] = v1.y; r[6] = v1.z; r[7] = v1.w;
        }
    }
}

template<int EPI>
__device__ __forceinline__ void epi2(
    int kc, int r, int c, float v0, float v1,
    const float* bias, float* out, int ldout,
    float* mean_out, float* std_out, __half* oap)
{
    if (EPI == EPI_F32) {
        if (bias) { v0 += __ldg(bias + c); v1 += __ldg(bias + c + 1); }
        *reinterpret_cast<float2*>(out + (size_t)r * ldout + c) = make_float2(v0, v1);
    } else if (EPI == EPI_TILEA) {
        v0 = eluf(v0 + __ldg(bias + c));
        v1 = eluf(v1 + __ldg(bias + c + 1));
        *reinterpret_cast<__half2*>(oap + pt_idx(32, r, c)) = __floats2half2_rn(v0, v1);
    } else if (EPI == EPI_HEADAT) {
        float b0 = (kc == 0) ? __ldg(bias + c)     : 0.f;
        float b1 = (kc == 0) ? __ldg(bias + c + 1) : 0.f;
        if (c < DST) {
            atomicAdd(mean_out + (size_t)r * DST + c,     v0 + b0);
            atomicAdd(mean_out + (size_t)r * DST + c + 1, v1 + b1);
        } else {
            atomicAdd(std_out + (size_t)r * DST + (c - DST),     v0 + b0);
            atomicAdd(std_out + (size_t)r * DST + (c - DST) + 1, v1 + b1);
        }
    } else { // EPI_HEADST
        float w0 = v0 + __ldg(bias + c), w1 = v1 + __ldg(bias + c + 1);
        if (c < DST) {
            mean_out[(size_t)r * DST + c]     = w0;
            mean_out[(size_t)r * DST + c + 1] = w1;
        } else {
            std_out[(size_t)r * DST + (c - DST)]     = splusf(w0) + 0.1f;
            std_out[(size_t)r * DST + (c - DST) + 1] = splusf(w1) + 0.1f;
        }
    }
}

// smem: 2 stage buffers x (A0 A1 Bh0 Bh1 Bl0 Bl1) x 5120 = 61440 B + 2 mbarriers
#define GEMM_SMEM 61472
template<int KC, int ALOAD, int EPI>
__device__ __forceinline__ void gemm64(
    int mb, int nb, int kc,
    const __half* ap1, const __half* ap2, int ks1,
    const float* A2f, int lda2, int K1,
    const float* st_mq, const float* st_sq, const float* st_eps,
    const float* st_nt, const float* st_prev,
    const __half* bh, const __half* bl, int kspmb,
    const float* bias, float* out, int ldout,
    float* mean_out, float* std_out, __half* oap)
{
    constexpr int NCH  = KC / 32;           // 32-K chunks
    constexpr int NSTG = (NCH + 1) / 2;     // 64-K stages
    constexpr bool TILEDA = (ALOAD == AT_TILED || ALOAD == AT_TILED2);
    extern __shared__ __align__(16) char dsm[];

    const int tid  = threadIdx.x;
    const int lane = tid & 31;
    const int wid  = tid >> 5;
    const int wm = (wid >> 1) * 32;
    const int wn = (wid & 1) * 32;
    const int ksbeg = kc * NCH;

    const uint32_t sb = (uint32_t)__cvta_generic_to_shared(dsm);
    const uint32_t CH  = 5120u;
    const uint32_t STG = 30720u;
    const uint32_t mb0 = sb + 61440u;

    if (tid == 0) { MBAR_INIT(mb0, 1); MBAR_INIT(mb0 + 8, 1); }
    __syncthreads();

    auto issue = [&](int s) {
        const int st = s & 1;
        const int n2 = (2 * s + 1 < NCH) ? 2 : 1;
        const uint32_t buf = sb + st * STG, mbar = mb0 + st * 8;
        MBAR_EXPECT(mbar, (uint32_t)n2 * (TILEDA ? 15360u : 10240u));
        for (int j = 0; j < n2; j++) {
            const int ks = ksbeg + 2 * s + j;
            if (TILEDA) {
                const __half* pa;
                if (ALOAD == AT_TILED2 && ks >= ks1) pa = ap2 + (size_t)(mb * 32 + (ks - ks1)) * 2560;
                else                                  pa = ap1 + (size_t)(mb * 32 + ks) * 2560;
                bulkcp(buf + j * CH, pa, 5120u, mbar);
            }
            bulkcp(buf + 2 * CH + j * CH, bh + (size_t)(nb * kspmb + ks) * 2560, 5120u, mbar);
            bulkcp(buf + 4 * CH + j * CH, bl + (size_t)(nb * kspmb + ks) * 2560, 5120u, mbar);
        }
    };
    auto fillA = [&](int s) {
        if (TILEDA) return;
        const int st = s & 1;
        const int n2 = (2 * s + 1 < NCH) ? 2 : 1;
        const int lrow = tid >> 1, lkb = (tid & 1) << 4;
        const int gm = mb * 64 + lrow;
        for (int j = 0; j < n2; j++) {
            __half* as = reinterpret_cast<__half*>(dsm + st * STG + j * CH);
#pragma unroll
            for (int q = 0; q < 2; q++) {
                float r8[8];
                load_a8<ALOAD>(gm, (ksbeg + 2 * s + j) * 32 + lkb + q * 8, r8,
                               A2f, lda2, K1, st_mq, st_sq, st_eps, st_nt, st_prev);
                uint4 pk; pack8h(r8, pk);
                *reinterpret_cast<uint4*>(&as[lrow * 40 + lkb + q * 8]) = pk;
            }
        }
    };

    if (tid == 0) { issue(0); if (NSTG > 1) issue(1); }
    fillA(0);
    if (NSTG > 1) fillA(1);
    __syncthreads();

    float acc[2][4][4];
#pragma unroll
    for (int i = 0; i < 2; i++)
#pragma unroll
        for (int j = 0; j < 4; j++)
#pragma unroll
            for (int q = 0; q < 4; q++) acc[i][j][q] = 0.f;

    const int amat = lane >> 3, arin = lane & 7;
    const int arowb = wm + ((amat & 1) << 3) + arin;
    const int acol  = (amat >> 1) << 3;
    const int brow = wn + ((lane >> 4) << 3) + (lane & 7);
    const int bcol = ((lane >> 3) & 1) << 3;

    int ph[2] = {0, 0};
#pragma unroll 1
    for (int s = 0; s < NSTG; s++) {
        const int cur = s & 1;
        MBAR_WAIT(mb0 + cur * 8, ph[cur]); ph[cur] ^= 1;
        const int n2 = (2 * s + 1 < NCH) ? 2 : 1;
#pragma unroll
        for (int j = 0; j < 2; j++) {
            if (j >= n2) break;
            const uint32_t aOff  = sb + cur * STG + j * CH;
            const uint32_t bhOff = sb + cur * STG + 2 * CH + j * CH;
            const uint32_t blOff = sb + cur * STG + 4 * CH + j * CH;
#pragma unroll
            for (int kk = 0; kk < 32; kk += 16) {
                uint32_t Am[2][4], Bh[4][2], Bl[4][2];
#pragma unroll
                for (int mf = 0; mf < 2; mf++) {
                    uint32_t off = (uint32_t)(((arowb + mf*16) * 40 + kk + acol) * 2);
                    ldsm4(Am[mf], aOff + off);
                }
#pragma unroll
                for (int nfp = 0; nfp < 2; nfp++) {
                    uint32_t off = (uint32_t)(((brow + nfp*16) * 40 + kk + bcol) * 2);
                    uint32_t rh[4], rl[4];
                    ldsm4(rh, bhOff + off);
                    ldsm4(rl, blOff + off);
                    Bh[nfp*2][0]   = rh[0]; Bh[nfp*2][1]   = rh[1];
                    Bh[nfp*2+1][0] = rh[2]; Bh[nfp*2+1][1] = rh[3];
                    Bl[nfp*2][0]   = rl[0]; Bl[nfp*2][1]   = rl[1];
                    Bl[nfp*2+1][0] = rl[2]; Bl[nfp*2+1][1] = rl[3];
                }
#pragma unroll
                for (int mf = 0; mf < 2; mf++)
#pragma unroll
                    for (int nf = 0; nf < 4; nf++) {
                        mmah(acc[mf][nf], Am[mf], Bh[nf]);
                        mmah(acc[mf][nf], Am[mf], Bl[nf]);
                    }
            }
        }
        __syncthreads();
        if (s + 2 < NSTG) {
            fillA(s + 2);
            if (tid == 0) issue(s + 2);
        }
    }

    const int gr = lane >> 2, gc = (lane & 3) << 1;
#pragma unroll
    for (int mf = 0; mf < 2; mf++)
#pragma unroll
        for (int nf = 0; nf < 4; nf++) {
            int r = mb * 64 + wm + mf * 16 + gr;
            int c = nb * 64 + wn + nf * 8 + gc;
            epi2<EPI>(kc, r,     c, acc[mf][nf][0], acc[mf][nf][1], bias, out, ldout, mean_out, std_out, oap);
            epi2<EPI>(kc, r + 8, c, acc[mf][nf][2], acc[mf][nf][3], bias, out, ldout, mean_out, std_out, oap);
        }
}

// ---- phase kernels ----
__global__ void __launch_bounds__(128) k_x(
    const float* act, const float* nt, const float* mq, const float* sq,
    const float* eps, const float* prev, const float* b_sa)
{
    int mb = blockIdx.x >> 4, nb = blockIdx.x & 15;
    gemm64<160, AT_STATE, EPI_TILEA>(mb, nb, 0,
        nullptr, nullptr, 0, act, DACT, DST, mq, sq, eps, nt, prev,
        tWsa_h, tWsa_l, 5,
        b_sa, nullptr, 0, nullptr, nullptr, Ax_p);
}

__global__ void __launch_bounds__(128) k_gigh(
    const float* b_ih, const float* b_hh, const __half* belp)
{
    int tile = blockIdx.x;
    if (tile < 192) {
        int mb = tile / 48, nb = tile % 48;
        gemm64<1024, AT_TILED, EPI_F32>(mb, nb, 0,
            Ax_p, nullptr, 0, nullptr, 0, 0, nullptr, nullptr, nullptr, nullptr, nullptr,
            tWih_h, tWih_l, 32,
            b_ih, g_gi, GRU3, nullptr, nullptr, nullptr);
    } else {
        int r = tile - 192;
        int mb = r / 48, nb = r % 48;
        gemm64<1024, AT_TILED, EPI_F32>(mb, nb, 0,
            belp, nullptr, 0, nullptr, 0, 0, nullptr, nullptr, nullptr, nullptr, nullptr,
            tWhh_h, tWhh_l, 32,
            b_hh, g_gh, GRU3, nullptr, nullptr, nullptr);
    }
}

__global__ void __launch_bounds__(128) k_gru(float* belout, __half* abp)
{
    int i4 = (blockIdx.x * 128 + threadIdx.x) * 4;
    int m = i4 >> 10, j = i4 & 1023;
    const size_t base = (size_t)m * GRU3 + j;
    float4 gir = *reinterpret_cast<const float4*>(g_gi + base);
    float4 giz = *reinterpret_cast<const float4*>(g_gi + base + 1024);
    float4 gin = *reinterpret_cast<const float4*>(g_gi + base + 2048);
    float4 ghr = *reinterpret_cast<const float4*>(g_gh + base);
    float4 ghz = *reinterpret_cast<const float4*>(g_gh + base + 1024);
    float4 ghn = *reinterpret_cast<const float4*>(g_gh + base + 2048);
    float4 b   = *reinterpret_cast<const float4*>(g_belief + i4);
    float4 h;
    { float r = sigf(gir.x + ghr.x), z = sigf(giz.x + ghz.x);
      h.x = (1.f - z) * tanhf(gin.x + r * ghn.x) + z * b.x; }
    { float r = sigf(gir.y + ghr.y), z = sigf(giz.y + ghz.y);
      h.y = (1.f - z) * tanhf(gin.y + r * ghn.y) + z * b.y; }
    { float r = sigf(gir.z + ghr.z), z = sigf(giz.z + ghz.z);
      h.z = (1.f - z) * tanhf(gin.z + r * ghn.z) + z * b.z; }
    { float r = sigf(gir.w + ghr.w), z = sigf(giz.w + ghz.w);
      h.w = (1.f - z) * tanhf(gin.w + r * ghn.w) + z * b.w; }
    *reinterpret_cast<float4*>(g_belief + i4) = h;
    *reinterpret_cast<float4*>(belout + i4)  = h;
    store_a4(abp, pt_idx(32, m, j), h);
}

__global__ void __launch_bounds__(128) k_hq(
    const __half* belp, const __half* obsp, const float* b_poh)
{
    int tile = blockIdx.x;
    int kc = tile >> 6;
    int r = tile & 63;
    int mb = r >> 4, nb = r & 15;
    gemm64<1024, AT_TILED2, EPI_F32>(mb, nb, kc,
        belp, obsp, 32, nullptr, 0, 0, nullptr, nullptr, nullptr, nullptr, nullptr,
        tWpoh_h, tWpoh_l, 64,
        kc == 0 ? b_poh : nullptr,
        kc == 0 ? g_hq1 : g_hq2, DHID,
        nullptr, nullptr, nullptr);
}

__global__ void __launch_bounds__(128) k_head(
    const float* b_pos, float* mqo, float* sqo)
{
    int tile = blockIdx.x;
    int kc = tile >> 4;
    int r = tile & 15;
    int mb = r >> 2, nb = r & 3;
    gemm64<128, AT_ELUSUM, EPI_HEADAT>(mb, nb, kc,
        nullptr, nullptr, 0, nullptr, 0, 0, nullptr, nullptr, nullptr, nullptr, nullptr,
        tWpos_h, tWpos_l, 32,
        b_pos, nullptr, 0, mqo, sqo, nullptr);
}

__global__ void __launch_bounds__(128) k_prh(const float* b_prh)
{
    int mb = blockIdx.x >> 4, nb = blockIdx.x & 15;
    gemm64<1024, AT_TILED, EPI_TILEA>(mb, nb, 0,
        Abel_p, nullptr, 0, nullptr, 0, 0, nullptr, nullptr, nullptr, nullptr, nullptr,
        tWprh_h, tWprh_l, 32,
        b_prh, nullptr, 0, nullptr, nullptr, Ahp_p);
}

__global__ void __launch_bounds__(128) k_prs(const float* b_prs, float* mp, float* sp)
{
    int mb = blockIdx.x >> 2, nb = blockIdx.x & 3;
    gemm64<1024, AT_TILED, EPI_HEADST>(mb, nb, 0,
        Ahp_p, nullptr, 0, nullptr, 0, 0, nullptr, nullptr, nullptr, nullptr, nullptr,
        tWprs_h, tWprs_l, 32,
        b_prs, nullptr, 0, mp, sp, nullptr);
}

// ---- elementwise ----
__global__ void conv_w(const float* __restrict__ W, __half* th, __half* tl, int N, int K)
{
    int e2 = (blockIdx.x * 256 + threadIdx.x) * 2;
    if (e2 >= N * K) return;
    int n = e2 / K, k = e2 % K;
    float v0 = __ldg(W + e2), v1 = __ldg(W + e2 + 1);
    __half h0 = __float2half_rn(v0), h1 = __float2half_rn(v1);
    __half l0 = __float2half_rn(v0 - __half2float(h0));
    __half l1 = __float2half_rn(v1 - __half2float(h1));
    size_t idx = ((size_t)(n >> 6) * (K >> 5) + (k >> 5)) * 2560 + (n & 63) * 40 + (k & 31);
    *reinterpret_cast<__half2*>(th + idx) = __halves2half2(h0, h1);
    *reinterpret_cast<__half2*>(tl + idx) = __halves2half2(l0, l1);
}

__global__ void conv_a(const float* __restrict__ X, __half* tp, int N, int K)
{
    int e4 = (blockIdx.x * 256 + threadIdx.x) * 4;
    if (e4 >= N * K) return;
    int n = e4 / K, k = e4 % K;
    float4 v = __ldg(reinterpret_cast<const float4*>(X + e4));
    size_t idx = ((size_t)(n >> 6) * (K >> 5) + (k >> 5)) * 2560 + (n & 63) * 40 + (k & 31);
    store_a4(tp, idx, v);
}

__global__ void k_init(const float* __restrict__ prevb, float* __restrict__ out)
{
    int i4 = (blockIdx.x * 128 + threadIdx.x) * 4;
    if (i4 < 2 * TT * BB * DST)
        *reinterpret_cast<float4*>(out + OFF_MQ + i4) = make_float4(0.f, 0.f, 0.f, 0.f);
    if (i4 < BB * DBEL) {
        float4 v = __ldg(reinterpret_cast<const float4*>(prevb + i4));
        *reinterpret_cast<float4*>(g_belief + i4) = v;
        int m = i4 >> 10, k = i4 & 1023;
        store_a4(AbelI_p, pt_idx(32, m, k), v);
    }
}

__global__ void k_sample(float* __restrict__ out,
                         const float* __restrict__ ep, const float* __restrict__ eq)
{
    int i = (blockIdx.x * 128 + threadIdx.x) * 4;
    if (i >= TT * BB * DST) return;
    float4 mp = *reinterpret_cast<const float4*>(out + OFF_MP + i);
    float4 sp = *reinterpret_cast<const float4*>(out + OFF_SP + i);
    float4 e1 = __ldg(reinterpret_cast<const float4*>(ep + i));
    float4 mq = *reinterpret_cast<const float4*>(out + OFF_MQ + i);
    float4 sq = *reinterpret_cast<const float4*>(out + OFF_SQ + i);
    float4 e2 = __ldg(reinterpret_cast<const float4*>(eq + i));
    float4 prs, pos, sqo;
    prs.x = mp.x + sp.x * e1.x; prs.y = mp.y + sp.y * e1.y;
    prs.z = mp.z + sp.z * e1.z; prs.w = mp.w + sp.w * e1.w;
    sqo.x = splusf(sq.x) + 0.1f; sqo.y = splusf(sq.y) + 0.1f;
    sqo.z = splusf(sq.z) + 0.1f; sqo.w = splusf(sq.w) + 0.1f;
    pos.x = mq.x + sqo.x * e2.x; pos.y = mq.y + sqo.y * e2.y;
    pos.z = mq.z + sqo.z * e2.z; pos.w = mq.w + sqo.w * e2.w;
    *reinterpret_cast<float4*>(out + OFF_PRS + i) = prs;
    *reinterpret_cast<float4*>(out + OFF_SQ  + i) = sqo;
    *reinterpret_cast<float4*>(out + OFF_POS + i) = pos;
}

// ---- host ----
extern "C" void kernel_launch(void* const* d_in, const int* in_sizes, int n_in,
                              void* d_out, int out_size)
{
    (void)in_sizes; (void)n_in; (void)out_size;
    const float* prev_state   = (const float*)d_in[0];
    const float* actions      = (const float*)d_in[1];
    const float* prev_belief  = (const float*)d_in[2];
    const float* observations = (const float*)d_in[3];
    const float* nonterminals = (const float*)d_in[4];
    const float* prior_noise  = (const float*)d_in[5];
    const float* post_noise   = (const float*)d_in[6];
    const float* W_sa  = (const float*)d_in[7];
    const float* b_sa  = (const float*)d_in[8];
    const float* w_ih  = (const float*)d_in[9];
    const float* b_ih  = (const float*)d_in[10];
    const float* w_hh  = (const float*)d_in[11];
    const float* b_hh  = (const float*)d_in[12];
    const float* W_prh = (const float*)d_in[13];
    const float* b_prh = (const float*)d_in[14];
    const float* W_prs = (const float*)d_in[15];
    const float* b_prs = (const float*)d_in[16];
    const float* W_poh = (const float*)d_in[17];
    const float* b_poh = (const float*)d_in[18];
    const float* W_pos = (const float*)d_in[19];
    const float* b_pos = (const float*)d_in[20];
    float* out = (float*)d_out;

    cudaFuncSetAttribute(k_x,    cudaFuncAttributeMaxDynamicSharedMemorySize, GEMM_SMEM);
    cudaFuncSetAttribute(k_gigh, cudaFuncAttributeMaxDynamicSharedMemorySize, GEMM_SMEM);
    cudaFuncSetAttribute(k_hq,   cudaFuncAttributeMaxDynamicSharedMemorySize, GEMM_SMEM);
    cudaFuncSetAttribute(k_head, cudaFuncAttributeMaxDynamicSharedMemorySize, GEMM_SMEM);
    cudaFuncSetAttribute(k_prh,  cudaFuncAttributeMaxDynamicSharedMemorySize, GEMM_SMEM);
    cudaFuncSetAttribute(k_prs,  cudaFuncAttributeMaxDynamicSharedMemorySize, GEMM_SMEM);

    __half *p_wsa_h, *p_wsa_l, *p_wih_h, *p_wih_l, *p_whh_h, *p_whh_l,
           *p_wpoh_h, *p_wpoh_l, *p_wpos_h, *p_wpos_l, *p_wprh_h, *p_wprh_l,
           *p_wprs_h, *p_wprs_l, *p_abel, *p_abeli, *p_aobs;
    cudaGetSymbolAddress((void**)&p_wsa_h,  tWsa_h);  cudaGetSymbolAddress((void**)&p_wsa_l,  tWsa_l);
    cudaGetSymbolAddress((void**)&p_wih_h,  tWih_h);  cudaGetSymbolAddress((void**)&p_wih_l,  tWih_l);
    cudaGetSymbolAddress((void**)&p_whh_h,  tWhh_h);  cudaGetSymbolAddress((void**)&p_whh_l,  tWhh_l);
    cudaGetSymbolAddress((void**)&p_wpoh_h, tWpoh_h); cudaGetSymbolAddress((void**)&p_wpoh_l, tWpoh_l);
    cudaGetSymbolAddress((void**)&p_wpos_h, tWpos_h); cudaGetSymbolAddress((void**)&p_wpos_l, tWpos_l);
    cudaGetSymbolAddress((void**)&p_wprh_h, tWprh_h); cudaGetSymbolAddress((void**)&p_wprh_l, tWprh_l);
    cudaGetSymbolAddress((void**)&p_wprs_h, tWprs_h); cudaGetSymbolAddress((void**)&p_wprs_l, tWprs_l);
    cudaGetSymbolAddress((void**)&p_abel,  Abel_p);
    cudaGetSymbolAddress((void**)&p_abeli, AbelI_p);
    cudaGetSymbolAddress((void**)&p_aobs,  Aobs_p);

    auto cw = [](const float* W, __half* h, __half* l, int N, int K) {
        conv_w<<<(N * K / 2 + 255) / 256, 256>>>(W, h, l, N, K);
    };
    cw(W_sa,  p_wsa_h,  p_wsa_l,  DBEL, 160);
    cw(w_ih,  p_wih_h,  p_wih_l,  GRU3, DBEL);
    cw(w_hh,  p_whh_h,  p_whh_l,  GRU3, DBEL);
    cw(W_poh, p_wpoh_h, p_wpoh_l, DHID, 2048);
    cw(W_pos, p_wpos_h, p_wpos_l, 2*DST, DHID);
    cw(W_prh, p_wprh_h, p_wprh_l, DHID, DBEL);
    cw(W_prs, p_wprs_h, p_wprs_l, 2*DST, DHID);
    conv_a<<<(TT * BB * DEMB / 4 + 255) / 256, 256>>>(observations, p_aobs, TT * BB, DEMB);

    k_init<<<(2 * TT * BB * DST / 4 + 127) / 128, 128>>>(prev_belief, out);

    const size_t TSTEP = PT(BB, DBEL);
    for (int t = 0; t < TT; t++) {
        const float* act = actions      + (size_t)t * BB * DACT;
        const float* nt  = nonterminals + (size_t)t * BB;
        const float* mq  = (t == 0) ? nullptr : out + OFF_MQ + (size_t)(t-1) * BB * DST;
        const float* sq  = (t == 0) ? nullptr : out + OFF_SQ + (size_t)(t-1) * BB * DST;
        const float* ep  = (t == 0) ? nullptr : post_noise + (size_t)(t-1) * BB * DST;
        const __half* bpp = (t == 0) ? p_abeli : p_abel + (size_t)(t-1) * TSTEP;

        k_x   <<<64, 128, GEMM_SMEM>>>(act, nt, mq, sq, ep, prev_state, b_sa);
        k_gigh<<<384, 128, GEMM_SMEM>>>(b_ih, b_hh, bpp);
        k_gru <<<512, 128>>>(out + OFF_BEL + (size_t)t * BB * DBEL, p_abel + (size_t)t * TSTEP);
        k_hq  <<<128, 128, GEMM_SMEM>>>(p_abel + (size_t)t * TSTEP,
                                        p_aobs + (size_t)t * TSTEP, b_poh);
        k_head<<<128, 128, GEMM_SMEM>>>(b_pos,
                                        out + OFF_MQ + (size_t)t * BB * DST,
                                        out + OFF_SQ + (size_t)t * BB * DST);
    }

    k_prh<<<3200, 128, GEMM_SMEM>>>(b_prh);
    k_prs<<<800, 128, GEMM_SMEM>>>(b_prs, out + OFF_MP, out + OFF_SP);
    k_sample<<<(TT * BB * DST / 4 + 127) / 128, 128>>>(out, prior_noise, post_noise);
}